// round 10
// baseline (speedup 1.0000x reference)
#include <cuda_runtime.h>
#include <cuda_bf16.h>
#include <math.h>
#include <stdint.h>

// ---------------- static scratch ----------------
#define MAXN 131072
#define DD 256
__device__ float g_x  [(size_t)MAXN * DD];
__device__ float g_xs [(size_t)MAXN * DD];
__device__ __nv_bfloat16 g_ba[(size_t)MAXN * 768];
__device__ __nv_bfloat16 g_bb[(size_t)MAXN * 512];
__device__ __nv_bfloat16 g_fe[(size_t)MAXN * 256];
__device__ __nv_bfloat16 g_gr[(size_t)MAXN * 256];   // raw gate hidden (pre-bias)
__device__ __nv_bfloat16 g_wt[786432];
__device__ float g_key[MAXN];
__device__ int   g_idx[MAXN];
__device__ float g_gt [8 * DD];
__device__ float g_ggb[8 * DD];
__device__ float g_fb [8 * DD];
__device__ float g_stats[8 * 12];

// ---------------- fast math ----------------
__device__ __forceinline__ float fexp2_fast(float z) {
    z = fmaxf(z, -80.f);
    float n = rintf(z);
    float f = z - n;
    float p = 0.009618129f;
    p = p * f + 0.055504109f;
    p = p * f + 0.240226507f;
    p = p * f + 0.693147181f;
    p = p * f + 1.0f;
    return p * __int_as_float(((int)n + 127) << 23);
}
__device__ __forceinline__ float fexpf_fast(float x) {
    return fexp2_fast(x * 1.4426950408889634f);
}
__device__ __forceinline__ float frcp_fast(float d) {
    float y = __int_as_float(0x7ef311c3 - __float_as_int(d));
    y = y * (2.f - d * y);
    y = y * (2.f - d * y);
    y = y * (2.f - d * y);
    return y;
}
__device__ __forceinline__ uint32_t smem_u32(const void* p) {
    return (uint32_t)__cvta_generic_to_shared(p);
}
__device__ __forceinline__ float blocksum256(float v, float* red8) {
    #pragma unroll
    for (int off = 16; off; off >>= 1) v += __shfl_xor_sync(0xffffffffu, v, off);
    if ((threadIdx.x & 31) == 0) red8[threadIdx.x >> 5] = v;
    __syncthreads();
    float s = 0.f;
    #pragma unroll
    for (int i = 0; i < 8; i++) s += red8[i];
    return s;
}

// ---------------- prep ----------------
struct PrepArgs {
    const float* coord; float* stats; int Lc; int B;
    const float* wsrc[8]; __nv_bfloat16* wdst[8];
    int wK[8], wN[8], wt0[8];
    int totalWTiles;
    float* gt;
};
__global__ void __launch_bounds__(1024) prep_kernel(PrepArgs a) {
    __shared__ float red[1024];
    __shared__ float tt[32][33];
    int b = blockIdx.x, tid = threadIdx.x;
    if (b < a.B) {
        int c = b, Lc = a.Lc;
        float sum[3] = {0,0,0}, mn[3] = {1e30f,1e30f,1e30f}, mx[3] = {-1e30f,-1e30f,-1e30f};
        for (int i = tid; i < Lc; i += 1024) {
            const float* cp = a.coord + (size_t)(c * Lc + i) * 3;
            #pragma unroll
            for (int d = 0; d < 3; d++) {
                float v = cp[d];
                sum[d] += v; mn[d] = fminf(mn[d], v); mx[d] = fmaxf(mx[d], v);
            }
        }
        for (int d = 0; d < 3; d++) {
            red[tid] = sum[d]; __syncthreads();
            for (int s = 512; s > 0; s >>= 1) { if (tid < s) red[tid] += red[tid + s]; __syncthreads(); }
            float tot = red[0]; __syncthreads();
            red[tid] = mn[d]; __syncthreads();
            for (int s = 512; s > 0; s >>= 1) { if (tid < s) red[tid] = fminf(red[tid], red[tid + s]); __syncthreads(); }
            float tmn = red[0]; __syncthreads();
            red[tid] = mx[d]; __syncthreads();
            for (int s = 512; s > 0; s >>= 1) { if (tid < s) red[tid] = fmaxf(red[tid], red[tid + s]); __syncthreads(); }
            float tmx = red[0]; __syncthreads();
            if (tid == 0) {
                float mean = tot / (float)Lc;
                a.stats[c*12 + d]     = mean;
                a.stats[c*12 + 3 + d] = fmaxf(fmaxf(tmx - mean, mean - tmn), 1e-6f);
                a.stats[c*12 + 6 + d] = tmn;
                a.stats[c*12 + 9 + d] = 1.f / fmaxf(tmx - tmn, 1e-6f);
            }
            __syncthreads();
        }
    } else if (b < a.B + a.totalWTiles) {
        int t = b - a.B;
        int w = 0;
        #pragma unroll
        for (int q = 1; q < 8; q++) if (t >= a.wt0[q]) w = q;
        int lt = t - a.wt0[w];
        int tilesX = a.wN[w] >> 5;
        int bx = (lt % tilesX) << 5, by = (lt / tilesX) << 5;
        const float* src = a.wsrc[w];
        __nv_bfloat16* dst = a.wdst[w];
        int K = a.wK[w], Ncols = a.wN[w];
        int tx = tid & 31, ty = tid >> 5;
        tt[ty][tx] = src[(size_t)(by + ty) * Ncols + bx + tx];
        __syncthreads();
        dst[(size_t)(bx + ty) * K + by + tx] = __float2bfloat16(tt[tx][ty]);
    } else {
        a.gt[tid] = 0.f;
        a.gt[tid + 1024] = 0.f;
    }
}

// ---------------- PE + pre-LN + LN1 + key + feats->bf16 ----------------
__global__ void __launch_bounds__(256) pe_ln_key_kernel(
    const float* __restrict__ feats, const float* __restrict__ coord,
    const float* __restrict__ w1, const float* __restrict__ b1,
    const float* __restrict__ w2, const float* __restrict__ b2,
    const float* __restrict__ g, const float* __restrict__ beta,
    const float* __restrict__ n1g, const float* __restrict__ n1b,
    const float* __restrict__ stats,
    float* __restrict__ xout, __nv_bfloat16* __restrict__ hbf,
    __nv_bfloat16* __restrict__ febf,
    float* __restrict__ key, int* __restrict__ idx, int Lc)
{
    int i = blockIdx.x, tid = threadIdx.x;
    int c = i / Lc;
    __shared__ float hid[64];
    __shared__ float red8[8];
    const float* st = stats + c * 12;
    float c0 = coord[(size_t)i*3+0], c1 = coord[(size_t)i*3+1], c2 = coord[(size_t)i*3+2];
    if (tid < 64) {
        float n0 = (c0 - st[0]) / st[3];
        float n1 = (c1 - st[1]) / st[4];
        float n2 = (c2 - st[2]) / st[5];
        float hv = b1[tid] + n0 * w1[tid] + n1 * w1[64 + tid] + n2 * w1[128 + tid];
        hid[tid] = fmaxf(hv, 0.f);
    }
    if (tid == 0) {
        float k0 = (c0 - st[6]) * st[9];
        float k1 = (c1 - st[7]) * st[10];
        float k2 = (c2 - st[8]) * st[11];
        key[i] = k0 + 2.17f * k1 + 3.31f * k2;
        idx[i] = i;
    }
    __syncthreads();
    float fv = feats[(size_t)i * 256 + tid];
    febf[(size_t)i * 256 + tid] = __float2bfloat16(fv);
    float pe = b2[tid];
    #pragma unroll 8
    for (int h = 0; h < 64; h++) pe += hid[h] * w2[h * 256 + tid];
    float v = fv + pe;
    float mean = blocksum256(v, red8) * (1.f / 256.f);
    __syncthreads();
    float dv = v - mean;
    float var = blocksum256(dv * dv, red8) * (1.f / 256.f);
    float xv = dv * rsqrtf(var + 1e-5f) * g[tid] + beta[tid];
    xout[(size_t)i * 256 + tid] = xv;
    __syncthreads();
    float m2 = blocksum256(xv, red8) * (1.f / 256.f);
    __syncthreads();
    float d2 = xv - m2;
    float v2 = blocksum256(d2 * d2, red8) * (1.f / 256.f);
    hbf[(size_t)i * 256 + tid] = __float2bfloat16(d2 * rsqrtf(v2 + 1e-5f) * n1g[tid] + n1b[tid]);
}

// ---------------- hierarchical bitonic sort (CHUNK=4096) ----------------
#define CHUNK 4096
__global__ void __launch_bounds__(1024) sort_local(float* __restrict__ key, int* __restrict__ idx, int Lc) {
    extern __shared__ char smraw[];
    float* sk = (float*)smraw;
    int*   si = (int*)(smraw + CHUNK * 4);
    size_t gbase = (size_t)blockIdx.x * CHUNK;
    int lbase = (int)(gbase % (size_t)Lc);
    for (int t = threadIdx.x; t < CHUNK; t += 1024) { sk[t] = key[gbase + t]; si[t] = idx[gbase + t]; }
    __syncthreads();
    for (int k = 2; k <= CHUNK; k <<= 1) {
        for (int j = k >> 1; j > 0; j >>= 1) {
            #pragma unroll
            for (int it = 0; it < CHUNK / 2048; it++) {
                int t = threadIdx.x + it * 1024;
                int i = 2 * t - (t & (j - 1));
                int p = i + j;
                bool up = (((lbase + i) & k) == 0);
                float a = sk[i], b = sk[p];
                int ia = si[i], ib = si[p];
                bool sw = up ? (a > b || (a == b && ia > ib)) : (a < b || (a == b && ia < ib));
                if (sw) { sk[i] = b; sk[p] = a; si[i] = ib; si[p] = ia; }
            }
            __syncthreads();
        }
    }
    for (int t = threadIdx.x; t < CHUNK; t += 1024) { key[gbase + t] = sk[t]; idx[gbase + t] = si[t]; }
}

__global__ void __launch_bounds__(1024) merge_local(float* __restrict__ key, int* __restrict__ idx, int k, int Lc) {
    extern __shared__ char smraw[];
    float* sk = (float*)smraw;
    int*   si = (int*)(smraw + CHUNK * 4);
    size_t gbase = (size_t)blockIdx.x * CHUNK;
    int lbase = (int)(gbase % (size_t)Lc);
    for (int t = threadIdx.x; t < CHUNK; t += 1024) { sk[t] = key[gbase + t]; si[t] = idx[gbase + t]; }
    __syncthreads();
    for (int j = CHUNK / 2; j > 0; j >>= 1) {
        #pragma unroll
        for (int it = 0; it < CHUNK / 2048; it++) {
            int t = threadIdx.x + it * 1024;
            int i = 2 * t - (t & (j - 1));
            int p = i + j;
            bool up = (((lbase + i) & k) == 0);
            float a = sk[i], b = sk[p];
            int ia = si[i], ib = si[p];
            bool sw = up ? (a > b || (a == b && ia > ib)) : (a < b || (a == b && ia < ib));
            if (sw) { sk[i] = b; sk[p] = a; si[i] = ib; si[p] = ia; }
        }
        __syncthreads();
    }
    for (int t = threadIdx.x; t < CHUNK; t += 1024) { key[gbase + t] = sk[t]; idx[gbase + t] = si[t]; }
}

__global__ void __launch_bounds__(256) sort_global(float* __restrict__ key, int* __restrict__ idx, int k, int j, int Lc) {
    int c = blockIdx.y;
    size_t base = (size_t)c * Lc;
    int t = blockIdx.x * 256 + threadIdx.x;
    int i = 2 * t - (t & (j - 1));
    int p = i + j;
    bool up = ((i & k) == 0);
    float a = key[base + i], b = key[base + p];
    int ia = idx[base + i], ib = idx[base + p];
    bool sw = up ? (a > b || (a == b && ia > ib)) : (a < b || (a == b && ia < ib));
    if (sw) {
        key[base + i] = b; key[base + p] = a;
        idx[base + i] = ib; idx[base + p] = ia;
    }
}

// ---------------- LN -> bf16 ----------------
__global__ void __launch_bounds__(256) ln_bf(const float* __restrict__ x, const float* __restrict__ g,
                                             const float* __restrict__ b, __nv_bfloat16* __restrict__ y) {
    int row = blockIdx.x, tid = threadIdx.x;
    __shared__ float red8[8];
    float v = x[(size_t)row * 256 + tid];
    float mean = blocksum256(v, red8) * (1.f / 256.f);
    __syncthreads();
    float dv = v - mean;
    float var = blocksum256(dv * dv, red8) * (1.f / 256.f);
    y[(size_t)row * 256 + tid] = __float2bfloat16(dv * rsqrtf(var + 1e-5f) * g[tid] + b[tid]);
}

// ---------------- bias + relu (gate hidden finalize) ----------------
__global__ void __launch_bounds__(256) biasrelu(const __nv_bfloat16* __restrict__ gr,
                                                const float* __restrict__ ggb,
                                                __nv_bfloat16* __restrict__ out, int Lc) {
    int i = blockIdx.x, t = threadIdx.x;
    int c = i / Lc;
    float v = __bfloat162float(gr[(size_t)i * 256 + t]) + ggb[c * 256 + t];
    out[(size_t)i * 256 + t] = __float2bfloat16(fmaxf(v, 0.f));
}

// ---------------- tensor-core GEMM (templated K, 4-stage, 1 sync/iter) ----------------
#define GBM 128
#define GBN 128
#define GKT 32
#define STG_BYTES 20480
#define NSTAGE 4

template<int NK>
__global__ void __launch_bounds__(256) gemm_bf16(
    const __nv_bfloat16* __restrict__ A_, const __nv_bfloat16* __restrict__ Bt_,
    const float* __restrict__ bias_,
    const float* __restrict__ resid, const float* __restrict__ gate,
    void* __restrict__ Cout_,
    int M, int Ncols, int cloudLen, int epi, int outBf16,
    const int* __restrict__ ridx, float* __restrict__ gtp, int gtLc,
    const __nv_bfloat16* A2, const __nv_bfloat16* Bt2, const float* bias2, void* Cout2)
{
    constexpr int K = NK * GKT;
    extern __shared__ char smraw[];
    const __nv_bfloat16* A = A_;
    const __nv_bfloat16* Bt = Bt_;
    const float* bias = bias_;
    void* Cout = Cout_;
    if (blockIdx.z == 1) { A = A2; Bt = Bt2; bias = bias2; Cout = Cout2; }
    const int tid = threadIdx.x;
    const int lane = tid & 31;
    const int warp = tid >> 5;
    const int wm = warp >> 1, wn = warp & 1;
    const int m0 = blockIdx.y * GBM, n0 = blockIdx.x * GBN;

    float acc[2][8][4];
    #pragma unroll
    for (int i = 0; i < 2; i++)
        #pragma unroll
        for (int j = 0; j < 8; j++)
            #pragma unroll
            for (int q = 0; q < 4; q++) acc[i][j][q] = 0.f;

    const int ldrow0 = tid >> 2, ldc0 = tid & 3;
    const int ldrow1 = (tid + 256) >> 2;
    const __nv_bfloat16* gA0 = A + (size_t)(m0 + ldrow0) * K + ldc0 * 8;
    const __nv_bfloat16* gA1 = A + (size_t)(m0 + ldrow1) * K + ldc0 * 8;
    const __nv_bfloat16* gB0 = Bt + (size_t)(n0 + ldrow0) * K + ldc0 * 8;
    const __nv_bfloat16* gB1 = Bt + (size_t)(n0 + ldrow1) * K + ldc0 * 8;
    const uint32_t smemBase = smem_u32(smraw);
    const uint32_t dA0 = smemBase + ldrow0 * 80 + ldc0 * 16;
    const uint32_t dA1 = smemBase + ldrow1 * 80 + ldc0 * 16;
    const uint32_t dB0 = dA0 + 10240;
    const uint32_t dB1 = dA1 + 10240;

    uint32_t aoff[2], boff[4];
    #pragma unroll
    for (int i = 0; i < 2; i++)
        aoff[i] = smemBase + (wm * 32 + i * 16 + (lane & 15)) * 80 + (lane >> 4) * 16;
    #pragma unroll
    for (int jp = 0; jp < 4; jp++)
        boff[jp] = smemBase + 10240 + (wn * 64 + jp * 16 + (lane & 15)) * 80 + (lane >> 4) * 16;

    auto issue = [&](int s, int kt) {
        uint32_t sb = s * STG_BYTES;
        int go = kt * GKT;
        asm volatile("cp.async.cg.shared.global [%0], [%1], 16;\n" :: "r"(dA0 + sb), "l"(gA0 + go));
        asm volatile("cp.async.cg.shared.global [%0], [%1], 16;\n" :: "r"(dB0 + sb), "l"(gB0 + go));
        asm volatile("cp.async.cg.shared.global [%0], [%1], 16;\n" :: "r"(dA1 + sb), "l"(gA1 + go));
        asm volatile("cp.async.cg.shared.global [%0], [%1], 16;\n" :: "r"(dB1 + sb), "l"(gB1 + go));
        asm volatile("cp.async.commit_group;\n");
    };

    issue(0, 0);
    issue(1, 1);
    #pragma unroll
    for (int kt = 0; kt < NK; kt++) {
        const int s = kt & (NSTAGE - 1);
        if (kt + 2 < NK) {
            issue((kt + 2) & (NSTAGE - 1), kt + 2);
            asm volatile("cp.async.wait_group 2;\n");
        } else if (kt + 1 < NK) {
            asm volatile("cp.async.wait_group 1;\n");
        } else {
            asm volatile("cp.async.wait_group 0;\n");
        }
        __syncthreads();

        const uint32_t sb = s * STG_BYTES;
        #pragma unroll
        for (int kk = 0; kk < 2; kk++) {
            uint32_t af[2][4];
            #pragma unroll
            for (int i = 0; i < 2; i++) {
                asm volatile("ldmatrix.sync.aligned.m8n8.x4.shared.b16 {%0,%1,%2,%3}, [%4];"
                             : "=r"(af[i][0]), "=r"(af[i][1]), "=r"(af[i][2]), "=r"(af[i][3])
                             : "r"(aoff[i] + sb + kk * 32));
            }
            uint32_t bf[8][2];
            #pragma unroll
            for (int jp = 0; jp < 4; jp++) {
                uint32_t r0, r1, r2, r3;
                asm volatile("ldmatrix.sync.aligned.m8n8.x4.shared.b16 {%0,%1,%2,%3}, [%4];"
                             : "=r"(r0), "=r"(r1), "=r"(r2), "=r"(r3)
                             : "r"(boff[jp] + sb + kk * 32));
                bf[2*jp][0] = r0; bf[2*jp+1][0] = r1;
                bf[2*jp][1] = r2; bf[2*jp+1][1] = r3;
            }
            #pragma unroll
            for (int i = 0; i < 2; i++)
                #pragma unroll
                for (int j = 0; j < 8; j++) {
                    asm volatile("mma.sync.aligned.m16n8k16.row.col.f32.bf16.bf16.f32 "
                                 "{%0,%1,%2,%3}, {%4,%5,%6,%7}, {%8,%9}, {%0,%1,%2,%3};"
                                 : "+f"(acc[i][j][0]), "+f"(acc[i][j][1]),
                                   "+f"(acc[i][j][2]), "+f"(acc[i][j][3])
                                 : "r"(af[i][0]), "r"(af[i][1]), "r"(af[i][2]), "r"(af[i][3]),
                                   "r"(bf[j][0]), "r"(bf[j][1]));
                }
        }
    }

    const int rbase = m0 + wm * 32 + (lane >> 2);
    const int cbase = n0 + wn * 64 + 2 * (lane & 3);
    float gta[8][2];
    #pragma unroll
    for (int j = 0; j < 8; j++) { gta[j][0] = 0.f; gta[j][1] = 0.f; }

    #pragma unroll
    for (int i = 0; i < 2; i++) {
        #pragma unroll
        for (int half = 0; half < 2; half++) {
            int m = rbase + i * 16 + half * 8;
            const float* bp = (cloudLen > 0) ? (bias + (size_t)(m / cloudLen) * Ncols) : bias;
            #pragma unroll
            for (int j = 0; j < 8; j++) {
                int n = cbase + j * 8;
                float v0 = acc[i][j][half * 2 + 0] + bp[n];
                float v1 = acc[i][j][half * 2 + 1] + bp[n + 1];
                size_t o = (size_t)m * Ncols + n;
                bool stored = false;
                switch (epi) {
                    case 1: v0 = fmaxf(v0, 0.f); v1 = fmaxf(v1, 0.f); break;
                    case 2:
                        v0 = 0.5f * v0 * (1.f + erff(v0 * 0.70710678118f));
                        v1 = 0.5f * v1 * (1.f + erff(v1 * 0.70710678118f));
                        break;
                    case 3:
                        v0 = frcp_fast(1.f + fexpf_fast(-v0));
                        v1 = frcp_fast(1.f + fexpf_fast(-v1));
                        break;
                    case 4: {
                        size_t ro = (size_t)(ridx ? ridx[m] : m) * Ncols + n;
                        float2 r = *(const float2*)(resid + ro);
                        v0 += r.x; v1 += r.y;
                    } break;
                    case 5: {
                        float2 r = *(const float2*)(resid + o);
                        float2 gg = *(const float2*)(gate + o);
                        v0 = r.x + gg.x * v0; v1 = r.y + gg.y * v1;
                    } break;
                    case 6: {
                        float2 r = *(const float2*)(resid + o);
                        v0 += r.x; v1 += r.y;
                        gta[j][0] += v0; gta[j][1] += v1;
                        size_t od = (size_t)ridx[m] * Ncols + n;
                        __nv_bfloat162 h;
                        h.x = __float2bfloat16(v0); h.y = __float2bfloat16(v1);
                        *(__nv_bfloat162*)((__nv_bfloat16*)Cout + od) = h;
                        stored = true;
                    } break;
                    default: break;
                }
                if (!stored) {
                    if (outBf16) {
                        __nv_bfloat162 h;
                        h.x = __float2bfloat16(v0); h.y = __float2bfloat16(v1);
                        *(__nv_bfloat162*)((__nv_bfloat16*)Cout + o) = h;
                    } else {
                        *(float2*)((float*)Cout + o) = make_float2(v0, v1);
                    }
                }
            }
        }
    }
    if (epi == 6) {
        int c = m0 / gtLc;
        #pragma unroll
        for (int j = 0; j < 8; j++) {
            float s0 = gta[j][0], s1 = gta[j][1];
            #pragma unroll
            for (int off = 4; off <= 16; off <<= 1) {
                s0 += __shfl_xor_sync(0xffffffffu, s0, off);
                s1 += __shfl_xor_sync(0xffffffffu, s1, off);
            }
            if ((lane >> 2) == 0) {
                int n = cbase + j * 8;
                atomicAdd(gtp + c * 256 + n, s0);
                atomicAdd(gtp + c * 256 + n + 1, s1);
            }
        }
    }
}

// ---------------- flash attention (gathers rows via sidx) ----------------
#define FA_SMEM (20480 * 2 + 32 * 528)
__global__ void __launch_bounds__(256) fattn(const __nv_bfloat16* __restrict__ qkv,
                                             const int* __restrict__ sidx,
                                             __nv_bfloat16* __restrict__ o) {
    extern __shared__ char sm[];
    char* sq = sm;
    char* sk = sm + 20480;
    char* svt = sm + 40960;
    const int p = blockIdx.x, h = blockIdx.y;
    const int tid = threadIdx.x;
    const int lane = tid & 31;
    const int w = tid >> 5;
    const size_t base = (size_t)p * 256;
    const float SC = 0.17677669529663687f * 1.4426950408889634f;

    {
        const size_t src = (size_t)sidx[base + tid] * 768;
        const uint4* qr = (const uint4*)(qkv + src + h * 32);
        const uint4* kr = (const uint4*)(qkv + src + 256 + h * 32);
        const uint4* vr = (const uint4*)(qkv + src + 512 + h * 32);
        uint4* dq = (uint4*)(sq + tid * 80);
        uint4* dk = (uint4*)(sk + tid * 80);
        uint4 v0 = vr[0], v1 = vr[1], v2 = vr[2], v3 = vr[3];
        dq[0] = qr[0]; dq[1] = qr[1]; dq[2] = qr[2]; dq[3] = qr[3];
        dk[0] = kr[0]; dk[1] = kr[1]; dk[2] = kr[2]; dk[3] = kr[3];
        uint32_t vu[8] = {v0.x, v0.y, v0.z, v0.w, v1.x, v1.y, v1.z, v1.w};
        uint32_t vu2[8] = {v2.x, v2.y, v2.z, v2.w, v3.x, v3.y, v3.z, v3.w};
        #pragma unroll
        for (int e = 0; e < 8; e++) {
            ((__nv_bfloat16*)(svt + (2 * e + 0) * 528))[tid] = ((__nv_bfloat162*)&vu[e])->x;
            ((__nv_bfloat16*)(svt + (2 * e + 1) * 528))[tid] = ((__nv_bfloat162*)&vu[e])->y;
        }
        #pragma unroll
        for (int e = 0; e < 8; e++) {
            ((__nv_bfloat16*)(svt + (16 + 2 * e + 0) * 528))[tid] = ((__nv_bfloat162*)&vu2[e])->x;
            ((__nv_bfloat16*)(svt + (16 + 2 * e + 1) * 528))[tid] = ((__nv_bfloat162*)&vu2[e])->y;
        }
    }
    __syncthreads();

    const int m0w = w * 32;
    uint32_t qa[2][2][4];
    #pragma unroll
    for (int i = 0; i < 2; i++)
        #pragma unroll
        for (int kk = 0; kk < 2; kk++) {
            int r = m0w + i * 16 + (lane & 15);
            uint32_t addr = smem_u32(sq + r * 80 + kk * 32 + (lane >> 4) * 16);
            asm volatile("ldmatrix.sync.aligned.m8n8.x4.shared.b16 {%0,%1,%2,%3}, [%4];"
                         : "=r"(qa[i][kk][0]), "=r"(qa[i][kk][1]),
                           "=r"(qa[i][kk][2]), "=r"(qa[i][kk][3])
                         : "r"(addr));
        }

    float oacc[2][4][4];
    #pragma unroll
    for (int i = 0; i < 2; i++)
        #pragma unroll
        for (int d = 0; d < 4; d++)
            #pragma unroll
            for (int q = 0; q < 4; q++) oacc[i][d][q] = 0.f;
    float mrow[2][2] = {{-1e30f, -1e30f}, {-1e30f, -1e30f}};
    float lrow[2][2] = {{0.f, 0.f}, {0.f, 0.f}};

    for (int jc = 0; jc < 8; jc++) {
        uint32_t kb[2][4][2];
        #pragma unroll
        for (int jp = 0; jp < 2; jp++)
            #pragma unroll
            for (int kk = 0; kk < 2; kk++) {
                int r = jc * 32 + jp * 16 + (lane & 15);
                uint32_t addr = smem_u32(sk + r * 80 + kk * 32 + (lane >> 4) * 16);
                uint32_t r0, r1, r2, r3;
                asm volatile("ldmatrix.sync.aligned.m8n8.x4.shared.b16 {%0,%1,%2,%3}, [%4];"
                             : "=r"(r0), "=r"(r1), "=r"(r2), "=r"(r3) : "r"(addr));
                kb[kk][2*jp][0] = r0;   kb[kk][2*jp][1] = r2;
                kb[kk][2*jp+1][0] = r1; kb[kk][2*jp+1][1] = r3;
            }

        float sacc[2][4][4];
        #pragma unroll
        for (int i = 0; i < 2; i++)
            #pragma unroll
            for (int nt = 0; nt < 4; nt++)
                #pragma unroll
                for (int q = 0; q < 4; q++) sacc[i][nt][q] = 0.f;
        #pragma unroll
        for (int kk = 0; kk < 2; kk++)
            #pragma unroll
            for (int i = 0; i < 2; i++)
                #pragma unroll
                for (int nt = 0; nt < 4; nt++) {
                    asm volatile("mma.sync.aligned.m16n8k16.row.col.f32.bf16.bf16.f32 "
                                 "{%0,%1,%2,%3}, {%4,%5,%6,%7}, {%8,%9}, {%0,%1,%2,%3};"
                                 : "+f"(sacc[i][nt][0]), "+f"(sacc[i][nt][1]),
                                   "+f"(sacc[i][nt][2]), "+f"(sacc[i][nt][3])
                                 : "r"(qa[i][kk][0]), "r"(qa[i][kk][1]),
                                   "r"(qa[i][kk][2]), "r"(qa[i][kk][3]),
                                   "r"(kb[kk][nt][0]), "r"(kb[kk][nt][1]));
                }

        #pragma unroll
        for (int i = 0; i < 2; i++)
            #pragma unroll
            for (int nt = 0; nt < 4; nt++)
                #pragma unroll
                for (int q = 0; q < 4; q++) sacc[i][nt][q] *= SC;

        #pragma unroll
        for (int i = 0; i < 2; i++) {
            #pragma unroll
            for (int half = 0; half < 2; half++) {
                float mx = -1e30f;
                #pragma unroll
                for (int nt = 0; nt < 4; nt++) {
                    mx = fmaxf(mx, sacc[i][nt][half*2+0]);
                    mx = fmaxf(mx, sacc[i][nt][half*2+1]);
                }
                mx = fmaxf(mx, __shfl_xor_sync(0xffffffffu, mx, 1));
                mx = fmaxf(mx, __shfl_xor_sync(0xffffffffu, mx, 2));
                float newm = fmaxf(mrow[i][half], mx);
                float alpha = fexp2_fast(mrow[i][half] - newm);
                mrow[i][half] = newm;
                float rs = 0.f;
                #pragma unroll
                for (int nt = 0; nt < 4; nt++) {
                    float p0 = fexp2_fast(sacc[i][nt][half*2+0] - newm);
                    float p1 = fexp2_fast(sacc[i][nt][half*2+1] - newm);
                    sacc[i][nt][half*2+0] = p0;
                    sacc[i][nt][half*2+1] = p1;
                    rs += p0 + p1;
                }
                rs += __shfl_xor_sync(0xffffffffu, rs, 1);
                rs += __shfl_xor_sync(0xffffffffu, rs, 2);
                lrow[i][half] = lrow[i][half] * alpha + rs;
                #pragma unroll
                for (int dt = 0; dt < 4; dt++) {
                    oacc[i][dt][half*2+0] *= alpha;
                    oacc[i][dt][half*2+1] *= alpha;
                }
            }
        }

        uint32_t pa[2][2][4];
        #pragma unroll
        for (int i = 0; i < 2; i++)
            #pragma unroll
            for (int kk = 0; kk < 2; kk++) {
                int ntl = kk * 2, nth = kk * 2 + 1;
                __nv_bfloat162 b0 = __float22bfloat162_rn(make_float2(sacc[i][ntl][0], sacc[i][ntl][1]));
                __nv_bfloat162 b1 = __float22bfloat162_rn(make_float2(sacc[i][ntl][2], sacc[i][ntl][3]));
                __nv_bfloat162 b2 = __float22bfloat162_rn(make_float2(sacc[i][nth][0], sacc[i][nth][1]));
                __nv_bfloat162 b3 = __float22bfloat162_rn(make_float2(sacc[i][nth][2], sacc[i][nth][3]));
                pa[i][kk][0] = *(uint32_t*)&b0;
                pa[i][kk][1] = *(uint32_t*)&b1;
                pa[i][kk][2] = *(uint32_t*)&b2;
                pa[i][kk][3] = *(uint32_t*)&b3;
            }

        uint32_t vb[2][4][2];
        #pragma unroll
        for (int jp = 0; jp < 2; jp++)
            #pragma unroll
            for (int kk = 0; kk < 2; kk++) {
                int r = jp * 16 + (lane & 15);
                uint32_t addr = smem_u32(svt + r * 528 + jc * 64 + kk * 32 + (lane >> 4) * 16);
                uint32_t r0, r1, r2, r3;
                asm volatile("ldmatrix.sync.aligned.m8n8.x4.shared.b16 {%0,%1,%2,%3}, [%4];"
                             : "=r"(r0), "=r"(r1), "=r"(r2), "=r"(r3) : "r"(addr));
                vb[kk][2*jp][0] = r0;   vb[kk][2*jp][1] = r2;
                vb[kk][2*jp+1][0] = r1; vb[kk][2*jp+1][1] = r3;
            }

        #pragma unroll
        for (int kk = 0; kk < 2; kk++)
            #pragma unroll
            for (int i = 0; i < 2; i++)
                #pragma unroll
                for (int dt = 0; dt < 4; dt++) {
                    asm volatile("mma.sync.aligned.m16n8k16.row.col.f32.bf16.bf16.f32 "
                                 "{%0,%1,%2,%3}, {%4,%5,%6,%7}, {%8,%9}, {%0,%1,%2,%3};"
                                 : "+f"(oacc[i][dt][0]), "+f"(oacc[i][dt][1]),
                                   "+f"(oacc[i][dt][2]), "+f"(oacc[i][dt][3])
                                 : "r"(pa[i][kk][0]), "r"(pa[i][kk][1]),
                                   "r"(pa[i][kk][2]), "r"(pa[i][kk][3]),
                                   "r"(vb[kk][dt][0]), "r"(vb[kk][dt][1]));
                }
    }

    #pragma unroll
    for (int i = 0; i < 2; i++)
        #pragma unroll
        for (int half = 0; half < 2; half++) {
            float inv = 1.f / lrow[i][half];
            int row = m0w + i * 16 + half * 8 + (lane >> 2);
            #pragma unroll
            for (int dt = 0; dt < 4; dt++) {
                int col = h * 32 + dt * 8 + 2 * (lane & 3);
                __nv_bfloat162 hv;
                hv.x = __float2bfloat16(oacc[i][dt][half*2+0] * inv);
                hv.y = __float2bfloat16(oacc[i][dt][half*2+1] * inv);
                *(__nv_bfloat162*)(o + (base + row) * 256 + col) = hv;
            }
        }
}

// ---------------- fold gt into per-cloud biases ----------------
__global__ void cloudbias_kernel(const float* __restrict__ gtsum,
                                 const float* __restrict__ gg_w1, const float* __restrict__ gg_b1,
                                 const float* __restrict__ f_w1, const float* __restrict__ f_b1,
                                 float* __restrict__ ggb, float* __restrict__ fb, int Lc) {
    int c = blockIdx.x, j = threadIdx.x;
    float s1 = gg_b1[j], s2 = f_b1[j];
    float invL = 1.f / (float)Lc;
    for (int h = 0; h < 256; h++) {
        float gv = gtsum[c * 256 + h] * invL;
        s1 += gv * gg_w1[(size_t)(256 + h) * 256 + j];
        s2 += gv * f_w1[(size_t)(256 + h) * 256 + j];
    }
    ggb[c * 256 + j] = s1;
    fb[c * 256 + j] = s2;
}

// ---------------- launch ----------------
extern "C" void kernel_launch(void* const* d_in, const int* in_sizes, int n_in,
                              void* d_out, int out_size) {
    const float* feats = (const float*)d_in[0];
    const float* coord = (const float*)d_in[1];
    const float* pe_w1 = (const float*)d_in[3];
    const float* pe_b1 = (const float*)d_in[4];
    const float* pe_w2 = (const float*)d_in[5];
    const float* pe_b2 = (const float*)d_in[6];
    const float* pre_g = (const float*)d_in[7];
    const float* pre_b = (const float*)d_in[8];
    const float* n1_g  = (const float*)d_in[9];
    const float* n1_b  = (const float*)d_in[10];
    const float* wqkv  = (const float*)d_in[11];
    const float* bqkv  = (const float*)d_in[12];
    const float* wo    = (const float*)d_in[13];
    const float* bo    = (const float*)d_in[14];
    const float* n2_g  = (const float*)d_in[15];
    const float* n2_b  = (const float*)d_in[16];
    const float* m_w1  = (const float*)d_in[17];
    const float* m_b1  = (const float*)d_in[18];
    const float* m_w2  = (const float*)d_in[19];
    const float* m_b2  = (const float*)d_in[20];
    const float* gg_w1 = (const float*)d_in[21];
    const float* gg_b1 = (const float*)d_in[22];
    const float* gg_w2 = (const float*)d_in[23];
    const float* gg_b2 = (const float*)d_in[24];
    const float* f_w1  = (const float*)d_in[25];
    const float* f_b1  = (const float*)d_in[26];
    const float* f_w2  = (const float*)d_in[27];
    const float* f_b2  = (const float*)d_in[28];
    float* out = (float*)d_out;

    int N = in_sizes[0] / 256;
    int B = in_sizes[2];
    int Lc = N / B;
    int patches = N / 256;

    float *p_x, *p_xs, *p_key, *p_gt, *p_ggb, *p_fb, *p_stats;
    __nv_bfloat16 *p_ba, *p_bb, *p_fe, *p_gr, *p_wt;
    int* p_idx;
    cudaGetSymbolAddress((void**)&p_x, g_x);
    cudaGetSymbolAddress((void**)&p_xs, g_xs);
    cudaGetSymbolAddress((void**)&p_ba, g_ba);
    cudaGetSymbolAddress((void**)&p_bb, g_bb);
    cudaGetSymbolAddress((void**)&p_fe, g_fe);
    cudaGetSymbolAddress((void**)&p_gr, g_gr);
    cudaGetSymbolAddress((void**)&p_wt, g_wt);
    cudaGetSymbolAddress((void**)&p_key, g_key);
    cudaGetSymbolAddress((void**)&p_idx, g_idx);
    cudaGetSymbolAddress((void**)&p_gt, g_gt);
    cudaGetSymbolAddress((void**)&p_ggb, g_ggb);
    cudaGetSymbolAddress((void**)&p_fb, g_fb);
    cudaGetSymbolAddress((void**)&p_stats, g_stats);

    __nv_bfloat16* wqkv_t = p_wt + 0;
    __nv_bfloat16* wo_t   = p_wt + 196608;
    __nv_bfloat16* mw1_t  = p_wt + 262144;
    __nv_bfloat16* mw2_t  = p_wt + 393216;
    __nv_bfloat16* ggw1_t = p_wt + 524288;
    __nv_bfloat16* ggw2_t = p_wt + 589824;
    __nv_bfloat16* fw1_t  = p_wt + 655360;
    __nv_bfloat16* fw2_t  = p_wt + 720896;
    __nv_bfloat16* bb_lo = p_bb;
    __nv_bfloat16* bb_hi = p_bb + (size_t)N * 256;

    static cudaStream_t s2 = nullptr;
    static cudaEvent_t ev1 = nullptr, ev2 = nullptr, ev4 = nullptr, ev5 = nullptr;
    if (!s2) {
        cudaStreamCreateWithFlags(&s2, cudaStreamNonBlocking);
        cudaEventCreateWithFlags(&ev1, cudaEventDisableTiming);
        cudaEventCreateWithFlags(&ev2, cudaEventDisableTiming);
        cudaEventCreateWithFlags(&ev4, cudaEventDisableTiming);
        cudaEventCreateWithFlags(&ev5, cudaEventDisableTiming);
    }

    cudaFuncSetAttribute(fattn, cudaFuncAttributeMaxDynamicSharedMemorySize, FA_SMEM);
    cudaFuncSetAttribute(gemm_bf16<8>, cudaFuncAttributeMaxDynamicSharedMemorySize, NSTAGE * STG_BYTES);
    cudaFuncSetAttribute(gemm_bf16<16>, cudaFuncAttributeMaxDynamicSharedMemorySize, NSTAGE * STG_BYTES);

    PrepArgs pa;
    pa.coord = coord; pa.stats = p_stats; pa.Lc = Lc; pa.B = B;
    const float* ws[8] = {wqkv, wo, m_w1, m_w2, gg_w1, gg_w2, f_w1, f_w2};
    __nv_bfloat16* wd[8] = {wqkv_t, wo_t, mw1_t, mw2_t, ggw1_t, ggw2_t, fw1_t, fw2_t};
    int wK[8] = {256, 256, 256, 512, 256, 256, 256, 256};
    int wN[8] = {768, 256, 512, 256, 256, 256, 256, 256};
    int tiles = 0;
    for (int i = 0; i < 8; i++) {
        pa.wsrc[i] = ws[i]; pa.wdst[i] = wd[i];
        pa.wK[i] = wK[i]; pa.wN[i] = wN[i];
        pa.wt0[i] = tiles;
        tiles += (wK[i] / 32) * (wN[i] / 32);
    }
    pa.totalWTiles = tiles;
    pa.gt = p_gt;
    const float* zerobias = p_gt + 1024;  // zeroed in prep, untouched by gt atomics

    // 1: prep
    prep_kernel<<<B + tiles + 1, 1024>>>(pa);
    // 2: PE + pre-LN + LN1 + key
    pe_ln_key_kernel<<<N, 256>>>(feats, coord, pe_w1, pe_b1, pe_w2, pe_b2,
                                 pre_g, pre_b, n1_g, n1_b, p_stats,
                                 p_x, p_bb, p_fe, p_key, p_idx, Lc);
    // fork: sort + gate_raw on s2; qkv on main
    cudaEventRecord(ev1, 0);
    cudaStreamWaitEvent(s2, ev1, 0);
    // 3 (s2): local sort
    sort_local<<<N / CHUNK, 1024, CHUNK * 8, s2>>>(p_key, p_idx, Lc);
    // 4 (main): qkv GEMM -> ba  [profiled launch]
    gemm_bf16<8><<<dim3(768/GBN, N/GBM), 256, NSTAGE*STG_BYTES>>>(
        p_bb, wqkv_t, bqkv, nullptr, nullptr, p_ba, N, 768, 0, 0, 1,
        nullptr, nullptr, 0, nullptr, nullptr, nullptr, nullptr);
    // (s2): finish sort
    for (int k = CHUNK * 2; k <= Lc; k <<= 1) {
        for (int j = k >> 1; j >= CHUNK; j >>= 1)
            sort_global<<<dim3(Lc / 512, B), 256, 0, s2>>>(p_key, p_idx, k, j, Lc);
        merge_local<<<N / CHUNK, 1024, CHUNK * 8, s2>>>(p_key, p_idx, k, Lc);
    }
    cudaEventRecord(ev2, s2);
    // (s2): gate_raw = feats_bf16 @ gg_w1 (no bias) -> gr  [overlaps fattn/wo/mlp1]
    gemm_bf16<8><<<dim3(256/GBN, N/GBM), 256, NSTAGE*STG_BYTES, s2>>>(
        p_fe, ggw1_t, zerobias, nullptr, nullptr, p_gr, N, 256, 0, 0, 1,
        nullptr, nullptr, 0, nullptr, nullptr, nullptr, nullptr);
    // main: wait only for the sort
    cudaStreamWaitEvent(0, ev2, 0);
    // fattn -> bb
    fattn<<<dim3(patches, 8), 256, FA_SMEM>>>(p_ba, p_idx, p_bb);
    // wo GEMM + gathered residual -> xs fp32
    gemm_bf16<8><<<dim3(256/GBN, N/GBM), 256, NSTAGE*STG_BYTES>>>(
        p_bb, wo_t, bo, p_x, nullptr, p_xs, N, 256, 0, 4, 0,
        p_idx, nullptr, 0, nullptr, nullptr, nullptr, nullptr);
    // LN2 -> ba
    ln_bf<<<N, 256>>>(p_xs, n2_g, n2_b, p_ba);
    // MLP1 + gelu -> bb
    gemm_bf16<8><<<dim3(512/GBN, N/GBM), 256, NSTAGE*STG_BYTES>>>(
        p_ba, mw1_t, m_b1, nullptr, nullptr, p_bb, N, 512, 0, 2, 1,
        nullptr, nullptr, 0, nullptr, nullptr, nullptr, nullptr);
    // MLP2 + resid; scatter xo -> ba; gt atomics
    gemm_bf16<16><<<dim3(256/GBN, N/GBM), 256, NSTAGE*STG_BYTES>>>(
        p_bb, mw2_t, m_b2, p_xs, nullptr, p_ba, N, 256, 0, 6, 1,
        p_idx, p_gt, Lc, nullptr, nullptr, nullptr, nullptr);
    // per-cloud biases
    cloudbias_kernel<<<B, 256>>>(p_gt, gg_w1, gg_b1, f_w1, f_b1, p_ggb, p_fb, Lc);
    // fork2: gate branch on s2, fuse branch on main
    cudaEventRecord(ev4, 0);
    cudaStreamWaitEvent(s2, ev4, 0);
    // (s2): bias+relu gate hidden -> bb_lo
    biasrelu<<<N, 256, 0, s2>>>(p_gr, p_ggb, bb_lo, Lc);
    // (s2): gate = sigmoid(bb_lo @ gg_w2 + gg_b2) -> p_x fp32
    gemm_bf16<8><<<dim3(256/GBN, N/GBM), 256, NSTAGE*STG_BYTES, s2>>>(
        bb_lo, ggw2_t, gg_b2, nullptr, nullptr, p_x, N, 256, 0, 3, 0,
        nullptr, nullptr, 0, nullptr, nullptr, nullptr, nullptr);
    cudaEventRecord(ev5, s2);
    // (main): fuse hidden: relu(xo @ f_w1_top + fb[cloud]) -> bb_hi
    gemm_bf16<8><<<dim3(256/GBN, N/GBM), 256, NSTAGE*STG_BYTES>>>(
        p_ba, fw1_t, p_fb, nullptr, nullptr, bb_hi, N, 256, Lc, 1, 1,
        nullptr, nullptr, 0, nullptr, nullptr, nullptr, nullptr);
    // join: final needs both branches
    cudaStreamWaitEvent(0, ev5, 0);
    // out = feats + gate * (bb_hi @ f_w2 + f_b2)
    gemm_bf16<8><<<dim3(256/GBN, N/GBM), 256, NSTAGE*STG_BYTES>>>(
        bb_hi, fw2_t, f_b2, feats, p_x, out, N, 256, 0, 5, 0,
        nullptr, nullptr, 0, nullptr, nullptr, nullptr, nullptr);
}

// round 11
// speedup vs baseline: 1.0827x; 1.0827x over previous
#include <cuda_runtime.h>
#include <cuda_bf16.h>
#include <math.h>
#include <stdint.h>

// ---------------- static scratch ----------------
#define MAXN 131072
#define DD 256
__device__ float g_x  [(size_t)MAXN * DD];
__device__ float g_xs [(size_t)MAXN * DD];
__device__ __nv_bfloat16 g_ba[(size_t)MAXN * 768];
__device__ __nv_bfloat16 g_bb[(size_t)MAXN * 512];
__device__ __nv_bfloat16 g_fe[(size_t)MAXN * 256];
__device__ __nv_bfloat16 g_wt[786432];
__device__ float g_key[MAXN];
__device__ int   g_idx[MAXN];
__device__ float g_gt [8 * DD];
__device__ float g_ggb[8 * DD];
__device__ float g_fb [8 * DD];
__device__ float g_stats[8 * 12];

// ---------------- fast math ----------------
__device__ __forceinline__ float fexp2_fast(float z) {
    z = fmaxf(z, -80.f);
    float n = rintf(z);
    float f = z - n;
    float p = 0.009618129f;
    p = p * f + 0.055504109f;
    p = p * f + 0.240226507f;
    p = p * f + 0.693147181f;
    p = p * f + 1.0f;
    return p * __int_as_float(((int)n + 127) << 23);
}
__device__ __forceinline__ float fexpf_fast(float x) {
    return fexp2_fast(x * 1.4426950408889634f);
}
__device__ __forceinline__ float frcp_fast(float d) {
    float y = __int_as_float(0x7ef311c3 - __float_as_int(d));
    y = y * (2.f - d * y);
    y = y * (2.f - d * y);
    y = y * (2.f - d * y);
    return y;
}
__device__ __forceinline__ uint32_t smem_u32(const void* p) {
    return (uint32_t)__cvta_generic_to_shared(p);
}
__device__ __forceinline__ float blocksum256(float v, float* red8) {
    #pragma unroll
    for (int off = 16; off; off >>= 1) v += __shfl_xor_sync(0xffffffffu, v, off);
    if ((threadIdx.x & 31) == 0) red8[threadIdx.x >> 5] = v;
    __syncthreads();
    float s = 0.f;
    #pragma unroll
    for (int i = 0; i < 8; i++) s += red8[i];
    return s;
}

// ---------------- prep ----------------
struct PrepArgs {
    const float* coord; float* stats; int Lc; int B;
    const float* wsrc[8]; __nv_bfloat16* wdst[8];
    int wK[8], wN[8], wt0[8];
    int totalWTiles;
    float* gt;
};
__global__ void __launch_bounds__(1024) prep_kernel(PrepArgs a) {
    __shared__ float red[1024];
    __shared__ float tt[32][33];
    int b = blockIdx.x, tid = threadIdx.x;
    if (b < a.B) {
        int c = b, Lc = a.Lc;
        float sum[3] = {0,0,0}, mn[3] = {1e30f,1e30f,1e30f}, mx[3] = {-1e30f,-1e30f,-1e30f};
        for (int i = tid; i < Lc; i += 1024) {
            const float* cp = a.coord + (size_t)(c * Lc + i) * 3;
            #pragma unroll
            for (int d = 0; d < 3; d++) {
                float v = cp[d];
                sum[d] += v; mn[d] = fminf(mn[d], v); mx[d] = fmaxf(mx[d], v);
            }
        }
        for (int d = 0; d < 3; d++) {
            red[tid] = sum[d]; __syncthreads();
            for (int s = 512; s > 0; s >>= 1) { if (tid < s) red[tid] += red[tid + s]; __syncthreads(); }
            float tot = red[0]; __syncthreads();
            red[tid] = mn[d]; __syncthreads();
            for (int s = 512; s > 0; s >>= 1) { if (tid < s) red[tid] = fminf(red[tid], red[tid + s]); __syncthreads(); }
            float tmn = red[0]; __syncthreads();
            red[tid] = mx[d]; __syncthreads();
            for (int s = 512; s > 0; s >>= 1) { if (tid < s) red[tid] = fmaxf(red[tid], red[tid + s]); __syncthreads(); }
            float tmx = red[0]; __syncthreads();
            if (tid == 0) {
                float mean = tot / (float)Lc;
                a.stats[c*12 + d]     = mean;
                a.stats[c*12 + 3 + d] = fmaxf(fmaxf(tmx - mean, mean - tmn), 1e-6f);
                a.stats[c*12 + 6 + d] = tmn;
                a.stats[c*12 + 9 + d] = 1.f / fmaxf(tmx - tmn, 1e-6f);
            }
            __syncthreads();
        }
    } else if (b < a.B + a.totalWTiles) {
        int t = b - a.B;
        int w = 0;
        #pragma unroll
        for (int q = 1; q < 8; q++) if (t >= a.wt0[q]) w = q;
        int lt = t - a.wt0[w];
        int tilesX = a.wN[w] >> 5;
        int bx = (lt % tilesX) << 5, by = (lt / tilesX) << 5;
        const float* src = a.wsrc[w];
        __nv_bfloat16* dst = a.wdst[w];
        int K = a.wK[w], Ncols = a.wN[w];
        int tx = tid & 31, ty = tid >> 5;
        tt[ty][tx] = src[(size_t)(by + ty) * Ncols + bx + tx];
        __syncthreads();
        dst[(size_t)(bx + ty) * K + by + tx] = __float2bfloat16(tt[tx][ty]);
    } else {
        a.gt[tid] = 0.f;
        a.gt[tid + 1024] = 0.f;
    }
}

// ---------------- PE + pre-LN + LN1 + key + feats->bf16 ----------------
__global__ void __launch_bounds__(256) pe_ln_key_kernel(
    const float* __restrict__ feats, const float* __restrict__ coord,
    const float* __restrict__ w1, const float* __restrict__ b1,
    const float* __restrict__ w2, const float* __restrict__ b2,
    const float* __restrict__ g, const float* __restrict__ beta,
    const float* __restrict__ n1g, const float* __restrict__ n1b,
    const float* __restrict__ stats,
    float* __restrict__ xout, __nv_bfloat16* __restrict__ hbf,
    __nv_bfloat16* __restrict__ febf,
    float* __restrict__ key, int* __restrict__ idx, int Lc)
{
    int i = blockIdx.x, tid = threadIdx.x;
    int c = i / Lc;
    __shared__ float hid[64];
    __shared__ float red8[8];
    const float* st = stats + c * 12;
    float c0 = coord[(size_t)i*3+0], c1 = coord[(size_t)i*3+1], c2 = coord[(size_t)i*3+2];
    if (tid < 64) {
        float n0 = (c0 - st[0]) / st[3];
        float n1 = (c1 - st[1]) / st[4];
        float n2 = (c2 - st[2]) / st[5];
        float hv = b1[tid] + n0 * w1[tid] + n1 * w1[64 + tid] + n2 * w1[128 + tid];
        hid[tid] = fmaxf(hv, 0.f);
    }
    if (tid == 0) {
        float k0 = (c0 - st[6]) * st[9];
        float k1 = (c1 - st[7]) * st[10];
        float k2 = (c2 - st[8]) * st[11];
        key[i] = k0 + 2.17f * k1 + 3.31f * k2;
        idx[i] = i;
    }
    __syncthreads();
    float fv = feats[(size_t)i * 256 + tid];
    febf[(size_t)i * 256 + tid] = __float2bfloat16(fv);
    float pe = b2[tid];
    #pragma unroll 8
    for (int h = 0; h < 64; h++) pe += hid[h] * w2[h * 256 + tid];
    float v = fv + pe;
    float mean = blocksum256(v, red8) * (1.f / 256.f);
    __syncthreads();
    float dv = v - mean;
    float var = blocksum256(dv * dv, red8) * (1.f / 256.f);
    float xv = dv * rsqrtf(var + 1e-5f) * g[tid] + beta[tid];
    xout[(size_t)i * 256 + tid] = xv;
    __syncthreads();
    float m2 = blocksum256(xv, red8) * (1.f / 256.f);
    __syncthreads();
    float d2 = xv - m2;
    float v2 = blocksum256(d2 * d2, red8) * (1.f / 256.f);
    hbf[(size_t)i * 256 + tid] = __float2bfloat16(d2 * rsqrtf(v2 + 1e-5f) * n1g[tid] + n1b[tid]);
}

// ---------------- hierarchical bitonic sort (CHUNK=4096) ----------------
#define CHUNK 4096
__global__ void __launch_bounds__(1024) sort_local(float* __restrict__ key, int* __restrict__ idx, int Lc) {
    extern __shared__ char smraw[];
    float* sk = (float*)smraw;
    int*   si = (int*)(smraw + CHUNK * 4);
    size_t gbase = (size_t)blockIdx.x * CHUNK;
    int lbase = (int)(gbase % (size_t)Lc);
    for (int t = threadIdx.x; t < CHUNK; t += 1024) { sk[t] = key[gbase + t]; si[t] = idx[gbase + t]; }
    __syncthreads();
    for (int k = 2; k <= CHUNK; k <<= 1) {
        for (int j = k >> 1; j > 0; j >>= 1) {
            #pragma unroll
            for (int it = 0; it < CHUNK / 2048; it++) {
                int t = threadIdx.x + it * 1024;
                int i = 2 * t - (t & (j - 1));
                int p = i + j;
                bool up = (((lbase + i) & k) == 0);
                float a = sk[i], b = sk[p];
                int ia = si[i], ib = si[p];
                bool sw = up ? (a > b || (a == b && ia > ib)) : (a < b || (a == b && ia < ib));
                if (sw) { sk[i] = b; sk[p] = a; si[i] = ib; si[p] = ia; }
            }
            __syncthreads();
        }
    }
    for (int t = threadIdx.x; t < CHUNK; t += 1024) { key[gbase + t] = sk[t]; idx[gbase + t] = si[t]; }
}

__global__ void __launch_bounds__(1024) merge_local(float* __restrict__ key, int* __restrict__ idx, int k, int Lc) {
    extern __shared__ char smraw[];
    float* sk = (float*)smraw;
    int*   si = (int*)(smraw + CHUNK * 4);
    size_t gbase = (size_t)blockIdx.x * CHUNK;
    int lbase = (int)(gbase % (size_t)Lc);
    for (int t = threadIdx.x; t < CHUNK; t += 1024) { sk[t] = key[gbase + t]; si[t] = idx[gbase + t]; }
    __syncthreads();
    for (int j = CHUNK / 2; j > 0; j >>= 1) {
        #pragma unroll
        for (int it = 0; it < CHUNK / 2048; it++) {
            int t = threadIdx.x + it * 1024;
            int i = 2 * t - (t & (j - 1));
            int p = i + j;
            bool up = (((lbase + i) & k) == 0);
            float a = sk[i], b = sk[p];
            int ia = si[i], ib = si[p];
            bool sw = up ? (a > b || (a == b && ia > ib)) : (a < b || (a == b && ia < ib));
            if (sw) { sk[i] = b; sk[p] = a; si[i] = ib; si[p] = ia; }
        }
        __syncthreads();
    }
    for (int t = threadIdx.x; t < CHUNK; t += 1024) { key[gbase + t] = sk[t]; idx[gbase + t] = si[t]; }
}

__global__ void __launch_bounds__(256) sort_global(float* __restrict__ key, int* __restrict__ idx, int k, int j, int Lc) {
    int c = blockIdx.y;
    size_t base = (size_t)c * Lc;
    int t = blockIdx.x * 256 + threadIdx.x;
    int i = 2 * t - (t & (j - 1));
    int p = i + j;
    bool up = ((i & k) == 0);
    float a = key[base + i], b = key[base + p];
    int ia = idx[base + i], ib = idx[base + p];
    bool sw = up ? (a > b || (a == b && ia > ib)) : (a < b || (a == b && ia < ib));
    if (sw) {
        key[base + i] = b; key[base + p] = a;
        idx[base + i] = ib; idx[base + p] = ia;
    }
}

// ---------------- LN -> bf16 ----------------
__global__ void __launch_bounds__(256) ln_bf(const float* __restrict__ x, const float* __restrict__ g,
                                             const float* __restrict__ b, __nv_bfloat16* __restrict__ y) {
    int row = blockIdx.x, tid = threadIdx.x;
    __shared__ float red8[8];
    float v = x[(size_t)row * 256 + tid];
    float mean = blocksum256(v, red8) * (1.f / 256.f);
    __syncthreads();
    float dv = v - mean;
    float var = blocksum256(dv * dv, red8) * (1.f / 256.f);
    y[(size_t)row * 256 + tid] = __float2bfloat16(dv * rsqrtf(var + 1e-5f) * g[tid] + b[tid]);
}

// ---------------- tensor-core GEMM: 128x64 tile, warp tile 32x32, 3 CTAs/SM ----------------
// epi: 0 none, 1 relu, 2 gelu, 3 sigmoid, 4 +resid[ridx], 5 resid + gate*val,
//      6 +resid[m]; bf16 scatter to Cout[ridx[m]]; atomic gt column sums
#define GBM 128
#define GBN 64
#define GKT 32
#define STG_BYTES 15360   // A 10240 + B 5120
#define NSTAGE 4

template<int NK>
__global__ void __launch_bounds__(256, 3) gemm_bf16(
    const __nv_bfloat16* __restrict__ A_, const __nv_bfloat16* __restrict__ Bt_,
    const float* __restrict__ bias_,
    const float* __restrict__ resid, const float* __restrict__ gate,
    void* __restrict__ Cout_,
    int M, int Ncols, int cloudLen, int epi, int outBf16,
    const int* __restrict__ ridx, float* __restrict__ gtp, int gtLc,
    const __nv_bfloat16* A2, const __nv_bfloat16* Bt2, const float* bias2, void* Cout2)
{
    constexpr int K = NK * GKT;
    extern __shared__ char smraw[];
    const __nv_bfloat16* A = A_;
    const __nv_bfloat16* Bt = Bt_;
    const float* bias = bias_;
    void* Cout = Cout_;
    if (blockIdx.z == 1) { A = A2; Bt = Bt2; bias = bias2; Cout = Cout2; }
    const int tid = threadIdx.x;
    const int lane = tid & 31;
    const int warp = tid >> 5;
    const int wm = warp >> 1, wn = warp & 1;       // 4 x 2 warp grid, 32x32 per warp
    const int m0 = blockIdx.y * GBM, n0 = blockIdx.x * GBN;

    float acc[2][4][4];
    #pragma unroll
    for (int i = 0; i < 2; i++)
        #pragma unroll
        for (int j = 0; j < 4; j++)
            #pragma unroll
            for (int q = 0; q < 4; q++) acc[i][j][q] = 0.f;

    // cp.async: A 512 chunks (2/thread), B 256 chunks (1/thread)
    const int arow0 = tid >> 2, ac0 = tid & 3;
    const int arow1 = (tid + 256) >> 2;
    const __nv_bfloat16* gA0 = A + (size_t)(m0 + arow0) * K + ac0 * 8;
    const __nv_bfloat16* gA1 = A + (size_t)(m0 + arow1) * K + ac0 * 8;
    const __nv_bfloat16* gB0 = Bt + (size_t)(n0 + (tid >> 2)) * K + ac0 * 8;
    const uint32_t smemBase = smem_u32(smraw);
    const uint32_t dA0 = smemBase + arow0 * 80 + ac0 * 16;
    const uint32_t dA1 = smemBase + arow1 * 80 + ac0 * 16;
    const uint32_t dB0 = smemBase + 10240 + ((tid >> 2) & 63) * 80 + ac0 * 16;
    const bool bAct = (tid >> 2) < 64;  // B rows 0..63 (tid 0..255 -> rows 0..63 all, ok)

    // ldmatrix offsets (stage-relative)
    uint32_t aoff[2], boff[2];
    #pragma unroll
    for (int i = 0; i < 2; i++)
        aoff[i] = smemBase + (wm * 32 + i * 16 + (lane & 15)) * 80 + (lane >> 4) * 16;
    #pragma unroll
    for (int jp = 0; jp < 2; jp++)
        boff[jp] = smemBase + 10240 + (wn * 32 + jp * 16 + (lane & 15)) * 80 + (lane >> 4) * 16;

    auto issue = [&](int s, int kt) {
        uint32_t sb = s * STG_BYTES;
        int go = kt * GKT;
        asm volatile("cp.async.cg.shared.global [%0], [%1], 16;\n" :: "r"(dA0 + sb), "l"(gA0 + go));
        asm volatile("cp.async.cg.shared.global [%0], [%1], 16;\n" :: "r"(dA1 + sb), "l"(gA1 + go));
        asm volatile("cp.async.cg.shared.global [%0], [%1], 16;\n" :: "r"(dB0 + sb), "l"(gB0 + go));
        asm volatile("cp.async.commit_group;\n");
    };

    issue(0, 0);
    issue(1, 1);
    #pragma unroll
    for (int kt = 0; kt < NK; kt++) {
        const int s = kt & (NSTAGE - 1);
        if (kt + 2 < NK) {
            issue((kt + 2) & (NSTAGE - 1), kt + 2);
            asm volatile("cp.async.wait_group 2;\n");
        } else if (kt + 1 < NK) {
            asm volatile("cp.async.wait_group 1;\n");
        } else {
            asm volatile("cp.async.wait_group 0;\n");
        }
        __syncthreads();

        const uint32_t sb = s * STG_BYTES;
        #pragma unroll
        for (int kk = 0; kk < 2; kk++) {
            uint32_t af[2][4];
            #pragma unroll
            for (int i = 0; i < 2; i++) {
                asm volatile("ldmatrix.sync.aligned.m8n8.x4.shared.b16 {%0,%1,%2,%3}, [%4];"
                             : "=r"(af[i][0]), "=r"(af[i][1]), "=r"(af[i][2]), "=r"(af[i][3])
                             : "r"(aoff[i] + sb + kk * 32));
            }
            uint32_t bf[4][2];
            #pragma unroll
            for (int jp = 0; jp < 2; jp++) {
                uint32_t r0, r1, r2, r3;
                asm volatile("ldmatrix.sync.aligned.m8n8.x4.shared.b16 {%0,%1,%2,%3}, [%4];"
                             : "=r"(r0), "=r"(r1), "=r"(r2), "=r"(r3)
                             : "r"(boff[jp] + sb + kk * 32));
                bf[2*jp][0] = r0; bf[2*jp+1][0] = r1;
                bf[2*jp][1] = r2; bf[2*jp+1][1] = r3;
            }
            #pragma unroll
            for (int i = 0; i < 2; i++)
                #pragma unroll
                for (int j = 0; j < 4; j++) {
                    asm volatile("mma.sync.aligned.m16n8k16.row.col.f32.bf16.bf16.f32 "
                                 "{%0,%1,%2,%3}, {%4,%5,%6,%7}, {%8,%9}, {%0,%1,%2,%3};"
                                 : "+f"(acc[i][j][0]), "+f"(acc[i][j][1]),
                                   "+f"(acc[i][j][2]), "+f"(acc[i][j][3])
                                 : "r"(af[i][0]), "r"(af[i][1]), "r"(af[i][2]), "r"(af[i][3]),
                                   "r"(bf[j][0]), "r"(bf[j][1]));
                }
        }
    }

    const int rbase = m0 + wm * 32 + (lane >> 2);
    const int cbase = n0 + wn * 32 + 2 * (lane & 3);
    float gta[4][2];
    #pragma unroll
    for (int j = 0; j < 4; j++) { gta[j][0] = 0.f; gta[j][1] = 0.f; }

    #pragma unroll
    for (int i = 0; i < 2; i++) {
        #pragma unroll
        for (int half = 0; half < 2; half++) {
            int m = rbase + i * 16 + half * 8;
            const float* bp = (cloudLen > 0) ? (bias + (size_t)(m / cloudLen) * Ncols) : bias;
            #pragma unroll
            for (int j = 0; j < 4; j++) {
                int n = cbase + j * 8;
                float v0 = acc[i][j][half * 2 + 0] + bp[n];
                float v1 = acc[i][j][half * 2 + 1] + bp[n + 1];
                size_t o = (size_t)m * Ncols + n;
                bool stored = false;
                switch (epi) {
                    case 1: v0 = fmaxf(v0, 0.f); v1 = fmaxf(v1, 0.f); break;
                    case 2:
                        v0 = 0.5f * v0 * (1.f + erff(v0 * 0.70710678118f));
                        v1 = 0.5f * v1 * (1.f + erff(v1 * 0.70710678118f));
                        break;
                    case 3:
                        v0 = frcp_fast(1.f + fexpf_fast(-v0));
                        v1 = frcp_fast(1.f + fexpf_fast(-v1));
                        break;
                    case 4: {
                        size_t ro = (size_t)(ridx ? ridx[m] : m) * Ncols + n;
                        float2 r = *(const float2*)(resid + ro);
                        v0 += r.x; v1 += r.y;
                    } break;
                    case 5: {
                        float2 r = *(const float2*)(resid + o);
                        float2 gg = *(const float2*)(gate + o);
                        v0 = r.x + gg.x * v0; v1 = r.y + gg.y * v1;
                    } break;
                    case 6: {
                        float2 r = *(const float2*)(resid + o);
                        v0 += r.x; v1 += r.y;
                        gta[j][0] += v0; gta[j][1] += v1;
                        size_t od = (size_t)ridx[m] * Ncols + n;
                        __nv_bfloat162 h;
                        h.x = __float2bfloat16(v0); h.y = __float2bfloat16(v1);
                        *(__nv_bfloat162*)((__nv_bfloat16*)Cout + od) = h;
                        stored = true;
                    } break;
                    default: break;
                }
                if (!stored) {
                    if (outBf16) {
                        __nv_bfloat162 h;
                        h.x = __float2bfloat16(v0); h.y = __float2bfloat16(v1);
                        *(__nv_bfloat162*)((__nv_bfloat16*)Cout + o) = h;
                    } else {
                        *(float2*)((float*)Cout + o) = make_float2(v0, v1);
                    }
                }
            }
        }
    }
    if (epi == 6) {
        int c = m0 / gtLc;
        #pragma unroll
        for (int j = 0; j < 4; j++) {
            float s0 = gta[j][0], s1 = gta[j][1];
            #pragma unroll
            for (int off = 4; off <= 16; off <<= 1) {
                s0 += __shfl_xor_sync(0xffffffffu, s0, off);
                s1 += __shfl_xor_sync(0xffffffffu, s1, off);
            }
            if ((lane >> 2) == 0) {
                int n = cbase + j * 8;
                atomicAdd(gtp + c * 256 + n, s0);
                atomicAdd(gtp + c * 256 + n + 1, s1);
            }
        }
    }
}

// ---------------- flash attention (gathers rows via sidx) ----------------
#define FA_SMEM (20480 * 2 + 32 * 528)
__global__ void __launch_bounds__(256) fattn(const __nv_bfloat16* __restrict__ qkv,
                                             const int* __restrict__ sidx,
                                             __nv_bfloat16* __restrict__ o) {
    extern __shared__ char sm[];
    char* sq = sm;
    char* sk = sm + 20480;
    char* svt = sm + 40960;
    const int p = blockIdx.x, h = blockIdx.y;
    const int tid = threadIdx.x;
    const int lane = tid & 31;
    const int w = tid >> 5;
    const size_t base = (size_t)p * 256;
    const float SC = 0.17677669529663687f * 1.4426950408889634f;

    {
        const size_t src = (size_t)sidx[base + tid] * 768;
        const uint4* qr = (const uint4*)(qkv + src + h * 32);
        const uint4* kr = (const uint4*)(qkv + src + 256 + h * 32);
        const uint4* vr = (const uint4*)(qkv + src + 512 + h * 32);
        uint4* dq = (uint4*)(sq + tid * 80);
        uint4* dk = (uint4*)(sk + tid * 80);
        uint4 v0 = vr[0], v1 = vr[1], v2 = vr[2], v3 = vr[3];
        dq[0] = qr[0]; dq[1] = qr[1]; dq[2] = qr[2]; dq[3] = qr[3];
        dk[0] = kr[0]; dk[1] = kr[1]; dk[2] = kr[2]; dk[3] = kr[3];
        uint32_t vu[8] = {v0.x, v0.y, v0.z, v0.w, v1.x, v1.y, v1.z, v1.w};
        uint32_t vu2[8] = {v2.x, v2.y, v2.z, v2.w, v3.x, v3.y, v3.z, v3.w};
        #pragma unroll
        for (int e = 0; e < 8; e++) {
            ((__nv_bfloat16*)(svt + (2 * e + 0) * 528))[tid] = ((__nv_bfloat162*)&vu[e])->x;
            ((__nv_bfloat16*)(svt + (2 * e + 1) * 528))[tid] = ((__nv_bfloat162*)&vu[e])->y;
        }
        #pragma unroll
        for (int e = 0; e < 8; e++) {
            ((__nv_bfloat16*)(svt + (16 + 2 * e + 0) * 528))[tid] = ((__nv_bfloat162*)&vu2[e])->x;
            ((__nv_bfloat16*)(svt + (16 + 2 * e + 1) * 528))[tid] = ((__nv_bfloat162*)&vu2[e])->y;
        }
    }
    __syncthreads();

    const int m0w = w * 32;
    uint32_t qa[2][2][4];
    #pragma unroll
    for (int i = 0; i < 2; i++)
        #pragma unroll
        for (int kk = 0; kk < 2; kk++) {
            int r = m0w + i * 16 + (lane & 15);
            uint32_t addr = smem_u32(sq + r * 80 + kk * 32 + (lane >> 4) * 16);
            asm volatile("ldmatrix.sync.aligned.m8n8.x4.shared.b16 {%0,%1,%2,%3}, [%4];"
                         : "=r"(qa[i][kk][0]), "=r"(qa[i][kk][1]),
                           "=r"(qa[i][kk][2]), "=r"(qa[i][kk][3])
                         : "r"(addr));
        }

    float oacc[2][4][4];
    #pragma unroll
    for (int i = 0; i < 2; i++)
        #pragma unroll
        for (int d = 0; d < 4; d++)
            #pragma unroll
            for (int q = 0; q < 4; q++) oacc[i][d][q] = 0.f;
    float mrow[2][2] = {{-1e30f, -1e30f}, {-1e30f, -1e30f}};
    float lrow[2][2] = {{0.f, 0.f}, {0.f, 0.f}};

    for (int jc = 0; jc < 8; jc++) {
        uint32_t kb[2][4][2];
        #pragma unroll
        for (int jp = 0; jp < 2; jp++)
            #pragma unroll
            for (int kk = 0; kk < 2; kk++) {
                int r = jc * 32 + jp * 16 + (lane & 15);
                uint32_t addr = smem_u32(sk + r * 80 + kk * 32 + (lane >> 4) * 16);
                uint32_t r0, r1, r2, r3;
                asm volatile("ldmatrix.sync.aligned.m8n8.x4.shared.b16 {%0,%1,%2,%3}, [%4];"
                             : "=r"(r0), "=r"(r1), "=r"(r2), "=r"(r3) : "r"(addr));
                kb[kk][2*jp][0] = r0;   kb[kk][2*jp][1] = r2;
                kb[kk][2*jp+1][0] = r1; kb[kk][2*jp+1][1] = r3;
            }

        float sacc[2][4][4];
        #pragma unroll
        for (int i = 0; i < 2; i++)
            #pragma unroll
            for (int nt = 0; nt < 4; nt++)
                #pragma unroll
                for (int q = 0; q < 4; q++) sacc[i][nt][q] = 0.f;
        #pragma unroll
        for (int kk = 0; kk < 2; kk++)
            #pragma unroll
            for (int i = 0; i < 2; i++)
                #pragma unroll
                for (int nt = 0; nt < 4; nt++) {
                    asm volatile("mma.sync.aligned.m16n8k16.row.col.f32.bf16.bf16.f32 "
                                 "{%0,%1,%2,%3}, {%4,%5,%6,%7}, {%8,%9}, {%0,%1,%2,%3};"
                                 : "+f"(sacc[i][nt][0]), "+f"(sacc[i][nt][1]),
                                   "+f"(sacc[i][nt][2]), "+f"(sacc[i][nt][3])
                                 : "r"(qa[i][kk][0]), "r"(qa[i][kk][1]),
                                   "r"(qa[i][kk][2]), "r"(qa[i][kk][3]),
                                   "r"(kb[kk][nt][0]), "r"(kb[kk][nt][1]));
                }

        #pragma unroll
        for (int i = 0; i < 2; i++)
            #pragma unroll
            for (int nt = 0; nt < 4; nt++)
                #pragma unroll
                for (int q = 0; q < 4; q++) sacc[i][nt][q] *= SC;

        #pragma unroll
        for (int i = 0; i < 2; i++) {
            #pragma unroll
            for (int half = 0; half < 2; half++) {
                float mx = -1e30f;
                #pragma unroll
                for (int nt = 0; nt < 4; nt++) {
                    mx = fmaxf(mx, sacc[i][nt][half*2+0]);
                    mx = fmaxf(mx, sacc[i][nt][half*2+1]);
                }
                mx = fmaxf(mx, __shfl_xor_sync(0xffffffffu, mx, 1));
                mx = fmaxf(mx, __shfl_xor_sync(0xffffffffu, mx, 2));
                float newm = fmaxf(mrow[i][half], mx);
                float alpha = fexp2_fast(mrow[i][half] - newm);
                mrow[i][half] = newm;
                float rs = 0.f;
                #pragma unroll
                for (int nt = 0; nt < 4; nt++) {
                    float p0 = fexp2_fast(sacc[i][nt][half*2+0] - newm);
                    float p1 = fexp2_fast(sacc[i][nt][half*2+1] - newm);
                    sacc[i][nt][half*2+0] = p0;
                    sacc[i][nt][half*2+1] = p1;
                    rs += p0 + p1;
                }
                rs += __shfl_xor_sync(0xffffffffu, rs, 1);
                rs += __shfl_xor_sync(0xffffffffu, rs, 2);
                lrow[i][half] = lrow[i][half] * alpha + rs;
                #pragma unroll
                for (int dt = 0; dt < 4; dt++) {
                    oacc[i][dt][half*2+0] *= alpha;
                    oacc[i][dt][half*2+1] *= alpha;
                }
            }
        }

        uint32_t pa[2][2][4];
        #pragma unroll
        for (int i = 0; i < 2; i++)
            #pragma unroll
            for (int kk = 0; kk < 2; kk++) {
                int ntl = kk * 2, nth = kk * 2 + 1;
                __nv_bfloat162 b0 = __float22bfloat162_rn(make_float2(sacc[i][ntl][0], sacc[i][ntl][1]));
                __nv_bfloat162 b1 = __float22bfloat162_rn(make_float2(sacc[i][ntl][2], sacc[i][ntl][3]));
                __nv_bfloat162 b2 = __float22bfloat162_rn(make_float2(sacc[i][nth][0], sacc[i][nth][1]));
                __nv_bfloat162 b3 = __float22bfloat162_rn(make_float2(sacc[i][nth][2], sacc[i][nth][3]));
                pa[i][kk][0] = *(uint32_t*)&b0;
                pa[i][kk][1] = *(uint32_t*)&b1;
                pa[i][kk][2] = *(uint32_t*)&b2;
                pa[i][kk][3] = *(uint32_t*)&b3;
            }

        uint32_t vb[2][4][2];
        #pragma unroll
        for (int jp = 0; jp < 2; jp++)
            #pragma unroll
            for (int kk = 0; kk < 2; kk++) {
                int r = jp * 16 + (lane & 15);
                uint32_t addr = smem_u32(svt + r * 528 + jc * 64 + kk * 32 + (lane >> 4) * 16);
                uint32_t r0, r1, r2, r3;
                asm volatile("ldmatrix.sync.aligned.m8n8.x4.shared.b16 {%0,%1,%2,%3}, [%4];"
                             : "=r"(r0), "=r"(r1), "=r"(r2), "=r"(r3) : "r"(addr));
                vb[kk][2*jp][0] = r0;   vb[kk][2*jp][1] = r2;
                vb[kk][2*jp+1][0] = r1; vb[kk][2*jp+1][1] = r3;
            }

        #pragma unroll
        for (int kk = 0; kk < 2; kk++)
            #pragma unroll
            for (int i = 0; i < 2; i++)
                #pragma unroll
                for (int dt = 0; dt < 4; dt++) {
                    asm volatile("mma.sync.aligned.m16n8k16.row.col.f32.bf16.bf16.f32 "
                                 "{%0,%1,%2,%3}, {%4,%5,%6,%7}, {%8,%9}, {%0,%1,%2,%3};"
                                 : "+f"(oacc[i][dt][0]), "+f"(oacc[i][dt][1]),
                                   "+f"(oacc[i][dt][2]), "+f"(oacc[i][dt][3])
                                 : "r"(pa[i][kk][0]), "r"(pa[i][kk][1]),
                                   "r"(pa[i][kk][2]), "r"(pa[i][kk][3]),
                                   "r"(vb[kk][dt][0]), "r"(vb[kk][dt][1]));
                }
    }

    #pragma unroll
    for (int i = 0; i < 2; i++)
        #pragma unroll
        for (int half = 0; half < 2; half++) {
            float inv = 1.f / lrow[i][half];
            int row = m0w + i * 16 + half * 8 + (lane >> 2);
            #pragma unroll
            for (int dt = 0; dt < 4; dt++) {
                int col = h * 32 + dt * 8 + 2 * (lane & 3);
                __nv_bfloat162 hv;
                hv.x = __float2bfloat16(oacc[i][dt][half*2+0] * inv);
                hv.y = __float2bfloat16(oacc[i][dt][half*2+1] * inv);
                *(__nv_bfloat162*)(o + (base + row) * 256 + col) = hv;
            }
        }
}

// ---------------- fold gt into per-cloud biases ----------------
__global__ void cloudbias_kernel(const float* __restrict__ gtsum,
                                 const float* __restrict__ gg_w1, const float* __restrict__ gg_b1,
                                 const float* __restrict__ f_w1, const float* __restrict__ f_b1,
                                 float* __restrict__ ggb, float* __restrict__ fb, int Lc) {
    int c = blockIdx.x, j = threadIdx.x;
    float s1 = gg_b1[j], s2 = f_b1[j];
    float invL = 1.f / (float)Lc;
    for (int h = 0; h < 256; h++) {
        float gv = gtsum[c * 256 + h] * invL;
        s1 += gv * gg_w1[(size_t)(256 + h) * 256 + j];
        s2 += gv * f_w1[(size_t)(256 + h) * 256 + j];
    }
    ggb[c * 256 + j] = s1;
    fb[c * 256 + j] = s2;
}

// ---------------- launch ----------------
extern "C" void kernel_launch(void* const* d_in, const int* in_sizes, int n_in,
                              void* d_out, int out_size) {
    const float* feats = (const float*)d_in[0];
    const float* coord = (const float*)d_in[1];
    const float* pe_w1 = (const float*)d_in[3];
    const float* pe_b1 = (const float*)d_in[4];
    const float* pe_w2 = (const float*)d_in[5];
    const float* pe_b2 = (const float*)d_in[6];
    const float* pre_g = (const float*)d_in[7];
    const float* pre_b = (const float*)d_in[8];
    const float* n1_g  = (const float*)d_in[9];
    const float* n1_b  = (const float*)d_in[10];
    const float* wqkv  = (const float*)d_in[11];
    const float* bqkv  = (const float*)d_in[12];
    const float* wo    = (const float*)d_in[13];
    const float* bo    = (const float*)d_in[14];
    const float* n2_g  = (const float*)d_in[15];
    const float* n2_b  = (const float*)d_in[16];
    const float* m_w1  = (const float*)d_in[17];
    const float* m_b1  = (const float*)d_in[18];
    const float* m_w2  = (const float*)d_in[19];
    const float* m_b2  = (const float*)d_in[20];
    const float* gg_w1 = (const float*)d_in[21];
    const float* gg_b1 = (const float*)d_in[22];
    const float* gg_w2 = (const float*)d_in[23];
    const float* gg_b2 = (const float*)d_in[24];
    const float* f_w1  = (const float*)d_in[25];
    const float* f_b1  = (const float*)d_in[26];
    const float* f_w2  = (const float*)d_in[27];
    const float* f_b2  = (const float*)d_in[28];
    float* out = (float*)d_out;

    int N = in_sizes[0] / 256;
    int B = in_sizes[2];
    int Lc = N / B;
    int patches = N / 256;

    float *p_x, *p_xs, *p_key, *p_gt, *p_ggb, *p_fb, *p_stats;
    __nv_bfloat16 *p_ba, *p_bb, *p_fe, *p_wt;
    int* p_idx;
    cudaGetSymbolAddress((void**)&p_x, g_x);
    cudaGetSymbolAddress((void**)&p_xs, g_xs);
    cudaGetSymbolAddress((void**)&p_ba, g_ba);
    cudaGetSymbolAddress((void**)&p_bb, g_bb);
    cudaGetSymbolAddress((void**)&p_fe, g_fe);
    cudaGetSymbolAddress((void**)&p_wt, g_wt);
    cudaGetSymbolAddress((void**)&p_key, g_key);
    cudaGetSymbolAddress((void**)&p_idx, g_idx);
    cudaGetSymbolAddress((void**)&p_gt, g_gt);
    cudaGetSymbolAddress((void**)&p_ggb, g_ggb);
    cudaGetSymbolAddress((void**)&p_fb, g_fb);
    cudaGetSymbolAddress((void**)&p_stats, g_stats);

    __nv_bfloat16* wqkv_t = p_wt + 0;
    __nv_bfloat16* wo_t   = p_wt + 196608;
    __nv_bfloat16* mw1_t  = p_wt + 262144;
    __nv_bfloat16* mw2_t  = p_wt + 393216;
    __nv_bfloat16* ggw1_t = p_wt + 524288;
    __nv_bfloat16* ggw2_t = p_wt + 589824;
    __nv_bfloat16* fw1_t  = p_wt + 655360;
    __nv_bfloat16* fw2_t  = p_wt + 720896;
    __nv_bfloat16* bb_lo = p_bb;
    __nv_bfloat16* bb_hi = p_bb + (size_t)N * 256;

    static cudaStream_t s2 = nullptr;
    static cudaEvent_t ev1 = nullptr, ev2 = nullptr;
    if (!s2) {
        cudaStreamCreateWithFlags(&s2, cudaStreamNonBlocking);
        cudaEventCreateWithFlags(&ev1, cudaEventDisableTiming);
        cudaEventCreateWithFlags(&ev2, cudaEventDisableTiming);
    }

    cudaFuncSetAttribute(fattn, cudaFuncAttributeMaxDynamicSharedMemorySize, FA_SMEM);
    cudaFuncSetAttribute(gemm_bf16<8>, cudaFuncAttributeMaxDynamicSharedMemorySize, NSTAGE * STG_BYTES);
    cudaFuncSetAttribute(gemm_bf16<16>, cudaFuncAttributeMaxDynamicSharedMemorySize, NSTAGE * STG_BYTES);

    PrepArgs pa;
    pa.coord = coord; pa.stats = p_stats; pa.Lc = Lc; pa.B = B;
    const float* ws[8] = {wqkv, wo, m_w1, m_w2, gg_w1, gg_w2, f_w1, f_w2};
    __nv_bfloat16* wd[8] = {wqkv_t, wo_t, mw1_t, mw2_t, ggw1_t, ggw2_t, fw1_t, fw2_t};
    int wK[8] = {256, 256, 256, 512, 256, 256, 256, 256};
    int wN[8] = {768, 256, 512, 256, 256, 256, 256, 256};
    int tiles = 0;
    for (int i = 0; i < 8; i++) {
        pa.wsrc[i] = ws[i]; pa.wdst[i] = wd[i];
        pa.wK[i] = wK[i]; pa.wN[i] = wN[i];
        pa.wt0[i] = tiles;
        tiles += (wK[i] / 32) * (wN[i] / 32);
    }
    pa.totalWTiles = tiles;
    pa.gt = p_gt;

    // 1: prep
    prep_kernel<<<B + tiles + 1, 1024>>>(pa);
    // 2: PE + pre-LN + LN1 + key (original order)
    pe_ln_key_kernel<<<N, 256>>>(feats, coord, pe_w1, pe_b1, pe_w2, pe_b2,
                                 pre_g, pre_b, n1_g, n1_b, p_stats,
                                 p_x, p_bb, p_fe, p_key, p_idx, Lc);
    // fork: sort chain on s2, qkv GEMM on main — independent
    cudaEventRecord(ev1, 0);
    cudaStreamWaitEvent(s2, ev1, 0);
    // 3 (s2): local sort
    sort_local<<<N / CHUNK, 1024, CHUNK * 8, s2>>>(p_key, p_idx, Lc);
    // 4 (main): qkv GEMM (unpermuted) -> ba  [profiled launch]
    gemm_bf16<8><<<dim3(768/GBN, N/GBM), 256, NSTAGE*STG_BYTES>>>(
        p_bb, wqkv_t, bqkv, nullptr, nullptr, p_ba, N, 768, 0, 0, 1,
        nullptr, nullptr, 0, nullptr, nullptr, nullptr, nullptr);
    // (s2): finish the sort
    for (int k = CHUNK * 2; k <= Lc; k <<= 1) {
        for (int j = k >> 1; j >= CHUNK; j >>= 1)
            sort_global<<<dim3(Lc / 512, B), 256, 0, s2>>>(p_key, p_idx, k, j, Lc);
        merge_local<<<N / CHUNK, 1024, CHUNK * 8, s2>>>(p_key, p_idx, k, Lc);
    }
    cudaEventRecord(ev2, s2);
    cudaStreamWaitEvent(0, ev2, 0);
    // flash attention (gather via idx) -> bb
    fattn<<<dim3(patches, 8), 256, FA_SMEM>>>(p_ba, p_idx, p_bb);
    // wo GEMM + gathered residual -> xs fp32
    gemm_bf16<8><<<dim3(256/GBN, N/GBM), 256, NSTAGE*STG_BYTES>>>(
        p_bb, wo_t, bo, p_x, nullptr, p_xs, N, 256, 0, 4, 0,
        p_idx, nullptr, 0, nullptr, nullptr, nullptr, nullptr);
    // LN2 -> ba bf16
    ln_bf<<<N, 256>>>(p_xs, n2_g, n2_b, p_ba);
    // MLP1 + gelu -> bb
    gemm_bf16<8><<<dim3(512/GBN, N/GBM), 256, NSTAGE*STG_BYTES>>>(
        p_ba, mw1_t, m_b1, nullptr, nullptr, p_bb, N, 512, 0, 2, 1,
        nullptr, nullptr, 0, nullptr, nullptr, nullptr, nullptr);
    // MLP2 + resid; scatter xo -> ba; gt atomics
    gemm_bf16<16><<<dim3(256/GBN, N/GBM), 256, NSTAGE*STG_BYTES>>>(
        p_bb, mw2_t, m_b2, p_xs, nullptr, p_ba, N, 256, 0, 6, 1,
        p_idx, p_gt, Lc, nullptr, nullptr, nullptr, nullptr);
    // per-cloud biases
    cloudbias_kernel<<<B, 256>>>(p_gt, gg_w1, gg_b1, f_w1, f_b1, p_ggb, p_fb, Lc);
    // batched hidden GEMMs (z=0 gate, z=1 fuse)
    gemm_bf16<8><<<dim3(256/GBN, N/GBM, 2), 256, NSTAGE*STG_BYTES>>>(
        p_fe, ggw1_t, p_ggb, nullptr, nullptr, bb_lo, N, 256, Lc, 1, 1,
        nullptr, nullptr, 0, p_ba, fw1_t, p_fb, bb_hi);
    // gate sigmoid -> p_x fp32
    gemm_bf16<8><<<dim3(256/GBN, N/GBM), 256, NSTAGE*STG_BYTES>>>(
        bb_lo, ggw2_t, gg_b2, nullptr, nullptr, p_x, N, 256, 0, 3, 0,
        nullptr, nullptr, 0, nullptr, nullptr, nullptr, nullptr);
    // out = feats + gate * fused
    gemm_bf16<8><<<dim3(256/GBN, N/GBM), 256, NSTAGE*STG_BYTES>>>(
        bb_hi, fw2_t, f_b2, feats, p_x, out, N, 256, 0, 5, 0,
        nullptr, nullptr, 0, nullptr, nullptr, nullptr, nullptr);
}

// round 14
// speedup vs baseline: 1.1272x; 1.0412x over previous
#include <cuda_runtime.h>
#include <cuda_bf16.h>
#include <math.h>
#include <stdint.h>

// ---------------- static scratch ----------------
#define MAXN 131072
#define DD 256
__device__ float g_x  [(size_t)MAXN * DD];
__device__ float g_xs [(size_t)MAXN * DD];
__device__ __nv_bfloat16 g_ba[(size_t)MAXN * 768];
__device__ __nv_bfloat16 g_bb[(size_t)MAXN * 512];
__device__ __nv_bfloat16 g_fe[(size_t)MAXN * 256];
__device__ __nv_bfloat16 g_wt[786432];
__device__ float g_key[MAXN];
__device__ int   g_idx[MAXN];
__device__ float g_gt [8 * DD];
__device__ float g_ggb[8 * DD];
__device__ float g_fb [8 * DD];
__device__ float g_stats[8 * 12];

// ---------------- fast math ----------------
__device__ __forceinline__ float fexp2_fast(float z) {
    z = fmaxf(z, -80.f);
    float n = rintf(z);
    float f = z - n;
    float p = 0.009618129f;
    p = p * f + 0.055504109f;
    p = p * f + 0.240226507f;
    p = p * f + 0.693147181f;
    p = p * f + 1.0f;
    return p * __int_as_float(((int)n + 127) << 23);
}
__device__ __forceinline__ float fexpf_fast(float x) {
    return fexp2_fast(x * 1.4426950408889634f);
}
__device__ __forceinline__ float frcp_fast(float d) {
    float y = __int_as_float(0x7ef311c3 - __float_as_int(d));
    y = y * (2.f - d * y);
    y = y * (2.f - d * y);
    y = y * (2.f - d * y);
    return y;
}
__device__ __forceinline__ uint32_t smem_u32(const void* p) {
    return (uint32_t)__cvta_generic_to_shared(p);
}
// dual block sum (one barrier); caller must __syncthreads() before reusing red16
__device__ __forceinline__ float2 blocksum256_2(float a, float b, float* red16) {
    #pragma unroll
    for (int off = 16; off; off >>= 1) {
        a += __shfl_xor_sync(0xffffffffu, a, off);
        b += __shfl_xor_sync(0xffffffffu, b, off);
    }
    int w = threadIdx.x >> 5;
    if ((threadIdx.x & 31) == 0) { red16[w] = a; red16[8 + w] = b; }
    __syncthreads();
    float s1 = 0.f, s2 = 0.f;
    #pragma unroll
    for (int i = 0; i < 8; i++) { s1 += red16[i]; s2 += red16[8 + i]; }
    return make_float2(s1, s2);
}

// ---------------- prep ----------------
struct PrepArgs {
    const float* coord; float* stats; int Lc; int B;
    const float* wsrc[8]; __nv_bfloat16* wdst[8];
    int wK[8], wN[8], wt0[8];
    int totalWTiles;
    float* gt;
};
__global__ void __launch_bounds__(1024) prep_kernel(PrepArgs a) {
    __shared__ float red[1024];
    __shared__ float tt[32][33];
    int b = blockIdx.x, tid = threadIdx.x;
    if (b < a.B) {
        int c = b, Lc = a.Lc;
        float sum[3] = {0,0,0}, mn[3] = {1e30f,1e30f,1e30f}, mx[3] = {-1e30f,-1e30f,-1e30f};
        for (int i = tid; i < Lc; i += 1024) {
            const float* cp = a.coord + (size_t)(c * Lc + i) * 3;
            #pragma unroll
            for (int d = 0; d < 3; d++) {
                float v = cp[d];
                sum[d] += v; mn[d] = fminf(mn[d], v); mx[d] = fmaxf(mx[d], v);
            }
        }
        for (int d = 0; d < 3; d++) {
            red[tid] = sum[d]; __syncthreads();
            for (int s = 512; s > 0; s >>= 1) { if (tid < s) red[tid] += red[tid + s]; __syncthreads(); }
            float tot = red[0]; __syncthreads();
            red[tid] = mn[d]; __syncthreads();
            for (int s = 512; s > 0; s >>= 1) { if (tid < s) red[tid] = fminf(red[tid], red[tid + s]); __syncthreads(); }
            float tmn = red[0]; __syncthreads();
            red[tid] = mx[d]; __syncthreads();
            for (int s = 512; s > 0; s >>= 1) { if (tid < s) red[tid] = fmaxf(red[tid], red[tid + s]); __syncthreads(); }
            float tmx = red[0]; __syncthreads();
            if (tid == 0) {
                float mean = tot / (float)Lc;
                a.stats[c*12 + d]     = mean;
                a.stats[c*12 + 3 + d] = fmaxf(fmaxf(tmx - mean, mean - tmn), 1e-6f);
                a.stats[c*12 + 6 + d] = tmn;
                a.stats[c*12 + 9 + d] = 1.f / fmaxf(tmx - tmn, 1e-6f);
            }
            __syncthreads();
        }
    } else if (b < a.B + a.totalWTiles) {
        int t = b - a.B;
        int w = 0;
        #pragma unroll
        for (int q = 1; q < 8; q++) if (t >= a.wt0[q]) w = q;
        int lt = t - a.wt0[w];
        int tilesX = a.wN[w] >> 5;
        int bx = (lt % tilesX) << 5, by = (lt / tilesX) << 5;
        const float* src = a.wsrc[w];
        __nv_bfloat16* dst = a.wdst[w];
        int K = a.wK[w], Ncols = a.wN[w];
        int tx = tid & 31, ty = tid >> 5;
        tt[ty][tx] = src[(size_t)(by + ty) * Ncols + bx + tx];
        __syncthreads();
        dst[(size_t)(bx + ty) * K + by + tx] = __float2bfloat16(tt[tx][ty]);
    } else {
        a.gt[tid] = 0.f;
        a.gt[tid + 1024] = 0.f;
    }
}

// ---------------- PE + pre-LN + LN1 + key + feats->bf16 (single-pass LN) ----------------
__global__ void __launch_bounds__(256) pe_ln_key_kernel(
    const float* __restrict__ feats, const float* __restrict__ coord,
    const float* __restrict__ w1, const float* __restrict__ b1,
    const float* __restrict__ w2, const float* __restrict__ b2,
    const float* __restrict__ g, const float* __restrict__ beta,
    const float* __restrict__ n1g, const float* __restrict__ n1b,
    const float* __restrict__ stats,
    float* __restrict__ xout, __nv_bfloat16* __restrict__ hbf,
    __nv_bfloat16* __restrict__ febf,
    float* __restrict__ key, int* __restrict__ idx, int Lc)
{
    int i = blockIdx.x, tid = threadIdx.x;
    int c = i / Lc;
    __shared__ float hid[64];
    __shared__ float red16[16];
    const float* st = stats + c * 12;
    float c0 = coord[(size_t)i*3+0], c1 = coord[(size_t)i*3+1], c2 = coord[(size_t)i*3+2];
    if (tid < 64) {
        float n0 = (c0 - st[0]) / st[3];
        float n1 = (c1 - st[1]) / st[4];
        float n2 = (c2 - st[2]) / st[5];
        float hv = b1[tid] + n0 * w1[tid] + n1 * w1[64 + tid] + n2 * w1[128 + tid];
        hid[tid] = fmaxf(hv, 0.f);
    }
    if (tid == 0) {
        float k0 = (c0 - st[6]) * st[9];
        float k1 = (c1 - st[7]) * st[10];
        float k2 = (c2 - st[8]) * st[11];
        key[i] = k0 + 2.17f * k1 + 3.31f * k2;
        idx[i] = i;
    }
    __syncthreads();
    float fv = feats[(size_t)i * 256 + tid];
    febf[(size_t)i * 256 + tid] = __float2bfloat16(fv);
    float pe = b2[tid];
    #pragma unroll 8
    for (int h = 0; h < 64; h++) pe += hid[h] * w2[h * 256 + tid];
    float v = fv + pe;
    float2 ss = blocksum256_2(v, v * v, red16);
    float mean = ss.x * (1.f / 256.f);
    float var = ss.y * (1.f / 256.f) - mean * mean;
    float xv = (v - mean) * rsqrtf(var + 1e-5f) * g[tid] + beta[tid];
    xout[(size_t)i * 256 + tid] = xv;
    __syncthreads();
    float2 ss2 = blocksum256_2(xv, xv * xv, red16);
    float m2 = ss2.x * (1.f / 256.f);
    float v2 = ss2.y * (1.f / 256.f) - m2 * m2;
    hbf[(size_t)i * 256 + tid] = __float2bfloat16((xv - m2) * rsqrtf(v2 + 1e-5f) * n1g[tid] + n1b[tid]);
}

// ---------------- hierarchical bitonic sort (CHUNK=4096) ----------------
#define CHUNK 4096
__global__ void __launch_bounds__(1024) sort_local(float* __restrict__ key, int* __restrict__ idx, int Lc) {
    extern __shared__ char smraw[];
    float* sk = (float*)smraw;
    int*   si = (int*)(smraw + CHUNK * 4);
    size_t gbase = (size_t)blockIdx.x * CHUNK;
    int lbase = (int)(gbase % (size_t)Lc);
    for (int t = threadIdx.x; t < CHUNK; t += 1024) { sk[t] = key[gbase + t]; si[t] = idx[gbase + t]; }
    __syncthreads();
    for (int k = 2; k <= CHUNK; k <<= 1) {
        for (int j = k >> 1; j > 0; j >>= 1) {
            #pragma unroll
            for (int it = 0; it < CHUNK / 2048; it++) {
                int t = threadIdx.x + it * 1024;
                int i = 2 * t - (t & (j - 1));
                int p = i + j;
                bool up = (((lbase + i) & k) == 0);
                float a = sk[i], b = sk[p];
                int ia = si[i], ib = si[p];
                bool sw = up ? (a > b || (a == b && ia > ib)) : (a < b || (a == b && ia < ib));
                if (sw) { sk[i] = b; sk[p] = a; si[i] = ib; si[p] = ia; }
            }
            __syncthreads();
        }
    }
    for (int t = threadIdx.x; t < CHUNK; t += 1024) { key[gbase + t] = sk[t]; idx[gbase + t] = si[t]; }
}

__global__ void __launch_bounds__(1024) merge_local(float* __restrict__ key, int* __restrict__ idx, int k, int Lc) {
    extern __shared__ char smraw[];
    float* sk = (float*)smraw;
    int*   si = (int*)(smraw + CHUNK * 4);
    size_t gbase = (size_t)blockIdx.x * CHUNK;
    int lbase = (int)(gbase % (size_t)Lc);
    for (int t = threadIdx.x; t < CHUNK; t += 1024) { sk[t] = key[gbase + t]; si[t] = idx[gbase + t]; }
    __syncthreads();
    for (int j = CHUNK / 2; j > 0; j >>= 1) {
        #pragma unroll
        for (int it = 0; it < CHUNK / 2048; it++) {
            int t = threadIdx.x + it * 1024;
            int i = 2 * t - (t & (j - 1));
            int p = i + j;
            bool up = (((lbase + i) & k) == 0);
            float a = sk[i], b = sk[p];
            int ia = si[i], ib = si[p];
            bool sw = up ? (a > b || (a == b && ia > ib)) : (a < b || (a == b && ia < ib));
            if (sw) { sk[i] = b; sk[p] = a; si[i] = ib; si[p] = ia; }
        }
        __syncthreads();
    }
    for (int t = threadIdx.x; t < CHUNK; t += 1024) { key[gbase + t] = sk[t]; idx[gbase + t] = si[t]; }
}

__global__ void __launch_bounds__(256) sort_global(float* __restrict__ key, int* __restrict__ idx, int k, int j, int Lc) {
    int c = blockIdx.y;
    size_t base = (size_t)c * Lc;
    int t = blockIdx.x * 256 + threadIdx.x;
    int i = 2 * t - (t & (j - 1));
    int p = i + j;
    bool up = ((i & k) == 0);
    float a = key[base + i], b = key[base + p];
    int ia = idx[base + i], ib = idx[base + p];
    bool sw = up ? (a > b || (a == b && ia > ib)) : (a < b || (a == b && ia < ib));
    if (sw) {
        key[base + i] = b; key[base + p] = a;
        idx[base + i] = ib; idx[base + p] = ia;
    }
}

// ---------------- LN -> bf16 (single-pass) ----------------
__global__ void __launch_bounds__(256) ln_bf(const float* __restrict__ x, const float* __restrict__ g,
                                             const float* __restrict__ b, __nv_bfloat16* __restrict__ y) {
    int row = blockIdx.x, tid = threadIdx.x;
    __shared__ float red16[16];
    float v = x[(size_t)row * 256 + tid];
    float2 ss = blocksum256_2(v, v * v, red16);
    float mean = ss.x * (1.f / 256.f);
    float var = ss.y * (1.f / 256.f) - mean * mean;
    y[(size_t)row * 256 + tid] = __float2bfloat16((v - mean) * rsqrtf(var + 1e-5f) * g[tid] + b[tid]);
}

// ---------------- tensor-core GEMM: 128x64 tile, warp tile 32x32, 3 CTAs/SM ----------------
// epi: 0 none, 1 relu, 2 gelu, 3 sigmoid, 4 +resid[ridx], 5 resid + gate*val,
//      6 +resid[m]; bf16 scatter to Cout[ridx[m]]; atomic gt column sums
#define GBM 128
#define GBN 64
#define GKT 32
#define STG_BYTES 15360
#define NSTAGE 4

template<int NK>
__global__ void __launch_bounds__(256, 3) gemm_bf16(
    const __nv_bfloat16* __restrict__ A_, const __nv_bfloat16* __restrict__ Bt_,
    const float* __restrict__ bias_,
    const float* __restrict__ resid, const float* __restrict__ gate,
    void* __restrict__ Cout_,
    int M, int Ncols, int cloudLen, int epi, int outBf16,
    const int* __restrict__ ridx, float* __restrict__ gtp, int gtLc,
    const __nv_bfloat16* A2, const __nv_bfloat16* Bt2, const float* bias2, void* Cout2)
{
    constexpr int K = NK * GKT;
    extern __shared__ char smraw[];
    const __nv_bfloat16* A = A_;
    const __nv_bfloat16* Bt = Bt_;
    const float* bias = bias_;
    void* Cout = Cout_;
    if (blockIdx.z == 1) { A = A2; Bt = Bt2; bias = bias2; Cout = Cout2; }
    const int tid = threadIdx.x;
    const int lane = tid & 31;
    const int warp = tid >> 5;
    const int wm = warp >> 1, wn = warp & 1;
    const int m0 = blockIdx.y * GBM, n0 = blockIdx.x * GBN;

    float acc[2][4][4];
    #pragma unroll
    for (int i = 0; i < 2; i++)
        #pragma unroll
        for (int j = 0; j < 4; j++)
            #pragma unroll
            for (int q = 0; q < 4; q++) acc[i][j][q] = 0.f;

    const int arow0 = tid >> 2, ac0 = tid & 3;
    const int arow1 = (tid + 256) >> 2;
    const __nv_bfloat16* gA0 = A + (size_t)(m0 + arow0) * K + ac0 * 8;
    const __nv_bfloat16* gA1 = A + (size_t)(m0 + arow1) * K + ac0 * 8;
    const __nv_bfloat16* gB0 = Bt + (size_t)(n0 + arow0) * K + ac0 * 8;
    const uint32_t smemBase = smem_u32(smraw);
    const uint32_t dA0 = smemBase + arow0 * 80 + ac0 * 16;
    const uint32_t dA1 = smemBase + arow1 * 80 + ac0 * 16;
    const uint32_t dB0 = smemBase + 10240 + arow0 * 80 + ac0 * 16;

    uint32_t aoff[2], boff[2];
    #pragma unroll
    for (int i = 0; i < 2; i++)
        aoff[i] = smemBase + (wm * 32 + i * 16 + (lane & 15)) * 80 + (lane >> 4) * 16;
    #pragma unroll
    for (int jp = 0; jp < 2; jp++)
        boff[jp] = smemBase + 10240 + (wn * 32 + jp * 16 + (lane & 15)) * 80 + (lane >> 4) * 16;

    auto issue = [&](int s, int kt) {
        uint32_t sb = s * STG_BYTES;
        int go = kt * GKT;
        asm volatile("cp.async.cg.shared.global [%0], [%1], 16;\n" :: "r"(dA0 + sb), "l"(gA0 + go));
        asm volatile("cp.async.cg.shared.global [%0], [%1], 16;\n" :: "r"(dA1 + sb), "l"(gA1 + go));
        asm volatile("cp.async.cg.shared.global [%0], [%1], 16;\n" :: "r"(dB0 + sb), "l"(gB0 + go));
        asm volatile("cp.async.commit_group;\n");
    };

    issue(0, 0);
    issue(1, 1);
    #pragma unroll
    for (int kt = 0; kt < NK; kt++) {
        const int s = kt & (NSTAGE - 1);
        if (kt + 2 < NK) {
            issue((kt + 2) & (NSTAGE - 1), kt + 2);
            asm volatile("cp.async.wait_group 2;\n");
        } else if (kt + 1 < NK) {
            asm volatile("cp.async.wait_group 1;\n");
        } else {
            asm volatile("cp.async.wait_group 0;\n");
        }
        __syncthreads();

        const uint32_t sb = s * STG_BYTES;
        #pragma unroll
        for (int kk = 0; kk < 2; kk++) {
            uint32_t af[2][4];
            #pragma unroll
            for (int i = 0; i < 2; i++) {
                asm volatile("ldmatrix.sync.aligned.m8n8.x4.shared.b16 {%0,%1,%2,%3}, [%4];"
                             : "=r"(af[i][0]), "=r"(af[i][1]), "=r"(af[i][2]), "=r"(af[i][3])
                             : "r"(aoff[i] + sb + kk * 32));
            }
            uint32_t bf[4][2];
            #pragma unroll
            for (int jp = 0; jp < 2; jp++) {
                uint32_t r0, r1, r2, r3;
                asm volatile("ldmatrix.sync.aligned.m8n8.x4.shared.b16 {%0,%1,%2,%3}, [%4];"
                             : "=r"(r0), "=r"(r1), "=r"(r2), "=r"(r3)
                             : "r"(boff[jp] + sb + kk * 32));
                bf[2*jp][0] = r0; bf[2*jp+1][0] = r1;
                bf[2*jp][1] = r2; bf[2*jp+1][1] = r3;
            }
            #pragma unroll
            for (int i = 0; i < 2; i++)
                #pragma unroll
                for (int j = 0; j < 4; j++) {
                    asm volatile("mma.sync.aligned.m16n8k16.row.col.f32.bf16.bf16.f32 "
                                 "{%0,%1,%2,%3}, {%4,%5,%6,%7}, {%8,%9}, {%0,%1,%2,%3};"
                                 : "+f"(acc[i][j][0]), "+f"(acc[i][j][1]),
                                   "+f"(acc[i][j][2]), "+f"(acc[i][j][3])
                                 : "r"(af[i][0]), "r"(af[i][1]), "r"(af[i][2]), "r"(af[i][3]),
                                   "r"(bf[j][0]), "r"(bf[j][1]));
                }
        }
    }

    const int rbase = m0 + wm * 32 + (lane >> 2);
    const int cbase = n0 + wn * 32 + 2 * (lane & 3);
    float gta[4][2];
    #pragma unroll
    for (int j = 0; j < 4; j++) { gta[j][0] = 0.f; gta[j][1] = 0.f; }

    #pragma unroll
    for (int i = 0; i < 2; i++) {
        #pragma unroll
        for (int half = 0; half < 2; half++) {
            int m = rbase + i * 16 + half * 8;
            const float* bp = (cloudLen > 0) ? (bias + (size_t)(m / cloudLen) * Ncols) : bias;
            #pragma unroll
            for (int j = 0; j < 4; j++) {
                int n = cbase + j * 8;
                float v0 = acc[i][j][half * 2 + 0] + bp[n];
                float v1 = acc[i][j][half * 2 + 1] + bp[n + 1];
                size_t o = (size_t)m * Ncols + n;
                bool stored = false;
                switch (epi) {
                    case 1: v0 = fmaxf(v0, 0.f); v1 = fmaxf(v1, 0.f); break;
                    case 2:
                        v0 = 0.5f * v0 * (1.f + erff(v0 * 0.70710678118f));
                        v1 = 0.5f * v1 * (1.f + erff(v1 * 0.70710678118f));
                        break;
                    case 3:
                        v0 = frcp_fast(1.f + fexpf_fast(-v0));
                        v1 = frcp_fast(1.f + fexpf_fast(-v1));
                        break;
                    case 4: {
                        size_t ro = (size_t)(ridx ? ridx[m] : m) * Ncols + n;
                        float2 r = *(const float2*)(resid + ro);
                        v0 += r.x; v1 += r.y;
                    } break;
                    case 5: {
                        float2 r = *(const float2*)(resid + o);
                        float2 gg = *(const float2*)(gate + o);
                        v0 = r.x + gg.x * v0; v1 = r.y + gg.y * v1;
                    } break;
                    case 6: {
                        float2 r = *(const float2*)(resid + o);
                        v0 += r.x; v1 += r.y;
                        gta[j][0] += v0; gta[j][1] += v1;
                        size_t od = (size_t)ridx[m] * Ncols + n;
                        __nv_bfloat162 h;
                        h.x = __float2bfloat16(v0); h.y = __float2bfloat16(v1);
                        *(__nv_bfloat162*)((__nv_bfloat16*)Cout + od) = h;
                        stored = true;
                    } break;
                    default: break;
                }
                if (!stored) {
                    if (outBf16) {
                        __nv_bfloat162 h;
                        h.x = __float2bfloat16(v0); h.y = __float2bfloat16(v1);
                        *(__nv_bfloat162*)((__nv_bfloat16*)Cout + o) = h;
                    } else {
                        *(float2*)((float*)Cout + o) = make_float2(v0, v1);
                    }
                }
            }
        }
    }
    if (epi == 6) {
        int c = m0 / gtLc;
        #pragma unroll
        for (int j = 0; j < 4; j++) {
            float s0 = gta[j][0], s1 = gta[j][1];
            #pragma unroll
            for (int off = 4; off <= 16; off <<= 1) {
                s0 += __shfl_xor_sync(0xffffffffu, s0, off);
                s1 += __shfl_xor_sync(0xffffffffu, s1, off);
            }
            if ((lane >> 2) == 0) {
                int n = cbase + j * 8;
                atomicAdd(gtp + c * 256 + n, s0);
                atomicAdd(gtp + c * 256 + n + 1, s1);
            }
        }
    }
}

// ---------------- dual GEMM final: out = feats + sigmoid(A1@W1+b1) * (A2@W2+b2) ----------------
// 128x64 tile, K=256, 3-stage ring; issue AFTER barrier (race-free at distance 2)
#define DSTG 30720
#define DNSTAGE 3
__global__ void __launch_bounds__(256, 2) gemm_final(
    const __nv_bfloat16* __restrict__ A1, const __nv_bfloat16* __restrict__ W1,
    const float* __restrict__ b1,
    const __nv_bfloat16* __restrict__ A2, const __nv_bfloat16* __restrict__ W2,
    const float* __restrict__ b2,
    const float* __restrict__ feats, float* __restrict__ out, int Ncols)
{
    constexpr int NK = 8;  // K = 256
    extern __shared__ char smraw[];
    const int tid = threadIdx.x;
    const int lane = tid & 31;
    const int warp = tid >> 5;
    const int wm = warp >> 1, wn = warp & 1;
    const int m0 = blockIdx.y * 128, n0 = blockIdx.x * 64;

    float acc1[2][4][4], acc2[2][4][4];
    #pragma unroll
    for (int i = 0; i < 2; i++)
        #pragma unroll
        for (int j = 0; j < 4; j++)
            #pragma unroll
            for (int q = 0; q < 4; q++) { acc1[i][j][q] = 0.f; acc2[i][j][q] = 0.f; }

    const int arow0 = tid >> 2, ac0 = tid & 3;
    const int arow1 = (tid + 256) >> 2;
    const __nv_bfloat16* gA1_0 = A1 + (size_t)(m0 + arow0) * 256 + ac0 * 8;
    const __nv_bfloat16* gA1_1 = A1 + (size_t)(m0 + arow1) * 256 + ac0 * 8;
    const __nv_bfloat16* gA2_0 = A2 + (size_t)(m0 + arow0) * 256 + ac0 * 8;
    const __nv_bfloat16* gA2_1 = A2 + (size_t)(m0 + arow1) * 256 + ac0 * 8;
    const __nv_bfloat16* gB1_0 = W1 + (size_t)(n0 + arow0) * 256 + ac0 * 8;
    const __nv_bfloat16* gB2_0 = W2 + (size_t)(n0 + arow0) * 256 + ac0 * 8;
    const uint32_t smemBase = smem_u32(smraw);
    const uint32_t dA1_0 = smemBase + arow0 * 80 + ac0 * 16;
    const uint32_t dA1_1 = smemBase + arow1 * 80 + ac0 * 16;
    const uint32_t dB1_0 = smemBase + 10240 + arow0 * 80 + ac0 * 16;
    const uint32_t dA2_0 = smemBase + 15360 + arow0 * 80 + ac0 * 16;
    const uint32_t dA2_1 = smemBase + 15360 + arow1 * 80 + ac0 * 16;
    const uint32_t dB2_0 = smemBase + 25600 + arow0 * 80 + ac0 * 16;

    uint32_t aoff[2], boff[2];
    #pragma unroll
    for (int i = 0; i < 2; i++)
        aoff[i] = smemBase + (wm * 32 + i * 16 + (lane & 15)) * 80 + (lane >> 4) * 16;
    #pragma unroll
    for (int jp = 0; jp < 2; jp++)
        boff[jp] = smemBase + 10240 + (wn * 32 + jp * 16 + (lane & 15)) * 80 + (lane >> 4) * 16;

    auto issue = [&](int s, int kt) {
        uint32_t sb = s * DSTG;
        int go = kt * 32;
        asm volatile("cp.async.cg.shared.global [%0], [%1], 16;\n" :: "r"(dA1_0 + sb), "l"(gA1_0 + go));
        asm volatile("cp.async.cg.shared.global [%0], [%1], 16;\n" :: "r"(dA1_1 + sb), "l"(gA1_1 + go));
        asm volatile("cp.async.cg.shared.global [%0], [%1], 16;\n" :: "r"(dB1_0 + sb), "l"(gB1_0 + go));
        asm volatile("cp.async.cg.shared.global [%0], [%1], 16;\n" :: "r"(dA2_0 + sb), "l"(gA2_0 + go));
        asm volatile("cp.async.cg.shared.global [%0], [%1], 16;\n" :: "r"(dA2_1 + sb), "l"(gA2_1 + go));
        asm volatile("cp.async.cg.shared.global [%0], [%1], 16;\n" :: "r"(dB2_0 + sb), "l"(gB2_0 + go));
        asm volatile("cp.async.commit_group;\n");
    };

    issue(0, 0);
    issue(1, 1);
    #pragma unroll
    for (int kt = 0; kt < NK; kt++) {
        const int s = kt % DNSTAGE;
        // wait for stage kt (allow latest group kt+1 in flight)
        if (kt + 1 < NK) {
            asm volatile("cp.async.wait_group 1;\n");
        } else {
            asm volatile("cp.async.wait_group 0;\n");
        }
        __syncthreads();
        // safe: stage (kt+2)%3 was consumed at kt-1, strictly before this barrier
        if (kt + 2 < NK) issue((kt + 2) % DNSTAGE, kt + 2);

        const uint32_t sb = s * DSTG;
        #pragma unroll
        for (int kk = 0; kk < 2; kk++) {
            uint32_t af1[2][4], af2[2][4];
            #pragma unroll
            for (int i = 0; i < 2; i++) {
                asm volatile("ldmatrix.sync.aligned.m8n8.x4.shared.b16 {%0,%1,%2,%3}, [%4];"
                             : "=r"(af1[i][0]), "=r"(af1[i][1]), "=r"(af1[i][2]), "=r"(af1[i][3])
                             : "r"(aoff[i] + sb + kk * 32));
                asm volatile("ldmatrix.sync.aligned.m8n8.x4.shared.b16 {%0,%1,%2,%3}, [%4];"
                             : "=r"(af2[i][0]), "=r"(af2[i][1]), "=r"(af2[i][2]), "=r"(af2[i][3])
                             : "r"(aoff[i] + sb + 15360 + kk * 32));
            }
            uint32_t bf1[4][2], bf2[4][2];
            #pragma unroll
            for (int jp = 0; jp < 2; jp++) {
                uint32_t r0, r1, r2, r3;
                asm volatile("ldmatrix.sync.aligned.m8n8.x4.shared.b16 {%0,%1,%2,%3}, [%4];"
                             : "=r"(r0), "=r"(r1), "=r"(r2), "=r"(r3)
                             : "r"(boff[jp] + sb + kk * 32));
                bf1[2*jp][0] = r0; bf1[2*jp+1][0] = r1;
                bf1[2*jp][1] = r2; bf1[2*jp+1][1] = r3;
                asm volatile("ldmatrix.sync.aligned.m8n8.x4.shared.b16 {%0,%1,%2,%3}, [%4];"
                             : "=r"(r0), "=r"(r1), "=r"(r2), "=r"(r3)
                             : "r"(boff[jp] + sb + 15360 + kk * 32));
                bf2[2*jp][0] = r0; bf2[2*jp+1][0] = r1;
                bf2[2*jp][1] = r2; bf2[2*jp+1][1] = r3;
            }
            #pragma unroll
            for (int i = 0; i < 2; i++)
                #pragma unroll
                for (int j = 0; j < 4; j++) {
                    asm volatile("mma.sync.aligned.m16n8k16.row.col.f32.bf16.bf16.f32 "
                                 "{%0,%1,%2,%3}, {%4,%5,%6,%7}, {%8,%9}, {%0,%1,%2,%3};"
                                 : "+f"(acc1[i][j][0]), "+f"(acc1[i][j][1]),
                                   "+f"(acc1[i][j][2]), "+f"(acc1[i][j][3])
                                 : "r"(af1[i][0]), "r"(af1[i][1]), "r"(af1[i][2]), "r"(af1[i][3]),
                                   "r"(bf1[j][0]), "r"(bf1[j][1]));
                    asm volatile("mma.sync.aligned.m16n8k16.row.col.f32.bf16.bf16.f32 "
                                 "{%0,%1,%2,%3}, {%4,%5,%6,%7}, {%8,%9}, {%0,%1,%2,%3};"
                                 : "+f"(acc2[i][j][0]), "+f"(acc2[i][j][1]),
                                   "+f"(acc2[i][j][2]), "+f"(acc2[i][j][3])
                                 : "r"(af2[i][0]), "r"(af2[i][1]), "r"(af2[i][2]), "r"(af2[i][3]),
                                   "r"(bf2[j][0]), "r"(bf2[j][1]));
                }
        }
    }

    const int rbase = m0 + wm * 32 + (lane >> 2);
    const int cbase = n0 + wn * 32 + 2 * (lane & 3);
    #pragma unroll
    for (int i = 0; i < 2; i++) {
        #pragma unroll
        for (int half = 0; half < 2; half++) {
            int m = rbase + i * 16 + half * 8;
            #pragma unroll
            for (int j = 0; j < 4; j++) {
                int n = cbase + j * 8;
                float g0 = frcp_fast(1.f + fexpf_fast(-(acc1[i][j][half*2+0] + b1[n])));
                float g1 = frcp_fast(1.f + fexpf_fast(-(acc1[i][j][half*2+1] + b1[n+1])));
                float f0 = acc2[i][j][half*2+0] + b2[n];
                float f1 = acc2[i][j][half*2+1] + b2[n+1];
                size_t o = (size_t)m * Ncols + n;
                float2 r = *(const float2*)(feats + o);
                *(float2*)(out + o) = make_float2(r.x + g0 * f0, r.y + g1 * f1);
            }
        }
    }
}

// ---------------- flash attention (gathers rows via sidx) ----------------
#define FA_SMEM (20480 * 2 + 32 * 528)
__global__ void __launch_bounds__(256) fattn(const __nv_bfloat16* __restrict__ qkv,
                                             const int* __restrict__ sidx,
                                             __nv_bfloat16* __restrict__ o) {
    extern __shared__ char sm[];
    char* sq = sm;
    char* sk = sm + 20480;
    char* svt = sm + 40960;
    const int p = blockIdx.x, h = blockIdx.y;
    const int tid = threadIdx.x;
    const int lane = tid & 31;
    const int w = tid >> 5;
    const size_t base = (size_t)p * 256;
    const float SC = 0.17677669529663687f * 1.4426950408889634f;

    {
        const size_t src = (size_t)sidx[base + tid] * 768;
        const uint4* qr = (const uint4*)(qkv + src + h * 32);
        const uint4* kr = (const uint4*)(qkv + src + 256 + h * 32);
        const uint4* vr = (const uint4*)(qkv + src + 512 + h * 32);
        uint4* dq = (uint4*)(sq + tid * 80);
        uint4* dk = (uint4*)(sk + tid * 80);
        uint4 v0 = vr[0], v1 = vr[1], v2 = vr[2], v3 = vr[3];
        dq[0] = qr[0]; dq[1] = qr[1]; dq[2] = qr[2]; dq[3] = qr[3];
        dk[0] = kr[0]; dk[1] = kr[1]; dk[2] = kr[2]; dk[3] = kr[3];
        uint32_t vu[8] = {v0.x, v0.y, v0.z, v0.w, v1.x, v1.y, v1.z, v1.w};
        uint32_t vu2[8] = {v2.x, v2.y, v2.z, v2.w, v3.x, v3.y, v3.z, v3.w};
        #pragma unroll
        for (int e = 0; e < 8; e++) {
            ((__nv_bfloat16*)(svt + (2 * e + 0) * 528))[tid] = ((__nv_bfloat162*)&vu[e])->x;
            ((__nv_bfloat16*)(svt + (2 * e + 1) * 528))[tid] = ((__nv_bfloat162*)&vu[e])->y;
        }
        #pragma unroll
        for (int e = 0; e < 8; e++) {
            ((__nv_bfloat16*)(svt + (16 + 2 * e + 0) * 528))[tid] = ((__nv_bfloat162*)&vu2[e])->x;
            ((__nv_bfloat16*)(svt + (16 + 2 * e + 1) * 528))[tid] = ((__nv_bfloat162*)&vu2[e])->y;
        }
    }
    __syncthreads();

    const int m0w = w * 32;
    uint32_t qa[2][2][4];
    #pragma unroll
    for (int i = 0; i < 2; i++)
        #pragma unroll
        for (int kk = 0; kk < 2; kk++) {
            int r = m0w + i * 16 + (lane & 15);
            uint32_t addr = smem_u32(sq + r * 80 + kk * 32 + (lane >> 4) * 16);
            asm volatile("ldmatrix.sync.aligned.m8n8.x4.shared.b16 {%0,%1,%2,%3}, [%4];"
                         : "=r"(qa[i][kk][0]), "=r"(qa[i][kk][1]),
                           "=r"(qa[i][kk][2]), "=r"(qa[i][kk][3])
                         : "r"(addr));
        }

    float oacc[2][4][4];
    #pragma unroll
    for (int i = 0; i < 2; i++)
        #pragma unroll
        for (int d = 0; d < 4; d++)
            #pragma unroll
            for (int q = 0; q < 4; q++) oacc[i][d][q] = 0.f;
    float mrow[2][2] = {{-1e30f, -1e30f}, {-1e30f, -1e30f}};
    float lrow[2][2] = {{0.f, 0.f}, {0.f, 0.f}};

    for (int jc = 0; jc < 8; jc++) {
        uint32_t kb[2][4][2];
        #pragma unroll
        for (int jp = 0; jp < 2; jp++)
            #pragma unroll
            for (int kk = 0; kk < 2; kk++) {
                int r = jc * 32 + jp * 16 + (lane & 15);
                uint32_t addr = smem_u32(sk + r * 80 + kk * 32 + (lane >> 4) * 16);
                uint32_t r0, r1, r2, r3;
                asm volatile("ldmatrix.sync.aligned.m8n8.x4.shared.b16 {%0,%1,%2,%3}, [%4];"
                             : "=r"(r0), "=r"(r1), "=r"(r2), "=r"(r3) : "r"(addr));
                kb[kk][2*jp][0] = r0;   kb[kk][2*jp][1] = r2;
                kb[kk][2*jp+1][0] = r1; kb[kk][2*jp+1][1] = r3;
            }

        float sacc[2][4][4];
        #pragma unroll
        for (int i = 0; i < 2; i++)
            #pragma unroll
            for (int nt = 0; nt < 4; nt++)
                #pragma unroll
                for (int q = 0; q < 4; q++) sacc[i][nt][q] = 0.f;
        #pragma unroll
        for (int kk = 0; kk < 2; kk++)
            #pragma unroll
            for (int i = 0; i < 2; i++)
                #pragma unroll
                for (int nt = 0; nt < 4; nt++) {
                    asm volatile("mma.sync.aligned.m16n8k16.row.col.f32.bf16.bf16.f32 "
                                 "{%0,%1,%2,%3}, {%4,%5,%6,%7}, {%8,%9}, {%0,%1,%2,%3};"
                                 : "+f"(sacc[i][nt][0]), "+f"(sacc[i][nt][1]),
                                   "+f"(sacc[i][nt][2]), "+f"(sacc[i][nt][3])
                                 : "r"(qa[i][kk][0]), "r"(qa[i][kk][1]),
                                   "r"(qa[i][kk][2]), "r"(qa[i][kk][3]),
                                   "r"(kb[kk][nt][0]), "r"(kb[kk][nt][1]));
                }

        #pragma unroll
        for (int i = 0; i < 2; i++)
            #pragma unroll
            for (int nt = 0; nt < 4; nt++)
                #pragma unroll
                for (int q = 0; q < 4; q++) sacc[i][nt][q] *= SC;

        #pragma unroll
        for (int i = 0; i < 2; i++) {
            #pragma unroll
            for (int half = 0; half < 2; half++) {
                float mx = -1e30f;
                #pragma unroll
                for (int nt = 0; nt < 4; nt++) {
                    mx = fmaxf(mx, sacc[i][nt][half*2+0]);
                    mx = fmaxf(mx, sacc[i][nt][half*2+1]);
                }
                mx = fmaxf(mx, __shfl_xor_sync(0xffffffffu, mx, 1));
                mx = fmaxf(mx, __shfl_xor_sync(0xffffffffu, mx, 2));
                float newm = fmaxf(mrow[i][half], mx);
                float alpha = fexp2_fast(mrow[i][half] - newm);
                mrow[i][half] = newm;
                float rs = 0.f;
                #pragma unroll
                for (int nt = 0; nt < 4; nt++) {
                    float p0 = fexp2_fast(sacc[i][nt][half*2+0] - newm);
                    float p1 = fexp2_fast(sacc[i][nt][half*2+1] - newm);
                    sacc[i][nt][half*2+0] = p0;
                    sacc[i][nt][half*2+1] = p1;
                    rs += p0 + p1;
                }
                rs += __shfl_xor_sync(0xffffffffu, rs, 1);
                rs += __shfl_xor_sync(0xffffffffu, rs, 2);
                lrow[i][half] = lrow[i][half] * alpha + rs;
                #pragma unroll
                for (int dt = 0; dt < 4; dt++) {
                    oacc[i][dt][half*2+0] *= alpha;
                    oacc[i][dt][half*2+1] *= alpha;
                }
            }
        }

        uint32_t pa[2][2][4];
        #pragma unroll
        for (int i = 0; i < 2; i++)
            #pragma unroll
            for (int kk = 0; kk < 2; kk++) {
                int ntl = kk * 2, nth = kk * 2 + 1;
                __nv_bfloat162 b0 = __float22bfloat162_rn(make_float2(sacc[i][ntl][0], sacc[i][ntl][1]));
                __nv_bfloat162 b1 = __float22bfloat162_rn(make_float2(sacc[i][ntl][2], sacc[i][ntl][3]));
                __nv_bfloat162 b2 = __float22bfloat162_rn(make_float2(sacc[i][nth][0], sacc[i][nth][1]));
                __nv_bfloat162 b3 = __float22bfloat162_rn(make_float2(sacc[i][nth][2], sacc[i][nth][3]));
                pa[i][kk][0] = *(uint32_t*)&b0;
                pa[i][kk][1] = *(uint32_t*)&b1;
                pa[i][kk][2] = *(uint32_t*)&b2;
                pa[i][kk][3] = *(uint32_t*)&b3;
            }

        uint32_t vb[2][4][2];
        #pragma unroll
        for (int jp = 0; jp < 2; jp++)
            #pragma unroll
            for (int kk = 0; kk < 2; kk++) {
                int r = jp * 16 + (lane & 15);
                uint32_t addr = smem_u32(svt + r * 528 + jc * 64 + kk * 32 + (lane >> 4) * 16);
                uint32_t r0, r1, r2, r3;
                asm volatile("ldmatrix.sync.aligned.m8n8.x4.shared.b16 {%0,%1,%2,%3}, [%4];"
                             : "=r"(r0), "=r"(r1), "=r"(r2), "=r"(r3) : "r"(addr));
                vb[kk][2*jp][0] = r0;   vb[kk][2*jp][1] = r2;
                vb[kk][2*jp+1][0] = r1; vb[kk][2*jp+1][1] = r3;
            }

        #pragma unroll
        for (int kk = 0; kk < 2; kk++)
            #pragma unroll
            for (int i = 0; i < 2; i++)
                #pragma unroll
                for (int dt = 0; dt < 4; dt++) {
                    asm volatile("mma.sync.aligned.m16n8k16.row.col.f32.bf16.bf16.f32 "
                                 "{%0,%1,%2,%3}, {%4,%5,%6,%7}, {%8,%9}, {%0,%1,%2,%3};"
                                 : "+f"(oacc[i][dt][0]), "+f"(oacc[i][dt][1]),
                                   "+f"(oacc[i][dt][2]), "+f"(oacc[i][dt][3])
                                 : "r"(pa[i][kk][0]), "r"(pa[i][kk][1]),
                                   "r"(pa[i][kk][2]), "r"(pa[i][kk][3]),
                                   "r"(vb[kk][dt][0]), "r"(vb[kk][dt][1]));
                }
    }

    #pragma unroll
    for (int i = 0; i < 2; i++)
        #pragma unroll
        for (int half = 0; half < 2; half++) {
            float inv = 1.f / lrow[i][half];
            int row = m0w + i * 16 + half * 8 + (lane >> 2);
            #pragma unroll
            for (int dt = 0; dt < 4; dt++) {
                int col = h * 32 + dt * 8 + 2 * (lane & 3);
                __nv_bfloat162 hv;
                hv.x = __float2bfloat16(oacc[i][dt][half*2+0] * inv);
                hv.y = __float2bfloat16(oacc[i][dt][half*2+1] * inv);
                *(__nv_bfloat162*)(o + (base + row) * 256 + col) = hv;
            }
        }
}

// ---------------- fold gt into per-cloud biases ----------------
__global__ void cloudbias_kernel(const float* __restrict__ gtsum,
                                 const float* __restrict__ gg_w1, const float* __restrict__ gg_b1,
                                 const float* __restrict__ f_w1, const float* __restrict__ f_b1,
                                 float* __restrict__ ggb, float* __restrict__ fb, int Lc) {
    int c = blockIdx.x, j = threadIdx.x;
    float s1 = gg_b1[j], s2 = f_b1[j];
    float invL = 1.f / (float)Lc;
    for (int h = 0; h < 256; h++) {
        float gv = gtsum[c * 256 + h] * invL;
        s1 += gv * gg_w1[(size_t)(256 + h) * 256 + j];
        s2 += gv * f_w1[(size_t)(256 + h) * 256 + j];
    }
    ggb[c * 256 + j] = s1;
    fb[c * 256 + j] = s2;
}

// ---------------- launch ----------------
extern "C" void kernel_launch(void* const* d_in, const int* in_sizes, int n_in,
                              void* d_out, int out_size) {
    const float* feats = (const float*)d_in[0];
    const float* coord = (const float*)d_in[1];
    const float* pe_w1 = (const float*)d_in[3];
    const float* pe_b1 = (const float*)d_in[4];
    const float* pe_w2 = (const float*)d_in[5];
    const float* pe_b2 = (const float*)d_in[6];
    const float* pre_g = (const float*)d_in[7];
    const float* pre_b = (const float*)d_in[8];
    const float* n1_g  = (const float*)d_in[9];
    const float* n1_b  = (const float*)d_in[10];
    const float* wqkv  = (const float*)d_in[11];
    const float* bqkv  = (const float*)d_in[12];
    const float* wo    = (const float*)d_in[13];
    const float* bo    = (const float*)d_in[14];
    const float* n2_g  = (const float*)d_in[15];
    const float* n2_b  = (const float*)d_in[16];
    const float* m_w1  = (const float*)d_in[17];
    const float* m_b1  = (const float*)d_in[18];
    const float* m_w2  = (const float*)d_in[19];
    const float* m_b2  = (const float*)d_in[20];
    const float* gg_w1 = (const float*)d_in[21];
    const float* gg_b1 = (const float*)d_in[22];
    const float* gg_w2 = (const float*)d_in[23];
    const float* gg_b2 = (const float*)d_in[24];
    const float* f_w1  = (const float*)d_in[25];
    const float* f_b1  = (const float*)d_in[26];
    const float* f_w2  = (const float*)d_in[27];
    const float* f_b2  = (const float*)d_in[28];
    float* out = (float*)d_out;

    int N = in_sizes[0] / 256;
    int B = in_sizes[2];
    int Lc = N / B;
    int patches = N / 256;

    float *p_x, *p_xs, *p_key, *p_gt, *p_ggb, *p_fb, *p_stats;
    __nv_bfloat16 *p_ba, *p_bb, *p_fe, *p_wt;
    int* p_idx;
    cudaGetSymbolAddress((void**)&p_x, g_x);
    cudaGetSymbolAddress((void**)&p_xs, g_xs);
    cudaGetSymbolAddress((void**)&p_ba, g_ba);
    cudaGetSymbolAddress((void**)&p_bb, g_bb);
    cudaGetSymbolAddress((void**)&p_fe, g_fe);
    cudaGetSymbolAddress((void**)&p_wt, g_wt);
    cudaGetSymbolAddress((void**)&p_key, g_key);
    cudaGetSymbolAddress((void**)&p_idx, g_idx);
    cudaGetSymbolAddress((void**)&p_gt, g_gt);
    cudaGetSymbolAddress((void**)&p_ggb, g_ggb);
    cudaGetSymbolAddress((void**)&p_fb, g_fb);
    cudaGetSymbolAddress((void**)&p_stats, g_stats);

    __nv_bfloat16* wqkv_t = p_wt + 0;
    __nv_bfloat16* wo_t   = p_wt + 196608;
    __nv_bfloat16* mw1_t  = p_wt + 262144;
    __nv_bfloat16* mw2_t  = p_wt + 393216;
    __nv_bfloat16* ggw1_t = p_wt + 524288;
    __nv_bfloat16* ggw2_t = p_wt + 589824;
    __nv_bfloat16* fw1_t  = p_wt + 655360;
    __nv_bfloat16* fw2_t  = p_wt + 720896;
    __nv_bfloat16* bb_lo = p_bb;
    __nv_bfloat16* bb_hi = p_bb + (size_t)N * 256;

    static cudaStream_t s2 = nullptr;
    static cudaEvent_t ev1 = nullptr, ev2 = nullptr;
    if (!s2) {
        cudaStreamCreateWithFlags(&s2, cudaStreamNonBlocking);
        cudaEventCreateWithFlags(&ev1, cudaEventDisableTiming);
        cudaEventCreateWithFlags(&ev2, cudaEventDisableTiming);
    }

    cudaFuncSetAttribute(fattn, cudaFuncAttributeMaxDynamicSharedMemorySize, FA_SMEM);
    cudaFuncSetAttribute(gemm_bf16<8>, cudaFuncAttributeMaxDynamicSharedMemorySize, NSTAGE * STG_BYTES);
    cudaFuncSetAttribute(gemm_bf16<16>, cudaFuncAttributeMaxDynamicSharedMemorySize, NSTAGE * STG_BYTES);
    cudaFuncSetAttribute(gemm_final, cudaFuncAttributeMaxDynamicSharedMemorySize, DNSTAGE * DSTG);

    PrepArgs pa;
    pa.coord = coord; pa.stats = p_stats; pa.Lc = Lc; pa.B = B;
    const float* ws[8] = {wqkv, wo, m_w1, m_w2, gg_w1, gg_w2, f_w1, f_w2};
    __nv_bfloat16* wd[8] = {wqkv_t, wo_t, mw1_t, mw2_t, ggw1_t, ggw2_t, fw1_t, fw2_t};
    int wK[8] = {256, 256, 256, 512, 256, 256, 256, 256};
    int wN[8] = {768, 256, 512, 256, 256, 256, 256, 256};
    int tiles = 0;
    for (int i = 0; i < 8; i++) {
        pa.wsrc[i] = ws[i]; pa.wdst[i] = wd[i];
        pa.wK[i] = wK[i]; pa.wN[i] = wN[i];
        pa.wt0[i] = tiles;
        tiles += (wK[i] / 32) * (wN[i] / 32);
    }
    pa.totalWTiles = tiles;
    pa.gt = p_gt;

    // 1: prep
    prep_kernel<<<B + tiles + 1, 1024>>>(pa);
    // 2: PE + pre-LN + LN1 + key (original order)
    pe_ln_key_kernel<<<N, 256>>>(feats, coord, pe_w1, pe_b1, pe_w2, pe_b2,
                                 pre_g, pre_b, n1_g, n1_b, p_stats,
                                 p_x, p_bb, p_fe, p_key, p_idx, Lc);
    // fork: sort chain on s2, qkv GEMM on main
    cudaEventRecord(ev1, 0);
    cudaStreamWaitEvent(s2, ev1, 0);
    // 3 (s2): local sort
    sort_local<<<N / CHUNK, 1024, CHUNK * 8, s2>>>(p_key, p_idx, Lc);
    // 4 (main): qkv GEMM -> ba  [profiled launch]
    gemm_bf16<8><<<dim3(768/GBN, N/GBM), 256, NSTAGE*STG_BYTES>>>(
        p_bb, wqkv_t, bqkv, nullptr, nullptr, p_ba, N, 768, 0, 0, 1,
        nullptr, nullptr, 0, nullptr, nullptr, nullptr, nullptr);
    // (s2): finish the sort
    for (int k = CHUNK * 2; k <= Lc; k <<= 1) {
        for (int j = k >> 1; j >= CHUNK; j >>= 1)
            sort_global<<<dim3(Lc / 512, B), 256, 0, s2>>>(p_key, p_idx, k, j, Lc);
        merge_local<<<N / CHUNK, 1024, CHUNK * 8, s2>>>(p_key, p_idx, k, Lc);
    }
    cudaEventRecord(ev2, s2);
    cudaStreamWaitEvent(0, ev2, 0);
    // flash attention (gather via idx) -> bb
    fattn<<<dim3(patches, 8), 256, FA_SMEM>>>(p_ba, p_idx, p_bb);
    // wo GEMM + gathered residual -> xs fp32
    gemm_bf16<8><<<dim3(256/GBN, N/GBM), 256, NSTAGE*STG_BYTES>>>(
        p_bb, wo_t, bo, p_x, nullptr, p_xs, N, 256, 0, 4, 0,
        p_idx, nullptr, 0, nullptr, nullptr, nullptr, nullptr);
    // LN2 -> ba bf16
    ln_bf<<<N, 256>>>(p_xs, n2_g, n2_b, p_ba);
    // MLP1 + gelu -> bb
    gemm_bf16<8><<<dim3(512/GBN, N/GBM), 256, NSTAGE*STG_BYTES>>>(
        p_ba, mw1_t, m_b1, nullptr, nullptr, p_bb, N, 512, 0, 2, 1,
        nullptr, nullptr, 0, nullptr, nullptr, nullptr, nullptr);
    // MLP2 + resid; scatter xo -> ba; gt atomics
    gemm_bf16<16><<<dim3(256/GBN, N/GBM), 256, NSTAGE*STG_BYTES>>>(
        p_bb, mw2_t, m_b2, p_xs, nullptr, p_ba, N, 256, 0, 6, 1,
        p_idx, p_gt, Lc, nullptr, nullptr, nullptr, nullptr);
    // per-cloud biases
    cloudbias_kernel<<<B, 256>>>(p_gt, gg_w1, gg_b1, f_w1, f_b1, p_ggb, p_fb, Lc);
    // batched hidden GEMMs (z=0 gate-hidden, z=1 fuse-hidden)
    gemm_bf16<8><<<dim3(256/GBN, N/GBM, 2), 256, NSTAGE*STG_BYTES>>>(
        p_fe, ggw1_t, p_ggb, nullptr, nullptr, bb_lo, N, 256, Lc, 1, 1,
        nullptr, nullptr, 0, p_ba, fw1_t, p_fb, bb_hi);
    // fused final: out = feats + sigmoid(bb_lo@gg_w2+gg_b2) * (bb_hi@f_w2+f_b2)
    gemm_final<<<dim3(256/64, N/128), 256, DNSTAGE*DSTG>>>(
        bb_lo, ggw2_t, gg_b2, bb_hi, fw2_t, f_b2, feats, out, 256);
}

// round 15
// speedup vs baseline: 1.3699x; 1.2153x over previous
#include <cuda_runtime.h>
#include <cuda_bf16.h>
#include <math.h>
#include <stdint.h>

// ---------------- static scratch ----------------
#define MAXN 131072
#define DD 256
__device__ float g_x  [(size_t)MAXN * DD];
__device__ float g_xs [(size_t)MAXN * DD];
__device__ __nv_bfloat16 g_ba[(size_t)MAXN * 768];
__device__ __nv_bfloat16 g_bb[(size_t)MAXN * 512];
__device__ __nv_bfloat16 g_fe[(size_t)MAXN * 256];
__device__ __nv_bfloat16 g_wt[802816];
__device__ float g_key[MAXN];
__device__ int   g_idx[MAXN];
__device__ float g_gt [8 * DD];
__device__ float g_ggb[8 * DD];
__device__ float g_fb [8 * DD];
__device__ float g_stats[8 * 12];

// ---------------- fast math ----------------
__device__ __forceinline__ float fexp2_fast(float z) {
    z = fmaxf(z, -80.f);
    float n = rintf(z);
    float f = z - n;
    float p = 0.009618129f;
    p = p * f + 0.055504109f;
    p = p * f + 0.240226507f;
    p = p * f + 0.693147181f;
    p = p * f + 1.0f;
    return p * __int_as_float(((int)n + 127) << 23);
}
__device__ __forceinline__ float fexpf_fast(float x) {
    return fexp2_fast(x * 1.4426950408889634f);
}
__device__ __forceinline__ float frcp_fast(float d) {
    float y = __int_as_float(0x7ef311c3 - __float_as_int(d));
    y = y * (2.f - d * y);
    y = y * (2.f - d * y);
    y = y * (2.f - d * y);
    return y;
}
__device__ __forceinline__ uint32_t smem_u32(const void* p) {
    return (uint32_t)__cvta_generic_to_shared(p);
}
// warp dual-sum
__device__ __forceinline__ float2 warpsum2(float a, float b) {
    #pragma unroll
    for (int off = 16; off; off >>= 1) {
        a += __shfl_xor_sync(0xffffffffu, a, off);
        b += __shfl_xor_sync(0xffffffffu, b, off);
    }
    return make_float2(a, b);
}

// ---------------- prep ----------------
struct PrepArgs {
    const float* coord; float* stats; int Lc; int B;
    const float* wsrc[9]; __nv_bfloat16* wdst[9];
    int wK[9], wN[9], wt0[9];
    int totalWTiles;
    float* gt;
};
__global__ void __launch_bounds__(1024) prep_kernel(PrepArgs a) {
    __shared__ float red[1024];
    __shared__ float tt[32][33];
    int b = blockIdx.x, tid = threadIdx.x;
    if (b < a.B) {
        int c = b, Lc = a.Lc;
        float sum[3] = {0,0,0}, mn[3] = {1e30f,1e30f,1e30f}, mx[3] = {-1e30f,-1e30f,-1e30f};
        for (int i = tid; i < Lc; i += 1024) {
            const float* cp = a.coord + (size_t)(c * Lc + i) * 3;
            #pragma unroll
            for (int d = 0; d < 3; d++) {
                float v = cp[d];
                sum[d] += v; mn[d] = fminf(mn[d], v); mx[d] = fmaxf(mx[d], v);
            }
        }
        for (int d = 0; d < 3; d++) {
            red[tid] = sum[d]; __syncthreads();
            for (int s = 512; s > 0; s >>= 1) { if (tid < s) red[tid] += red[tid + s]; __syncthreads(); }
            float tot = red[0]; __syncthreads();
            red[tid] = mn[d]; __syncthreads();
            for (int s = 512; s > 0; s >>= 1) { if (tid < s) red[tid] = fminf(red[tid], red[tid + s]); __syncthreads(); }
            float tmn = red[0]; __syncthreads();
            red[tid] = mx[d]; __syncthreads();
            for (int s = 512; s > 0; s >>= 1) { if (tid < s) red[tid] = fmaxf(red[tid], red[tid + s]); __syncthreads(); }
            float tmx = red[0]; __syncthreads();
            if (tid == 0) {
                float mean = tot / (float)Lc;
                a.stats[c*12 + d]     = mean;
                a.stats[c*12 + 3 + d] = fmaxf(fmaxf(tmx - mean, mean - tmn), 1e-6f);
                a.stats[c*12 + 6 + d] = tmn;
                a.stats[c*12 + 9 + d] = 1.f / fmaxf(tmx - tmn, 1e-6f);
            }
            __syncthreads();
        }
    } else if (b < a.B + a.totalWTiles) {
        int t = b - a.B;
        int w = 0;
        #pragma unroll
        for (int q = 1; q < 9; q++) if (t >= a.wt0[q]) w = q;
        int lt = t - a.wt0[w];
        int tilesX = a.wN[w] >> 5;
        int bx = (lt % tilesX) << 5, by = (lt / tilesX) << 5;
        const float* src = a.wsrc[w];
        __nv_bfloat16* dst = a.wdst[w];
        int K = a.wK[w], Ncols = a.wN[w];
        int tx = tid & 31, ty = tid >> 5;
        tt[ty][tx] = src[(size_t)(by + ty) * Ncols + bx + tx];
        __syncthreads();
        dst[(size_t)(bx + ty) * K + by + tx] = __float2bfloat16(tt[tx][ty]);
    } else {
        a.gt[tid] = 0.f;
        a.gt[tid + 1024] = 0.f;
    }
}

// ---------------- hid + key (warp per point) ----------------
__global__ void __launch_bounds__(256) hid_key_kernel(
    const float* __restrict__ coord,
    const float* __restrict__ w1, const float* __restrict__ b1,
    const float* __restrict__ stats,
    __nv_bfloat16* __restrict__ hidout,
    float* __restrict__ key, int* __restrict__ idx, int Lc)
{
    int warp = threadIdx.x >> 5, lane = threadIdx.x & 31;
    int i = blockIdx.x * 8 + warp;
    int c = i / Lc;
    const float* st = stats + c * 12;
    float c0 = coord[(size_t)i*3+0], c1 = coord[(size_t)i*3+1], c2 = coord[(size_t)i*3+2];
    float n0 = (c0 - st[0]) / st[3];
    float n1 = (c1 - st[1]) / st[4];
    float n2 = (c2 - st[2]) / st[5];
    float hA = fmaxf(b1[lane]      + n0 * w1[lane]      + n1 * w1[64 + lane]  + n2 * w1[128 + lane], 0.f);
    float hB = fmaxf(b1[lane + 32] + n0 * w1[lane + 32] + n1 * w1[96 + lane]  + n2 * w1[160 + lane], 0.f);
    hidout[(size_t)i * 64 + lane]      = __float2bfloat16(hA);
    hidout[(size_t)i * 64 + 32 + lane] = __float2bfloat16(hB);
    if (lane == 0) {
        float k0 = (c0 - st[6]) * st[9];
        float k1 = (c1 - st[7]) * st[10];
        float k2 = (c2 - st[8]) * st[11];
        key[i] = k0 + 2.17f * k1 + 3.31f * k2;
        idx[i] = i;
    }
}

// ---------------- LN1 chain (warp per point): v=feats+pe; preLN -> xout; LN1 -> hbf; febf ----------------
__global__ void __launch_bounds__(256) ln1_kernel(
    const float* __restrict__ feats, const __nv_bfloat16* __restrict__ pe,
    const float* __restrict__ g, const float* __restrict__ beta,
    const float* __restrict__ n1g, const float* __restrict__ n1b,
    float* __restrict__ xout, __nv_bfloat16* __restrict__ hbf,
    __nv_bfloat16* __restrict__ febf)
{
    int warp = threadIdx.x >> 5, lane = threadIdx.x & 31;
    size_t i = (size_t)blockIdx.x * 8 + warp;
    const int c0 = lane * 8;
    const float* fr = feats + i * 256 + c0;
    float4 fa = *(const float4*)fr;
    float4 fb = *(const float4*)(fr + 4);
    float f[8] = {fa.x, fa.y, fa.z, fa.w, fb.x, fb.y, fb.z, fb.w};
    uint4 pu = *(const uint4*)(pe + i * 256 + c0);
    const __nv_bfloat162* pp = (const __nv_bfloat162*)&pu;
    float v[8];
    #pragma unroll
    for (int e = 0; e < 4; e++) {
        float2 p2 = __bfloat1622float2(pp[e]);
        v[e*2+0] = f[e*2+0] + p2.x;
        v[e*2+1] = f[e*2+1] + p2.y;
    }
    // febf
    {
        uint4 pk; uint32_t* pw = (uint32_t*)&pk;
        #pragma unroll
        for (int e = 0; e < 4; e++) {
            __nv_bfloat162 h;
            h.x = __float2bfloat16(f[e*2+0]); h.y = __float2bfloat16(f[e*2+1]);
            pw[e] = *(uint32_t*)&h;
        }
        *(uint4*)(febf + i * 256 + c0) = pk;
    }
    float s1 = 0.f, s2 = 0.f;
    #pragma unroll
    for (int e = 0; e < 8; e++) { s1 += v[e]; s2 += v[e] * v[e]; }
    float2 ss = warpsum2(s1, s2);
    float mean = ss.x * (1.f / 256.f);
    float var = ss.y * (1.f / 256.f) - mean * mean;
    float rs = rsqrtf(var + 1e-5f);
    float xv[8];
    float t1 = 0.f, t2 = 0.f;
    #pragma unroll
    for (int e = 0; e < 8; e++) {
        xv[e] = (v[e] - mean) * rs * g[c0 + e] + beta[c0 + e];
        t1 += xv[e]; t2 += xv[e] * xv[e];
    }
    *(float4*)(xout + i * 256 + c0)     = make_float4(xv[0], xv[1], xv[2], xv[3]);
    *(float4*)(xout + i * 256 + c0 + 4) = make_float4(xv[4], xv[5], xv[6], xv[7]);
    float2 tt = warpsum2(t1, t2);
    float m2 = tt.x * (1.f / 256.f);
    float v2 = tt.y * (1.f / 256.f) - m2 * m2;
    float rs2 = rsqrtf(v2 + 1e-5f);
    uint4 pk; uint32_t* pw = (uint32_t*)&pk;
    #pragma unroll
    for (int e = 0; e < 4; e++) {
        __nv_bfloat162 h;
        h.x = __float2bfloat16((xv[e*2+0] - m2) * rs2 * n1g[c0 + e*2+0] + n1b[c0 + e*2+0]);
        h.y = __float2bfloat16((xv[e*2+1] - m2) * rs2 * n1g[c0 + e*2+1] + n1b[c0 + e*2+1]);
        pw[e] = *(uint32_t*)&h;
    }
    *(uint4*)(hbf + i * 256 + c0) = pk;
}

// ---------------- hierarchical bitonic sort (CHUNK=4096) ----------------
#define CHUNK 4096
__global__ void __launch_bounds__(1024) sort_local(float* __restrict__ key, int* __restrict__ idx, int Lc) {
    extern __shared__ char smraw[];
    float* sk = (float*)smraw;
    int*   si = (int*)(smraw + CHUNK * 4);
    size_t gbase = (size_t)blockIdx.x * CHUNK;
    int lbase = (int)(gbase % (size_t)Lc);
    for (int t = threadIdx.x; t < CHUNK; t += 1024) { sk[t] = key[gbase + t]; si[t] = idx[gbase + t]; }
    __syncthreads();
    for (int k = 2; k <= CHUNK; k <<= 1) {
        for (int j = k >> 1; j > 0; j >>= 1) {
            #pragma unroll
            for (int it = 0; it < CHUNK / 2048; it++) {
                int t = threadIdx.x + it * 1024;
                int i = 2 * t - (t & (j - 1));
                int p = i + j;
                bool up = (((lbase + i) & k) == 0);
                float a = sk[i], b = sk[p];
                int ia = si[i], ib = si[p];
                bool sw = up ? (a > b || (a == b && ia > ib)) : (a < b || (a == b && ia < ib));
                if (sw) { sk[i] = b; sk[p] = a; si[i] = ib; si[p] = ia; }
            }
            __syncthreads();
        }
    }
    for (int t = threadIdx.x; t < CHUNK; t += 1024) { key[gbase + t] = sk[t]; idx[gbase + t] = si[t]; }
}

__global__ void __launch_bounds__(1024) merge_local(float* __restrict__ key, int* __restrict__ idx, int k, int Lc) {
    extern __shared__ char smraw[];
    float* sk = (float*)smraw;
    int*   si = (int*)(smraw + CHUNK * 4);
    size_t gbase = (size_t)blockIdx.x * CHUNK;
    int lbase = (int)(gbase % (size_t)Lc);
    for (int t = threadIdx.x; t < CHUNK; t += 1024) { sk[t] = key[gbase + t]; si[t] = idx[gbase + t]; }
    __syncthreads();
    for (int j = CHUNK / 2; j > 0; j >>= 1) {
        #pragma unroll
        for (int it = 0; it < CHUNK / 2048; it++) {
            int t = threadIdx.x + it * 1024;
            int i = 2 * t - (t & (j - 1));
            int p = i + j;
            bool up = (((lbase + i) & k) == 0);
            float a = sk[i], b = sk[p];
            int ia = si[i], ib = si[p];
            bool sw = up ? (a > b || (a == b && ia > ib)) : (a < b || (a == b && ia < ib));
            if (sw) { sk[i] = b; sk[p] = a; si[i] = ib; si[p] = ia; }
        }
        __syncthreads();
    }
    for (int t = threadIdx.x; t < CHUNK; t += 1024) { key[gbase + t] = sk[t]; idx[gbase + t] = si[t]; }
}

__global__ void __launch_bounds__(256) sort_global(float* __restrict__ key, int* __restrict__ idx, int k, int j, int Lc) {
    int c = blockIdx.y;
    size_t base = (size_t)c * Lc;
    int t = blockIdx.x * 256 + threadIdx.x;
    int i = 2 * t - (t & (j - 1));
    int p = i + j;
    bool up = ((i & k) == 0);
    float a = key[base + i], b = key[base + p];
    int ia = idx[base + i], ib = idx[base + p];
    bool sw = up ? (a > b || (a == b && ia > ib)) : (a < b || (a == b && ia < ib));
    if (sw) {
        key[base + i] = b; key[base + p] = a;
        idx[base + i] = ib; idx[base + p] = ia;
    }
}

// ---------------- LN2 -> bf16 (warp per row) ----------------
__global__ void __launch_bounds__(256) ln_bf(const float* __restrict__ x, const float* __restrict__ g,
                                             const float* __restrict__ b, __nv_bfloat16* __restrict__ y) {
    int warp = threadIdx.x >> 5, lane = threadIdx.x & 31;
    size_t row = (size_t)blockIdx.x * 8 + warp;
    const int c0 = lane * 8;
    const float* xr = x + row * 256 + c0;
    float4 xa = *(const float4*)xr;
    float4 xb = *(const float4*)(xr + 4);
    float v[8] = {xa.x, xa.y, xa.z, xa.w, xb.x, xb.y, xb.z, xb.w};
    float s1 = 0.f, s2 = 0.f;
    #pragma unroll
    for (int e = 0; e < 8; e++) { s1 += v[e]; s2 += v[e] * v[e]; }
    float2 ss = warpsum2(s1, s2);
    float mean = ss.x * (1.f / 256.f);
    float var = ss.y * (1.f / 256.f) - mean * mean;
    float rs = rsqrtf(var + 1e-5f);
    uint4 pk; uint32_t* pw = (uint32_t*)&pk;
    #pragma unroll
    for (int e = 0; e < 4; e++) {
        __nv_bfloat162 h;
        h.x = __float2bfloat16((v[e*2+0] - mean) * rs * g[c0 + e*2+0] + b[c0 + e*2+0]);
        h.y = __float2bfloat16((v[e*2+1] - mean) * rs * g[c0 + e*2+1] + b[c0 + e*2+1]);
        pw[e] = *(uint32_t*)&h;
    }
    *(uint4*)(y + row * 256 + c0) = pk;
}

// ---------------- tensor-core GEMM: 128x64 tile, warp tile 32x32, 3 CTAs/SM ----------------
// epi: 0 none, 1 relu, 2 gelu, 3 sigmoid, 4 +resid[ridx], 5 resid + gate*val,
//      6 +resid[m]; bf16 scatter to Cout[ridx[m]]; atomic gt column sums
#define GBM 128
#define GBN 64
#define GKT 32
#define STG_BYTES 15360
#define NSTAGE 4

template<int NK>
__global__ void __launch_bounds__(256, 3) gemm_bf16(
    const __nv_bfloat16* __restrict__ A_, const __nv_bfloat16* __restrict__ Bt_,
    const float* __restrict__ bias_,
    const float* __restrict__ resid, const float* __restrict__ gate,
    void* __restrict__ Cout_,
    int M, int Ncols, int cloudLen, int epi, int outBf16,
    const int* __restrict__ ridx, float* __restrict__ gtp, int gtLc,
    const __nv_bfloat16* A2, const __nv_bfloat16* Bt2, const float* bias2, void* Cout2)
{
    constexpr int K = NK * GKT;
    extern __shared__ char smraw[];
    const __nv_bfloat16* A = A_;
    const __nv_bfloat16* Bt = Bt_;
    const float* bias = bias_;
    void* Cout = Cout_;
    if (blockIdx.z == 1) { A = A2; Bt = Bt2; bias = bias2; Cout = Cout2; }
    const int tid = threadIdx.x;
    const int lane = tid & 31;
    const int warp = tid >> 5;
    const int wm = warp >> 1, wn = warp & 1;
    const int m0 = blockIdx.y * GBM, n0 = blockIdx.x * GBN;

    float acc[2][4][4];
    #pragma unroll
    for (int i = 0; i < 2; i++)
        #pragma unroll
        for (int j = 0; j < 4; j++)
            #pragma unroll
            for (int q = 0; q < 4; q++) acc[i][j][q] = 0.f;

    const int arow0 = tid >> 2, ac0 = tid & 3;
    const int arow1 = (tid + 256) >> 2;
    const __nv_bfloat16* gA0 = A + (size_t)(m0 + arow0) * K + ac0 * 8;
    const __nv_bfloat16* gA1 = A + (size_t)(m0 + arow1) * K + ac0 * 8;
    const __nv_bfloat16* gB0 = Bt + (size_t)(n0 + arow0) * K + ac0 * 8;
    const uint32_t smemBase = smem_u32(smraw);
    const uint32_t dA0 = smemBase + arow0 * 80 + ac0 * 16;
    const uint32_t dA1 = smemBase + arow1 * 80 + ac0 * 16;
    const uint32_t dB0 = smemBase + 10240 + arow0 * 80 + ac0 * 16;

    uint32_t aoff[2], boff[2];
    #pragma unroll
    for (int i = 0; i < 2; i++)
        aoff[i] = smemBase + (wm * 32 + i * 16 + (lane & 15)) * 80 + (lane >> 4) * 16;
    #pragma unroll
    for (int jp = 0; jp < 2; jp++)
        boff[jp] = smemBase + 10240 + (wn * 32 + jp * 16 + (lane & 15)) * 80 + (lane >> 4) * 16;

    auto issue = [&](int s, int kt) {
        uint32_t sb = s * STG_BYTES;
        int go = kt * GKT;
        asm volatile("cp.async.cg.shared.global [%0], [%1], 16;\n" :: "r"(dA0 + sb), "l"(gA0 + go));
        asm volatile("cp.async.cg.shared.global [%0], [%1], 16;\n" :: "r"(dA1 + sb), "l"(gA1 + go));
        asm volatile("cp.async.cg.shared.global [%0], [%1], 16;\n" :: "r"(dB0 + sb), "l"(gB0 + go));
        asm volatile("cp.async.commit_group;\n");
    };

    issue(0, 0);
    issue(1, 1);
    #pragma unroll
    for (int kt = 0; kt < NK; kt++) {
        const int s = kt & (NSTAGE - 1);
        if (kt + 2 < NK) {
            issue((kt + 2) & (NSTAGE - 1), kt + 2);
            asm volatile("cp.async.wait_group 2;\n");
        } else if (kt + 1 < NK) {
            asm volatile("cp.async.wait_group 1;\n");
        } else {
            asm volatile("cp.async.wait_group 0;\n");
        }
        __syncthreads();

        const uint32_t sb = s * STG_BYTES;
        #pragma unroll
        for (int kk = 0; kk < 2; kk++) {
            uint32_t af[2][4];
            #pragma unroll
            for (int i = 0; i < 2; i++) {
                asm volatile("ldmatrix.sync.aligned.m8n8.x4.shared.b16 {%0,%1,%2,%3}, [%4];"
                             : "=r"(af[i][0]), "=r"(af[i][1]), "=r"(af[i][2]), "=r"(af[i][3])
                             : "r"(aoff[i] + sb + kk * 32));
            }
            uint32_t bf[4][2];
            #pragma unroll
            for (int jp = 0; jp < 2; jp++) {
                uint32_t r0, r1, r2, r3;
                asm volatile("ldmatrix.sync.aligned.m8n8.x4.shared.b16 {%0,%1,%2,%3}, [%4];"
                             : "=r"(r0), "=r"(r1), "=r"(r2), "=r"(r3)
                             : "r"(boff[jp] + sb + kk * 32));
                bf[2*jp][0] = r0; bf[2*jp+1][0] = r1;
                bf[2*jp][1] = r2; bf[2*jp+1][1] = r3;
            }
            #pragma unroll
            for (int i = 0; i < 2; i++)
                #pragma unroll
                for (int j = 0; j < 4; j++) {
                    asm volatile("mma.sync.aligned.m16n8k16.row.col.f32.bf16.bf16.f32 "
                                 "{%0,%1,%2,%3}, {%4,%5,%6,%7}, {%8,%9}, {%0,%1,%2,%3};"
                                 : "+f"(acc[i][j][0]), "+f"(acc[i][j][1]),
                                   "+f"(acc[i][j][2]), "+f"(acc[i][j][3])
                                 : "r"(af[i][0]), "r"(af[i][1]), "r"(af[i][2]), "r"(af[i][3]),
                                   "r"(bf[j][0]), "r"(bf[j][1]));
                }
        }
    }

    const int rbase = m0 + wm * 32 + (lane >> 2);
    const int cbase = n0 + wn * 32 + 2 * (lane & 3);
    float gta[4][2];
    #pragma unroll
    for (int j = 0; j < 4; j++) { gta[j][0] = 0.f; gta[j][1] = 0.f; }

    #pragma unroll
    for (int i = 0; i < 2; i++) {
        #pragma unroll
        for (int half = 0; half < 2; half++) {
            int m = rbase + i * 16 + half * 8;
            const float* bp = (cloudLen > 0) ? (bias + (size_t)(m / cloudLen) * Ncols) : bias;
            #pragma unroll
            for (int j = 0; j < 4; j++) {
                int n = cbase + j * 8;
                float v0 = acc[i][j][half * 2 + 0] + bp[n];
                float v1 = acc[i][j][half * 2 + 1] + bp[n + 1];
                size_t o = (size_t)m * Ncols + n;
                bool stored = false;
                switch (epi) {
                    case 1: v0 = fmaxf(v0, 0.f); v1 = fmaxf(v1, 0.f); break;
                    case 2:
                        v0 = 0.5f * v0 * (1.f + erff(v0 * 0.70710678118f));
                        v1 = 0.5f * v1 * (1.f + erff(v1 * 0.70710678118f));
                        break;
                    case 3:
                        v0 = frcp_fast(1.f + fexpf_fast(-v0));
                        v1 = frcp_fast(1.f + fexpf_fast(-v1));
                        break;
                    case 4: {
                        size_t ro = (size_t)(ridx ? ridx[m] : m) * Ncols + n;
                        float2 r = *(const float2*)(resid + ro);
                        v0 += r.x; v1 += r.y;
                    } break;
                    case 5: {
                        float2 r = *(const float2*)(resid + o);
                        float2 gg = *(const float2*)(gate + o);
                        v0 = r.x + gg.x * v0; v1 = r.y + gg.y * v1;
                    } break;
                    case 6: {
                        float2 r = *(const float2*)(resid + o);
                        v0 += r.x; v1 += r.y;
                        gta[j][0] += v0; gta[j][1] += v1;
                        size_t od = (size_t)ridx[m] * Ncols + n;
                        __nv_bfloat162 h;
                        h.x = __float2bfloat16(v0); h.y = __float2bfloat16(v1);
                        *(__nv_bfloat162*)((__nv_bfloat16*)Cout + od) = h;
                        stored = true;
                    } break;
                    default: break;
                }
                if (!stored) {
                    if (outBf16) {
                        __nv_bfloat162 h;
                        h.x = __float2bfloat16(v0); h.y = __float2bfloat16(v1);
                        *(__nv_bfloat162*)((__nv_bfloat16*)Cout + o) = h;
                    } else {
                        *(float2*)((float*)Cout + o) = make_float2(v0, v1);
                    }
                }
            }
        }
    }
    if (epi == 6) {
        int c = m0 / gtLc;
        #pragma unroll
        for (int j = 0; j < 4; j++) {
            float s0 = gta[j][0], s1 = gta[j][1];
            #pragma unroll
            for (int off = 4; off <= 16; off <<= 1) {
                s0 += __shfl_xor_sync(0xffffffffu, s0, off);
                s1 += __shfl_xor_sync(0xffffffffu, s1, off);
            }
            if ((lane >> 2) == 0) {
                int n = cbase + j * 8;
                atomicAdd(gtp + c * 256 + n, s0);
                atomicAdd(gtp + c * 256 + n + 1, s1);
            }
        }
    }
}

// ---------------- dual GEMM final: out = feats + sigmoid(A1@W1+b1) * (A2@W2+b2) ----------------
#define DSTG 30720
#define DNSTAGE 3
__global__ void __launch_bounds__(256, 2) gemm_final(
    const __nv_bfloat16* __restrict__ A1, const __nv_bfloat16* __restrict__ W1,
    const float* __restrict__ b1,
    const __nv_bfloat16* __restrict__ A2, const __nv_bfloat16* __restrict__ W2,
    const float* __restrict__ b2,
    const float* __restrict__ feats, float* __restrict__ out, int Ncols)
{
    constexpr int NK = 8;
    extern __shared__ char smraw[];
    const int tid = threadIdx.x;
    const int lane = tid & 31;
    const int warp = tid >> 5;
    const int wm = warp >> 1, wn = warp & 1;
    const int m0 = blockIdx.y * 128, n0 = blockIdx.x * 64;

    float acc1[2][4][4], acc2[2][4][4];
    #pragma unroll
    for (int i = 0; i < 2; i++)
        #pragma unroll
        for (int j = 0; j < 4; j++)
            #pragma unroll
            for (int q = 0; q < 4; q++) { acc1[i][j][q] = 0.f; acc2[i][j][q] = 0.f; }

    const int arow0 = tid >> 2, ac0 = tid & 3;
    const int arow1 = (tid + 256) >> 2;
    const __nv_bfloat16* gA1_0 = A1 + (size_t)(m0 + arow0) * 256 + ac0 * 8;
    const __nv_bfloat16* gA1_1 = A1 + (size_t)(m0 + arow1) * 256 + ac0 * 8;
    const __nv_bfloat16* gA2_0 = A2 + (size_t)(m0 + arow0) * 256 + ac0 * 8;
    const __nv_bfloat16* gA2_1 = A2 + (size_t)(m0 + arow1) * 256 + ac0 * 8;
    const __nv_bfloat16* gB1_0 = W1 + (size_t)(n0 + arow0) * 256 + ac0 * 8;
    const __nv_bfloat16* gB2_0 = W2 + (size_t)(n0 + arow0) * 256 + ac0 * 8;
    const uint32_t smemBase = smem_u32(smraw);
    const uint32_t dA1_0 = smemBase + arow0 * 80 + ac0 * 16;
    const uint32_t dA1_1 = smemBase + arow1 * 80 + ac0 * 16;
    const uint32_t dB1_0 = smemBase + 10240 + arow0 * 80 + ac0 * 16;
    const uint32_t dA2_0 = smemBase + 15360 + arow0 * 80 + ac0 * 16;
    const uint32_t dA2_1 = smemBase + 15360 + arow1 * 80 + ac0 * 16;
    const uint32_t dB2_0 = smemBase + 25600 + arow0 * 80 + ac0 * 16;

    uint32_t aoff[2], boff[2];
    #pragma unroll
    for (int i = 0; i < 2; i++)
        aoff[i] = smemBase + (wm * 32 + i * 16 + (lane & 15)) * 80 + (lane >> 4) * 16;
    #pragma unroll
    for (int jp = 0; jp < 2; jp++)
        boff[jp] = smemBase + 10240 + (wn * 32 + jp * 16 + (lane & 15)) * 80 + (lane >> 4) * 16;

    auto issue = [&](int s, int kt) {
        uint32_t sb = s * DSTG;
        int go = kt * 32;
        asm volatile("cp.async.cg.shared.global [%0], [%1], 16;\n" :: "r"(dA1_0 + sb), "l"(gA1_0 + go));
        asm volatile("cp.async.cg.shared.global [%0], [%1], 16;\n" :: "r"(dA1_1 + sb), "l"(gA1_1 + go));
        asm volatile("cp.async.cg.shared.global [%0], [%1], 16;\n" :: "r"(dB1_0 + sb), "l"(gB1_0 + go));
        asm volatile("cp.async.cg.shared.global [%0], [%1], 16;\n" :: "r"(dA2_0 + sb), "l"(gA2_0 + go));
        asm volatile("cp.async.cg.shared.global [%0], [%1], 16;\n" :: "r"(dA2_1 + sb), "l"(gA2_1 + go));
        asm volatile("cp.async.cg.shared.global [%0], [%1], 16;\n" :: "r"(dB2_0 + sb), "l"(gB2_0 + go));
        asm volatile("cp.async.commit_group;\n");
    };

    issue(0, 0);
    issue(1, 1);
    #pragma unroll
    for (int kt = 0; kt < NK; kt++) {
        const int s = kt % DNSTAGE;
        if (kt + 1 < NK) {
            asm volatile("cp.async.wait_group 1;\n");
        } else {
            asm volatile("cp.async.wait_group 0;\n");
        }
        __syncthreads();
        if (kt + 2 < NK) issue((kt + 2) % DNSTAGE, kt + 2);

        const uint32_t sb = s * DSTG;
        #pragma unroll
        for (int kk = 0; kk < 2; kk++) {
            uint32_t af1[2][4], af2[2][4];
            #pragma unroll
            for (int i = 0; i < 2; i++) {
                asm volatile("ldmatrix.sync.aligned.m8n8.x4.shared.b16 {%0,%1,%2,%3}, [%4];"
                             : "=r"(af1[i][0]), "=r"(af1[i][1]), "=r"(af1[i][2]), "=r"(af1[i][3])
                             : "r"(aoff[i] + sb + kk * 32));
                asm volatile("ldmatrix.sync.aligned.m8n8.x4.shared.b16 {%0,%1,%2,%3}, [%4];"
                             : "=r"(af2[i][0]), "=r"(af2[i][1]), "=r"(af2[i][2]), "=r"(af2[i][3])
                             : "r"(aoff[i] + sb + 15360 + kk * 32));
            }
            uint32_t bf1[4][2], bf2[4][2];
            #pragma unroll
            for (int jp = 0; jp < 2; jp++) {
                uint32_t r0, r1, r2, r3;
                asm volatile("ldmatrix.sync.aligned.m8n8.x4.shared.b16 {%0,%1,%2,%3}, [%4];"
                             : "=r"(r0), "=r"(r1), "=r"(r2), "=r"(r3)
                             : "r"(boff[jp] + sb + kk * 32));
                bf1[2*jp][0] = r0; bf1[2*jp+1][0] = r1;
                bf1[2*jp][1] = r2; bf1[2*jp+1][1] = r3;
                asm volatile("ldmatrix.sync.aligned.m8n8.x4.shared.b16 {%0,%1,%2,%3}, [%4];"
                             : "=r"(r0), "=r"(r1), "=r"(r2), "=r"(r3)
                             : "r"(boff[jp] + sb + 15360 + kk * 32));
                bf2[2*jp][0] = r0; bf2[2*jp+1][0] = r1;
                bf2[2*jp][1] = r2; bf2[2*jp+1][1] = r3;
            }
            #pragma unroll
            for (int i = 0; i < 2; i++)
                #pragma unroll
                for (int j = 0; j < 4; j++) {
                    asm volatile("mma.sync.aligned.m16n8k16.row.col.f32.bf16.bf16.f32 "
                                 "{%0,%1,%2,%3}, {%4,%5,%6,%7}, {%8,%9}, {%0,%1,%2,%3};"
                                 : "+f"(acc1[i][j][0]), "+f"(acc1[i][j][1]),
                                   "+f"(acc1[i][j][2]), "+f"(acc1[i][j][3])
                                 : "r"(af1[i][0]), "r"(af1[i][1]), "r"(af1[i][2]), "r"(af1[i][3]),
                                   "r"(bf1[j][0]), "r"(bf1[j][1]));
                    asm volatile("mma.sync.aligned.m16n8k16.row.col.f32.bf16.bf16.f32 "
                                 "{%0,%1,%2,%3}, {%4,%5,%6,%7}, {%8,%9}, {%0,%1,%2,%3};"
                                 : "+f"(acc2[i][j][0]), "+f"(acc2[i][j][1]),
                                   "+f"(acc2[i][j][2]), "+f"(acc2[i][j][3])
                                 : "r"(af2[i][0]), "r"(af2[i][1]), "r"(af2[i][2]), "r"(af2[i][3]),
                                   "r"(bf2[j][0]), "r"(bf2[j][1]));
                }
        }
    }

    const int rbase = m0 + wm * 32 + (lane >> 2);
    const int cbase = n0 + wn * 32 + 2 * (lane & 3);
    #pragma unroll
    for (int i = 0; i < 2; i++) {
        #pragma unroll
        for (int half = 0; half < 2; half++) {
            int m = rbase + i * 16 + half * 8;
            #pragma unroll
            for (int j = 0; j < 4; j++) {
                int n = cbase + j * 8;
                float g0 = frcp_fast(1.f + fexpf_fast(-(acc1[i][j][half*2+0] + b1[n])));
                float g1 = frcp_fast(1.f + fexpf_fast(-(acc1[i][j][half*2+1] + b1[n+1])));
                float f0 = acc2[i][j][half*2+0] + b2[n];
                float f1 = acc2[i][j][half*2+1] + b2[n+1];
                size_t o = (size_t)m * Ncols + n;
                float2 r = *(const float2*)(feats + o);
                *(float2*)(out + o) = make_float2(r.x + g0 * f0, r.y + g1 * f1);
            }
        }
    }
}

// ---------------- flash attention (gathers rows via sidx) ----------------
#define FA_SMEM (20480 * 2 + 32 * 528)
__global__ void __launch_bounds__(256) fattn(const __nv_bfloat16* __restrict__ qkv,
                                             const int* __restrict__ sidx,
                                             __nv_bfloat16* __restrict__ o) {
    extern __shared__ char sm[];
    char* sq = sm;
    char* sk = sm + 20480;
    char* svt = sm + 40960;
    const int p = blockIdx.x, h = blockIdx.y;
    const int tid = threadIdx.x;
    const int lane = tid & 31;
    const int w = tid >> 5;
    const size_t base = (size_t)p * 256;
    const float SC = 0.17677669529663687f * 1.4426950408889634f;

    {
        const size_t src = (size_t)sidx[base + tid] * 768;
        const uint4* qr = (const uint4*)(qkv + src + h * 32);
        const uint4* kr = (const uint4*)(qkv + src + 256 + h * 32);
        const uint4* vr = (const uint4*)(qkv + src + 512 + h * 32);
        uint4* dq = (uint4*)(sq + tid * 80);
        uint4* dk = (uint4*)(sk + tid * 80);
        uint4 v0 = vr[0], v1 = vr[1], v2 = vr[2], v3 = vr[3];
        dq[0] = qr[0]; dq[1] = qr[1]; dq[2] = qr[2]; dq[3] = qr[3];
        dk[0] = kr[0]; dk[1] = kr[1]; dk[2] = kr[2]; dk[3] = kr[3];
        uint32_t vu[8] = {v0.x, v0.y, v0.z, v0.w, v1.x, v1.y, v1.z, v1.w};
        uint32_t vu2[8] = {v2.x, v2.y, v2.z, v2.w, v3.x, v3.y, v3.z, v3.w};
        #pragma unroll
        for (int e = 0; e < 8; e++) {
            ((__nv_bfloat16*)(svt + (2 * e + 0) * 528))[tid] = ((__nv_bfloat162*)&vu[e])->x;
            ((__nv_bfloat16*)(svt + (2 * e + 1) * 528))[tid] = ((__nv_bfloat162*)&vu[e])->y;
        }
        #pragma unroll
        for (int e = 0; e < 8; e++) {
            ((__nv_bfloat16*)(svt + (16 + 2 * e + 0) * 528))[tid] = ((__nv_bfloat162*)&vu2[e])->x;
            ((__nv_bfloat16*)(svt + (16 + 2 * e + 1) * 528))[tid] = ((__nv_bfloat162*)&vu2[e])->y;
        }
    }
    __syncthreads();

    const int m0w = w * 32;
    uint32_t qa[2][2][4];
    #pragma unroll
    for (int i = 0; i < 2; i++)
        #pragma unroll
        for (int kk = 0; kk < 2; kk++) {
            int r = m0w + i * 16 + (lane & 15);
            uint32_t addr = smem_u32(sq + r * 80 + kk * 32 + (lane >> 4) * 16);
            asm volatile("ldmatrix.sync.aligned.m8n8.x4.shared.b16 {%0,%1,%2,%3}, [%4];"
                         : "=r"(qa[i][kk][0]), "=r"(qa[i][kk][1]),
                           "=r"(qa[i][kk][2]), "=r"(qa[i][kk][3])
                         : "r"(addr));
        }

    float oacc[2][4][4];
    #pragma unroll
    for (int i = 0; i < 2; i++)
        #pragma unroll
        for (int d = 0; d < 4; d++)
            #pragma unroll
            for (int q = 0; q < 4; q++) oacc[i][d][q] = 0.f;
    float mrow[2][2] = {{-1e30f, -1e30f}, {-1e30f, -1e30f}};
    float lrow[2][2] = {{0.f, 0.f}, {0.f, 0.f}};

    for (int jc = 0; jc < 8; jc++) {
        uint32_t kb[2][4][2];
        #pragma unroll
        for (int jp = 0; jp < 2; jp++)
            #pragma unroll
            for (int kk = 0; kk < 2; kk++) {
                int r = jc * 32 + jp * 16 + (lane & 15);
                uint32_t addr = smem_u32(sk + r * 80 + kk * 32 + (lane >> 4) * 16);
                uint32_t r0, r1, r2, r3;
                asm volatile("ldmatrix.sync.aligned.m8n8.x4.shared.b16 {%0,%1,%2,%3}, [%4];"
                             : "=r"(r0), "=r"(r1), "=r"(r2), "=r"(r3) : "r"(addr));
                kb[kk][2*jp][0] = r0;   kb[kk][2*jp][1] = r2;
                kb[kk][2*jp+1][0] = r1; kb[kk][2*jp+1][1] = r3;
            }

        float sacc[2][4][4];
        #pragma unroll
        for (int i = 0; i < 2; i++)
            #pragma unroll
            for (int nt = 0; nt < 4; nt++)
                #pragma unroll
                for (int q = 0; q < 4; q++) sacc[i][nt][q] = 0.f;
        #pragma unroll
        for (int kk = 0; kk < 2; kk++)
            #pragma unroll
            for (int i = 0; i < 2; i++)
                #pragma unroll
                for (int nt = 0; nt < 4; nt++) {
                    asm volatile("mma.sync.aligned.m16n8k16.row.col.f32.bf16.bf16.f32 "
                                 "{%0,%1,%2,%3}, {%4,%5,%6,%7}, {%8,%9}, {%0,%1,%2,%3};"
                                 : "+f"(sacc[i][nt][0]), "+f"(sacc[i][nt][1]),
                                   "+f"(sacc[i][nt][2]), "+f"(sacc[i][nt][3])
                                 : "r"(qa[i][kk][0]), "r"(qa[i][kk][1]),
                                   "r"(qa[i][kk][2]), "r"(qa[i][kk][3]),
                                   "r"(kb[kk][nt][0]), "r"(kb[kk][nt][1]));
                }

        #pragma unroll
        for (int i = 0; i < 2; i++)
            #pragma unroll
            for (int nt = 0; nt < 4; nt++)
                #pragma unroll
                for (int q = 0; q < 4; q++) sacc[i][nt][q] *= SC;

        #pragma unroll
        for (int i = 0; i < 2; i++) {
            #pragma unroll
            for (int half = 0; half < 2; half++) {
                float mx = -1e30f;
                #pragma unroll
                for (int nt = 0; nt < 4; nt++) {
                    mx = fmaxf(mx, sacc[i][nt][half*2+0]);
                    mx = fmaxf(mx, sacc[i][nt][half*2+1]);
                }
                mx = fmaxf(mx, __shfl_xor_sync(0xffffffffu, mx, 1));
                mx = fmaxf(mx, __shfl_xor_sync(0xffffffffu, mx, 2));
                float newm = fmaxf(mrow[i][half], mx);
                float alpha = fexp2_fast(mrow[i][half] - newm);
                mrow[i][half] = newm;
                float rs = 0.f;
                #pragma unroll
                for (int nt = 0; nt < 4; nt++) {
                    float p0 = fexp2_fast(sacc[i][nt][half*2+0] - newm);
                    float p1 = fexp2_fast(sacc[i][nt][half*2+1] - newm);
                    sacc[i][nt][half*2+0] = p0;
                    sacc[i][nt][half*2+1] = p1;
                    rs += p0 + p1;
                }
                rs += __shfl_xor_sync(0xffffffffu, rs, 1);
                rs += __shfl_xor_sync(0xffffffffu, rs, 2);
                lrow[i][half] = lrow[i][half] * alpha + rs;
                #pragma unroll
                for (int dt = 0; dt < 4; dt++) {
                    oacc[i][dt][half*2+0] *= alpha;
                    oacc[i][dt][half*2+1] *= alpha;
                }
            }
        }

        uint32_t pa[2][2][4];
        #pragma unroll
        for (int i = 0; i < 2; i++)
            #pragma unroll
            for (int kk = 0; kk < 2; kk++) {
                int ntl = kk * 2, nth = kk * 2 + 1;
                __nv_bfloat162 b0 = __float22bfloat162_rn(make_float2(sacc[i][ntl][0], sacc[i][ntl][1]));
                __nv_bfloat162 b1 = __float22bfloat162_rn(make_float2(sacc[i][ntl][2], sacc[i][ntl][3]));
                __nv_bfloat162 b2 = __float22bfloat162_rn(make_float2(sacc[i][nth][0], sacc[i][nth][1]));
                __nv_bfloat162 b3 = __float22bfloat162_rn(make_float2(sacc[i][nth][2], sacc[i][nth][3]));
                pa[i][kk][0] = *(uint32_t*)&b0;
                pa[i][kk][1] = *(uint32_t*)&b1;
                pa[i][kk][2] = *(uint32_t*)&b2;
                pa[i][kk][3] = *(uint32_t*)&b3;
            }

        uint32_t vb[2][4][2];
        #pragma unroll
        for (int jp = 0; jp < 2; jp++)
            #pragma unroll
            for (int kk = 0; kk < 2; kk++) {
                int r = jp * 16 + (lane & 15);
                uint32_t addr = smem_u32(svt + r * 528 + jc * 64 + kk * 32 + (lane >> 4) * 16);
                uint32_t r0, r1, r2, r3;
                asm volatile("ldmatrix.sync.aligned.m8n8.x4.shared.b16 {%0,%1,%2,%3}, [%4];"
                             : "=r"(r0), "=r"(r1), "=r"(r2), "=r"(r3) : "r"(addr));
                vb[kk][2*jp][0] = r0;   vb[kk][2*jp][1] = r2;
                vb[kk][2*jp+1][0] = r1; vb[kk][2*jp+1][1] = r3;
            }

        #pragma unroll
        for (int kk = 0; kk < 2; kk++)
            #pragma unroll
            for (int i = 0; i < 2; i++)
                #pragma unroll
                for (int dt = 0; dt < 4; dt++) {
                    asm volatile("mma.sync.aligned.m16n8k16.row.col.f32.bf16.bf16.f32 "
                                 "{%0,%1,%2,%3}, {%4,%5,%6,%7}, {%8,%9}, {%0,%1,%2,%3};"
                                 : "+f"(oacc[i][dt][0]), "+f"(oacc[i][dt][1]),
                                   "+f"(oacc[i][dt][2]), "+f"(oacc[i][dt][3])
                                 : "r"(pa[i][kk][0]), "r"(pa[i][kk][1]),
                                   "r"(pa[i][kk][2]), "r"(pa[i][kk][3]),
                                   "r"(vb[kk][dt][0]), "r"(vb[kk][dt][1]));
                }
    }

    #pragma unroll
    for (int i = 0; i < 2; i++)
        #pragma unroll
        for (int half = 0; half < 2; half++) {
            float inv = 1.f / lrow[i][half];
            int row = m0w + i * 16 + half * 8 + (lane >> 2);
            #pragma unroll
            for (int dt = 0; dt < 4; dt++) {
                int col = h * 32 + dt * 8 + 2 * (lane & 3);
                __nv_bfloat162 hv;
                hv.x = __float2bfloat16(oacc[i][dt][half*2+0] * inv);
                hv.y = __float2bfloat16(oacc[i][dt][half*2+1] * inv);
                *(__nv_bfloat162*)(o + (base + row) * 256 + col) = hv;
            }
        }
}

// ---------------- fold gt into per-cloud biases ----------------
__global__ void cloudbias_kernel(const float* __restrict__ gtsum,
                                 const float* __restrict__ gg_w1, const float* __restrict__ gg_b1,
                                 const float* __restrict__ f_w1, const float* __restrict__ f_b1,
                                 float* __restrict__ ggb, float* __restrict__ fb, int Lc) {
    int c = blockIdx.x, j = threadIdx.x;
    float s1 = gg_b1[j], s2 = f_b1[j];
    float invL = 1.f / (float)Lc;
    for (int h = 0; h < 256; h++) {
        float gv = gtsum[c * 256 + h] * invL;
        s1 += gv * gg_w1[(size_t)(256 + h) * 256 + j];
        s2 += gv * f_w1[(size_t)(256 + h) * 256 + j];
    }
    ggb[c * 256 + j] = s1;
    fb[c * 256 + j] = s2;
}

// ---------------- launch ----------------
extern "C" void kernel_launch(void* const* d_in, const int* in_sizes, int n_in,
                              void* d_out, int out_size) {
    const float* feats = (const float*)d_in[0];
    const float* coord = (const float*)d_in[1];
    const float* pe_w1 = (const float*)d_in[3];
    const float* pe_b1 = (const float*)d_in[4];
    const float* pe_w2 = (const float*)d_in[5];
    const float* pe_b2 = (const float*)d_in[6];
    const float* pre_g = (const float*)d_in[7];
    const float* pre_b = (const float*)d_in[8];
    const float* n1_g  = (const float*)d_in[9];
    const float* n1_b  = (const float*)d_in[10];
    const float* wqkv  = (const float*)d_in[11];
    const float* bqkv  = (const float*)d_in[12];
    const float* wo    = (const float*)d_in[13];
    const float* bo    = (const float*)d_in[14];
    const float* n2_g  = (const float*)d_in[15];
    const float* n2_b  = (const float*)d_in[16];
    const float* m_w1  = (const float*)d_in[17];
    const float* m_b1  = (const float*)d_in[18];
    const float* m_w2  = (const float*)d_in[19];
    const float* m_b2  = (const float*)d_in[20];
    const float* gg_w1 = (const float*)d_in[21];
    const float* gg_b1 = (const float*)d_in[22];
    const float* gg_w2 = (const float*)d_in[23];
    const float* gg_b2 = (const float*)d_in[24];
    const float* f_w1  = (const float*)d_in[25];
    const float* f_b1  = (const float*)d_in[26];
    const float* f_w2  = (const float*)d_in[27];
    const float* f_b2  = (const float*)d_in[28];
    float* out = (float*)d_out;

    int N = in_sizes[0] / 256;
    int B = in_sizes[2];
    int Lc = N / B;
    int patches = N / 256;

    float *p_x, *p_xs, *p_key, *p_gt, *p_ggb, *p_fb, *p_stats;
    __nv_bfloat16 *p_ba, *p_bb, *p_fe, *p_wt;
    int* p_idx;
    cudaGetSymbolAddress((void**)&p_x, g_x);
    cudaGetSymbolAddress((void**)&p_xs, g_xs);
    cudaGetSymbolAddress((void**)&p_ba, g_ba);
    cudaGetSymbolAddress((void**)&p_bb, g_bb);
    cudaGetSymbolAddress((void**)&p_fe, g_fe);
    cudaGetSymbolAddress((void**)&p_wt, g_wt);
    cudaGetSymbolAddress((void**)&p_key, g_key);
    cudaGetSymbolAddress((void**)&p_idx, g_idx);
    cudaGetSymbolAddress((void**)&p_gt, g_gt);
    cudaGetSymbolAddress((void**)&p_ggb, g_ggb);
    cudaGetSymbolAddress((void**)&p_fb, g_fb);
    cudaGetSymbolAddress((void**)&p_stats, g_stats);

    __nv_bfloat16* wqkv_t = p_wt + 0;
    __nv_bfloat16* wo_t   = p_wt + 196608;
    __nv_bfloat16* mw1_t  = p_wt + 262144;
    __nv_bfloat16* mw2_t  = p_wt + 393216;
    __nv_bfloat16* ggw1_t = p_wt + 524288;
    __nv_bfloat16* ggw2_t = p_wt + 589824;
    __nv_bfloat16* fw1_t  = p_wt + 655360;
    __nv_bfloat16* fw2_t  = p_wt + 720896;
    __nv_bfloat16* pew2_t = p_wt + 786432;
    __nv_bfloat16* bb_lo = p_bb;
    __nv_bfloat16* bb_hi = p_bb + (size_t)N * 256;
    __nv_bfloat16* p_pe  = p_ba;                      // pe buffer (dead after ln1)
    __nv_bfloat16* p_hid = p_ba + (size_t)N * 512;    // hid buffer (dead after pe gemm)

    static cudaStream_t s2 = nullptr;
    static cudaEvent_t ev1 = nullptr, ev2 = nullptr;
    if (!s2) {
        cudaStreamCreateWithFlags(&s2, cudaStreamNonBlocking);
        cudaEventCreateWithFlags(&ev1, cudaEventDisableTiming);
        cudaEventCreateWithFlags(&ev2, cudaEventDisableTiming);
    }

    cudaFuncSetAttribute(fattn, cudaFuncAttributeMaxDynamicSharedMemorySize, FA_SMEM);
    cudaFuncSetAttribute(gemm_bf16<2>, cudaFuncAttributeMaxDynamicSharedMemorySize, NSTAGE * STG_BYTES);
    cudaFuncSetAttribute(gemm_bf16<8>, cudaFuncAttributeMaxDynamicSharedMemorySize, NSTAGE * STG_BYTES);
    cudaFuncSetAttribute(gemm_bf16<16>, cudaFuncAttributeMaxDynamicSharedMemorySize, NSTAGE * STG_BYTES);
    cudaFuncSetAttribute(gemm_final, cudaFuncAttributeMaxDynamicSharedMemorySize, DNSTAGE * DSTG);

    PrepArgs pa;
    pa.coord = coord; pa.stats = p_stats; pa.Lc = Lc; pa.B = B;
    const float* ws[9] = {wqkv, wo, m_w1, m_w2, gg_w1, gg_w2, f_w1, f_w2, pe_w2};
    __nv_bfloat16* wd[9] = {wqkv_t, wo_t, mw1_t, mw2_t, ggw1_t, ggw2_t, fw1_t, fw2_t, pew2_t};
    int wK[9] = {256, 256, 256, 512, 256, 256, 256, 256, 64};
    int wN[9] = {768, 256, 512, 256, 256, 256, 256, 256, 256};
    int tiles = 0;
    for (int i = 0; i < 9; i++) {
        pa.wsrc[i] = ws[i]; pa.wdst[i] = wd[i];
        pa.wK[i] = wK[i]; pa.wN[i] = wN[i];
        pa.wt0[i] = tiles;
        tiles += (wK[i] / 32) * (wN[i] / 32);
    }
    pa.totalWTiles = tiles;
    pa.gt = p_gt;

    // 1: prep (stats + 9 weight transposes + gt zero)
    prep_kernel<<<B + tiles + 1, 1024>>>(pa);
    // 2: hid + key (warp per point)
    hid_key_kernel<<<N / 8, 256>>>(coord, pe_w1, pe_b1, p_stats, p_hid, p_key, p_idx, Lc);
    // fork: sort chain on s2 (key ready), PE-GEMM + LN1 + qkv on main
    cudaEventRecord(ev1, 0);
    cudaStreamWaitEvent(s2, ev1, 0);
    sort_local<<<N / CHUNK, 1024, CHUNK * 8, s2>>>(p_key, p_idx, Lc);
    // main: pe = hid @ pe_w2^T + pe_b2 -> bf16
    gemm_bf16<2><<<dim3(256/GBN, N/GBM), 256, NSTAGE*STG_BYTES>>>(
        p_hid, pew2_t, pe_b2, nullptr, nullptr, p_pe, N, 256, 0, 0, 1,
        nullptr, nullptr, 0, nullptr, nullptr, nullptr, nullptr);
    // main: LN1 chain (warp per point)
    ln1_kernel<<<N / 8, 256>>>(feats, p_pe, pre_g, pre_b, n1_g, n1_b, p_x, p_bb, p_fe);
    // main: qkv GEMM -> ba
    gemm_bf16<8><<<dim3(768/GBN, N/GBM), 256, NSTAGE*STG_BYTES>>>(
        p_bb, wqkv_t, bqkv, nullptr, nullptr, p_ba, N, 768, 0, 0, 1,
        nullptr, nullptr, 0, nullptr, nullptr, nullptr, nullptr);
    // (s2): finish the sort
    for (int k = CHUNK * 2; k <= Lc; k <<= 1) {
        for (int j = k >> 1; j >= CHUNK; j >>= 1)
            sort_global<<<dim3(Lc / 512, B), 256, 0, s2>>>(p_key, p_idx, k, j, Lc);
        merge_local<<<N / CHUNK, 1024, CHUNK * 8, s2>>>(p_key, p_idx, k, Lc);
    }
    cudaEventRecord(ev2, s2);
    cudaStreamWaitEvent(0, ev2, 0);
    // flash attention (gather via idx) -> bb
    fattn<<<dim3(patches, 8), 256, FA_SMEM>>>(p_ba, p_idx, p_bb);
    // wo GEMM + gathered residual -> xs fp32
    gemm_bf16<8><<<dim3(256/GBN, N/GBM), 256, NSTAGE*STG_BYTES>>>(
        p_bb, wo_t, bo, p_x, nullptr, p_xs, N, 256, 0, 4, 0,
        p_idx, nullptr, 0, nullptr, nullptr, nullptr, nullptr);
    // LN2 -> ba bf16 (warp per row)
    ln_bf<<<N / 8, 256>>>(p_xs, n2_g, n2_b, p_ba);
    // MLP1 + gelu -> bb
    gemm_bf16<8><<<dim3(512/GBN, N/GBM), 256, NSTAGE*STG_BYTES>>>(
        p_ba, mw1_t, m_b1, nullptr, nullptr, p_bb, N, 512, 0, 2, 1,
        nullptr, nullptr, 0, nullptr, nullptr, nullptr, nullptr);
    // MLP2 + resid; scatter xo -> ba; gt atomics
    gemm_bf16<16><<<dim3(256/GBN, N/GBM), 256, NSTAGE*STG_BYTES>>>(
        p_bb, mw2_t, m_b2, p_xs, nullptr, p_ba, N, 256, 0, 6, 1,
        p_idx, p_gt, Lc, nullptr, nullptr, nullptr, nullptr);
    // per-cloud biases
    cloudbias_kernel<<<B, 256>>>(p_gt, gg_w1, gg_b1, f_w1, f_b1, p_ggb, p_fb, Lc);
    // batched hidden GEMMs (z=0 gate-hidden, z=1 fuse-hidden)
    gemm_bf16<8><<<dim3(256/GBN, N/GBM, 2), 256, NSTAGE*STG_BYTES>>>(
        p_fe, ggw1_t, p_ggb, nullptr, nullptr, bb_lo, N, 256, Lc, 1, 1,
        nullptr, nullptr, 0, p_ba, fw1_t, p_fb, bb_hi);
    // fused final: out = feats + sigmoid(bb_lo@gg_w2+gg_b2) * (bb_hi@f_w2+f_b2)
    gemm_final<<<dim3(256/64, N/128), 256, DNSTAGE*DSTG>>>(
        bb_lo, ggw2_t, gg_b2, bb_hi, fw2_t, f_b2, feats, out, 256);
}

// round 16
// speedup vs baseline: 1.4174x; 1.0347x over previous
#include <cuda_runtime.h>
#include <cuda_bf16.h>
#include <math.h>
#include <stdint.h>

// ---------------- static scratch ----------------
#define MAXN 131072
#define DD 256
__device__ __nv_bfloat16 g_x  [(size_t)MAXN * DD];   // preLN out (orig order, resid1)
__device__ __nv_bfloat16 g_xs [(size_t)MAXN * DD];   // serialized residual stream
__device__ __nv_bfloat16 g_ba[(size_t)MAXN * 768];
__device__ __nv_bfloat16 g_bb[(size_t)MAXN * 512];
__device__ __nv_bfloat16 g_fe[(size_t)MAXN * 256];
__device__ __nv_bfloat16 g_wt[802816];
__device__ float g_key[MAXN];
__device__ int   g_idx[MAXN];
__device__ float g_gt [8 * DD];
__device__ float g_ggb[8 * DD];
__device__ float g_fb [8 * DD];
__device__ float g_stats[8 * 12];

// ---------------- fast math ----------------
__device__ __forceinline__ float fexp2_fast(float z) {
    z = fmaxf(z, -80.f);
    float n = rintf(z);
    float f = z - n;
    float p = 0.009618129f;
    p = p * f + 0.055504109f;
    p = p * f + 0.240226507f;
    p = p * f + 0.693147181f;
    p = p * f + 1.0f;
    return p * __int_as_float(((int)n + 127) << 23);
}
__device__ __forceinline__ float fexpf_fast(float x) {
    return fexp2_fast(x * 1.4426950408889634f);
}
__device__ __forceinline__ float frcp_fast(float d) {
    float y = __int_as_float(0x7ef311c3 - __float_as_int(d));
    y = y * (2.f - d * y);
    y = y * (2.f - d * y);
    y = y * (2.f - d * y);
    return y;
}
__device__ __forceinline__ uint32_t smem_u32(const void* p) {
    return (uint32_t)__cvta_generic_to_shared(p);
}
__device__ __forceinline__ float2 warpsum2(float a, float b) {
    #pragma unroll
    for (int off = 16; off; off >>= 1) {
        a += __shfl_xor_sync(0xffffffffu, a, off);
        b += __shfl_xor_sync(0xffffffffu, b, off);
    }
    return make_float2(a, b);
}

// ---------------- prep ----------------
struct PrepArgs {
    const float* coord; float* stats; int Lc; int B;
    const float* wsrc[9]; __nv_bfloat16* wdst[9];
    int wK[9], wN[9], wt0[9];
    int totalWTiles;
    float* gt;
};
__global__ void __launch_bounds__(1024) prep_kernel(PrepArgs a) {
    __shared__ float red[1024];
    __shared__ float tt[32][33];
    int b = blockIdx.x, tid = threadIdx.x;
    if (b < a.B) {
        int c = b, Lc = a.Lc;
        float sum[3] = {0,0,0}, mn[3] = {1e30f,1e30f,1e30f}, mx[3] = {-1e30f,-1e30f,-1e30f};
        for (int i = tid; i < Lc; i += 1024) {
            const float* cp = a.coord + (size_t)(c * Lc + i) * 3;
            #pragma unroll
            for (int d = 0; d < 3; d++) {
                float v = cp[d];
                sum[d] += v; mn[d] = fminf(mn[d], v); mx[d] = fmaxf(mx[d], v);
            }
        }
        for (int d = 0; d < 3; d++) {
            red[tid] = sum[d]; __syncthreads();
            for (int s = 512; s > 0; s >>= 1) { if (tid < s) red[tid] += red[tid + s]; __syncthreads(); }
            float tot = red[0]; __syncthreads();
            red[tid] = mn[d]; __syncthreads();
            for (int s = 512; s > 0; s >>= 1) { if (tid < s) red[tid] = fminf(red[tid], red[tid + s]); __syncthreads(); }
            float tmn = red[0]; __syncthreads();
            red[tid] = mx[d]; __syncthreads();
            for (int s = 512; s > 0; s >>= 1) { if (tid < s) red[tid] = fmaxf(red[tid], red[tid + s]); __syncthreads(); }
            float tmx = red[0]; __syncthreads();
            if (tid == 0) {
                float mean = tot / (float)Lc;
                a.stats[c*12 + d]     = mean;
                a.stats[c*12 + 3 + d] = fmaxf(fmaxf(tmx - mean, mean - tmn), 1e-6f);
                a.stats[c*12 + 6 + d] = tmn;
                a.stats[c*12 + 9 + d] = 1.f / fmaxf(tmx - tmn, 1e-6f);
            }
            __syncthreads();
        }
    } else if (b < a.B + a.totalWTiles) {
        int t = b - a.B;
        int w = 0;
        #pragma unroll
        for (int q = 1; q < 9; q++) if (t >= a.wt0[q]) w = q;
        int lt = t - a.wt0[w];
        int tilesX = a.wN[w] >> 5;
        int bx = (lt % tilesX) << 5, by = (lt / tilesX) << 5;
        const float* src = a.wsrc[w];
        __nv_bfloat16* dst = a.wdst[w];
        int K = a.wK[w], Ncols = a.wN[w];
        int tx = tid & 31, ty = tid >> 5;
        tt[ty][tx] = src[(size_t)(by + ty) * Ncols + bx + tx];
        __syncthreads();
        dst[(size_t)(bx + ty) * K + by + tx] = __float2bfloat16(tt[tx][ty]);
    } else {
        a.gt[tid] = 0.f;
        a.gt[tid + 1024] = 0.f;
    }
}

// ---------------- hid + key (warp per point) ----------------
__global__ void __launch_bounds__(256) hid_key_kernel(
    const float* __restrict__ coord,
    const float* __restrict__ w1, const float* __restrict__ b1,
    const float* __restrict__ stats,
    __nv_bfloat16* __restrict__ hidout,
    float* __restrict__ key, int* __restrict__ idx, int Lc)
{
    int warp = threadIdx.x >> 5, lane = threadIdx.x & 31;
    int i = blockIdx.x * 8 + warp;
    int c = i / Lc;
    const float* st = stats + c * 12;
    float c0 = coord[(size_t)i*3+0], c1 = coord[(size_t)i*3+1], c2 = coord[(size_t)i*3+2];
    float n0 = (c0 - st[0]) / st[3];
    float n1 = (c1 - st[1]) / st[4];
    float n2 = (c2 - st[2]) / st[5];
    float hA = fmaxf(b1[lane]      + n0 * w1[lane]      + n1 * w1[64 + lane]  + n2 * w1[128 + lane], 0.f);
    float hB = fmaxf(b1[lane + 32] + n0 * w1[lane + 32] + n1 * w1[96 + lane]  + n2 * w1[160 + lane], 0.f);
    hidout[(size_t)i * 64 + lane]      = __float2bfloat16(hA);
    hidout[(size_t)i * 64 + 32 + lane] = __float2bfloat16(hB);
    if (lane == 0) {
        float k0 = (c0 - st[6]) * st[9];
        float k1 = (c1 - st[7]) * st[10];
        float k2 = (c2 - st[8]) * st[11];
        key[i] = k0 + 2.17f * k1 + 3.31f * k2;
        idx[i] = i;
    }
}

// ---------------- LN1 chain (warp per point): v=feats+pe; preLN -> xout(bf16); LN1 -> hbf; febf ----------------
__global__ void __launch_bounds__(256) ln1_kernel(
    const float* __restrict__ feats, const __nv_bfloat16* __restrict__ pe,
    const float* __restrict__ g, const float* __restrict__ beta,
    const float* __restrict__ n1g, const float* __restrict__ n1b,
    __nv_bfloat16* __restrict__ xout, __nv_bfloat16* __restrict__ hbf,
    __nv_bfloat16* __restrict__ febf)
{
    int warp = threadIdx.x >> 5, lane = threadIdx.x & 31;
    size_t i = (size_t)blockIdx.x * 8 + warp;
    const int c0 = lane * 8;
    const float* fr = feats + i * 256 + c0;
    float4 fa = *(const float4*)fr;
    float4 fb = *(const float4*)(fr + 4);
    float f[8] = {fa.x, fa.y, fa.z, fa.w, fb.x, fb.y, fb.z, fb.w};
    uint4 pu = *(const uint4*)(pe + i * 256 + c0);
    const __nv_bfloat162* pp = (const __nv_bfloat162*)&pu;
    float v[8];
    #pragma unroll
    for (int e = 0; e < 4; e++) {
        float2 p2 = __bfloat1622float2(pp[e]);
        v[e*2+0] = f[e*2+0] + p2.x;
        v[e*2+1] = f[e*2+1] + p2.y;
    }
    {
        uint4 pk; uint32_t* pw = (uint32_t*)&pk;
        #pragma unroll
        for (int e = 0; e < 4; e++) {
            __nv_bfloat162 h;
            h.x = __float2bfloat16(f[e*2+0]); h.y = __float2bfloat16(f[e*2+1]);
            pw[e] = *(uint32_t*)&h;
        }
        *(uint4*)(febf + i * 256 + c0) = pk;
    }
    float s1 = 0.f, s2 = 0.f;
    #pragma unroll
    for (int e = 0; e < 8; e++) { s1 += v[e]; s2 += v[e] * v[e]; }
    float2 ss = warpsum2(s1, s2);
    float mean = ss.x * (1.f / 256.f);
    float var = ss.y * (1.f / 256.f) - mean * mean;
    float rs = rsqrtf(var + 1e-5f);
    float xv[8];
    float t1 = 0.f, t2 = 0.f;
    #pragma unroll
    for (int e = 0; e < 8; e++) {
        xv[e] = (v[e] - mean) * rs * g[c0 + e] + beta[c0 + e];
        t1 += xv[e]; t2 += xv[e] * xv[e];
    }
    {
        uint4 pk; uint32_t* pw = (uint32_t*)&pk;
        #pragma unroll
        for (int e = 0; e < 4; e++) {
            __nv_bfloat162 h;
            h.x = __float2bfloat16(xv[e*2+0]); h.y = __float2bfloat16(xv[e*2+1]);
            pw[e] = *(uint32_t*)&h;
        }
        *(uint4*)(xout + i * 256 + c0) = pk;
    }
    float2 tt = warpsum2(t1, t2);
    float m2 = tt.x * (1.f / 256.f);
    float v2 = tt.y * (1.f / 256.f) - m2 * m2;
    float rs2 = rsqrtf(v2 + 1e-5f);
    uint4 pk; uint32_t* pw = (uint32_t*)&pk;
    #pragma unroll
    for (int e = 0; e < 4; e++) {
        __nv_bfloat162 h;
        h.x = __float2bfloat16((xv[e*2+0] - m2) * rs2 * n1g[c0 + e*2+0] + n1b[c0 + e*2+0]);
        h.y = __float2bfloat16((xv[e*2+1] - m2) * rs2 * n1g[c0 + e*2+1] + n1b[c0 + e*2+1]);
        pw[e] = *(uint32_t*)&h;
    }
    *(uint4*)(hbf + i * 256 + c0) = pk;
}

// ---------------- hierarchical bitonic sort (CHUNK=4096) ----------------
#define CHUNK 4096
__global__ void __launch_bounds__(1024) sort_local(float* __restrict__ key, int* __restrict__ idx, int Lc) {
    extern __shared__ char smraw[];
    float* sk = (float*)smraw;
    int*   si = (int*)(smraw + CHUNK * 4);
    size_t gbase = (size_t)blockIdx.x * CHUNK;
    int lbase = (int)(gbase % (size_t)Lc);
    for (int t = threadIdx.x; t < CHUNK; t += 1024) { sk[t] = key[gbase + t]; si[t] = idx[gbase + t]; }
    __syncthreads();
    for (int k = 2; k <= CHUNK; k <<= 1) {
        for (int j = k >> 1; j > 0; j >>= 1) {
            #pragma unroll
            for (int it = 0; it < CHUNK / 2048; it++) {
                int t = threadIdx.x + it * 1024;
                int i = 2 * t - (t & (j - 1));
                int p = i + j;
                bool up = (((lbase + i) & k) == 0);
                float a = sk[i], b = sk[p];
                int ia = si[i], ib = si[p];
                bool sw = up ? (a > b || (a == b && ia > ib)) : (a < b || (a == b && ia < ib));
                if (sw) { sk[i] = b; sk[p] = a; si[i] = ib; si[p] = ia; }
            }
            __syncthreads();
        }
    }
    for (int t = threadIdx.x; t < CHUNK; t += 1024) { key[gbase + t] = sk[t]; idx[gbase + t] = si[t]; }
}

__global__ void __launch_bounds__(1024) merge_local(float* __restrict__ key, int* __restrict__ idx, int k, int Lc) {
    extern __shared__ char smraw[];
    float* sk = (float*)smraw;
    int*   si = (int*)(smraw + CHUNK * 4);
    size_t gbase = (size_t)blockIdx.x * CHUNK;
    int lbase = (int)(gbase % (size_t)Lc);
    for (int t = threadIdx.x; t < CHUNK; t += 1024) { sk[t] = key[gbase + t]; si[t] = idx[gbase + t]; }
    __syncthreads();
    for (int j = CHUNK / 2; j > 0; j >>= 1) {
        #pragma unroll
        for (int it = 0; it < CHUNK / 2048; it++) {
            int t = threadIdx.x + it * 1024;
            int i = 2 * t - (t & (j - 1));
            int p = i + j;
            bool up = (((lbase + i) & k) == 0);
            float a = sk[i], b = sk[p];
            int ia = si[i], ib = si[p];
            bool sw = up ? (a > b || (a == b && ia > ib)) : (a < b || (a == b && ia < ib));
            if (sw) { sk[i] = b; sk[p] = a; si[i] = ib; si[p] = ia; }
        }
        __syncthreads();
    }
    for (int t = threadIdx.x; t < CHUNK; t += 1024) { key[gbase + t] = sk[t]; idx[gbase + t] = si[t]; }
}

__global__ void __launch_bounds__(256) sort_global(float* __restrict__ key, int* __restrict__ idx, int k, int j, int Lc) {
    int c = blockIdx.y;
    size_t base = (size_t)c * Lc;
    int t = blockIdx.x * 256 + threadIdx.x;
    int i = 2 * t - (t & (j - 1));
    int p = i + j;
    bool up = ((i & k) == 0);
    float a = key[base + i], b = key[base + p];
    int ia = idx[base + i], ib = idx[base + p];
    bool sw = up ? (a > b || (a == b && ia > ib)) : (a < b || (a == b && ia < ib));
    if (sw) {
        key[base + i] = b; key[base + p] = a;
        idx[base + i] = ib; idx[base + p] = ia;
    }
}

// ---------------- LN2 -> bf16 (warp per row, bf16 input) ----------------
__global__ void __launch_bounds__(256) ln_bf(const __nv_bfloat16* __restrict__ x, const float* __restrict__ g,
                                             const float* __restrict__ b, __nv_bfloat16* __restrict__ y) {
    int warp = threadIdx.x >> 5, lane = threadIdx.x & 31;
    size_t row = (size_t)blockIdx.x * 8 + warp;
    const int c0 = lane * 8;
    uint4 xu = *(const uint4*)(x + row * 256 + c0);
    const __nv_bfloat162* xp = (const __nv_bfloat162*)&xu;
    float v[8];
    #pragma unroll
    for (int e = 0; e < 4; e++) {
        float2 x2 = __bfloat1622float2(xp[e]);
        v[e*2+0] = x2.x; v[e*2+1] = x2.y;
    }
    float s1 = 0.f, s2 = 0.f;
    #pragma unroll
    for (int e = 0; e < 8; e++) { s1 += v[e]; s2 += v[e] * v[e]; }
    float2 ss = warpsum2(s1, s2);
    float mean = ss.x * (1.f / 256.f);
    float var = ss.y * (1.f / 256.f) - mean * mean;
    float rs = rsqrtf(var + 1e-5f);
    uint4 pk; uint32_t* pw = (uint32_t*)&pk;
    #pragma unroll
    for (int e = 0; e < 4; e++) {
        __nv_bfloat162 h;
        h.x = __float2bfloat16((v[e*2+0] - mean) * rs * g[c0 + e*2+0] + b[c0 + e*2+0]);
        h.y = __float2bfloat16((v[e*2+1] - mean) * rs * g[c0 + e*2+1] + b[c0 + e*2+1]);
        pw[e] = *(uint32_t*)&h;
    }
    *(uint4*)(y + row * 256 + c0) = pk;
}

// ---------------- tensor-core GEMM: 128x64 tile, warp tile 32x32, 3 CTAs/SM ----------------
// epi: 0 none, 1 relu, 2 gelu, 3 sigmoid, 4 +resid_bf16[ridx], 5 unused,
//      6 +resid_bf16[m]; bf16 scatter to Cout[ridx[m]]; atomic gt column sums
#define GBM 128
#define GBN 64
#define GKT 32
#define STG_BYTES 15360
#define NSTAGE 4

template<int NK>
__global__ void __launch_bounds__(256, 3) gemm_bf16(
    const __nv_bfloat16* __restrict__ A_, const __nv_bfloat16* __restrict__ Bt_,
    const float* __restrict__ bias_,
    const __nv_bfloat16* __restrict__ resid, const float* __restrict__ gate,
    void* __restrict__ Cout_,
    int M, int Ncols, int cloudLen, int epi, int outBf16,
    const int* __restrict__ ridx, float* __restrict__ gtp, int gtLc,
    const __nv_bfloat16* A2, const __nv_bfloat16* Bt2, const float* bias2, void* Cout2)
{
    constexpr int K = NK * GKT;
    extern __shared__ char smraw[];
    const __nv_bfloat16* A = A_;
    const __nv_bfloat16* Bt = Bt_;
    const float* bias = bias_;
    void* Cout = Cout_;
    if (blockIdx.z == 1) { A = A2; Bt = Bt2; bias = bias2; Cout = Cout2; }
    const int tid = threadIdx.x;
    const int lane = tid & 31;
    const int warp = tid >> 5;
    const int wm = warp >> 1, wn = warp & 1;
    const int m0 = blockIdx.y * GBM, n0 = blockIdx.x * GBN;

    float acc[2][4][4];
    #pragma unroll
    for (int i = 0; i < 2; i++)
        #pragma unroll
        for (int j = 0; j < 4; j++)
            #pragma unroll
            for (int q = 0; q < 4; q++) acc[i][j][q] = 0.f;

    const int arow0 = tid >> 2, ac0 = tid & 3;
    const int arow1 = (tid + 256) >> 2;
    const __nv_bfloat16* gA0 = A + (size_t)(m0 + arow0) * K + ac0 * 8;
    const __nv_bfloat16* gA1 = A + (size_t)(m0 + arow1) * K + ac0 * 8;
    const __nv_bfloat16* gB0 = Bt + (size_t)(n0 + arow0) * K + ac0 * 8;
    const uint32_t smemBase = smem_u32(smraw);
    const uint32_t dA0 = smemBase + arow0 * 80 + ac0 * 16;
    const uint32_t dA1 = smemBase + arow1 * 80 + ac0 * 16;
    const uint32_t dB0 = smemBase + 10240 + arow0 * 80 + ac0 * 16;

    uint32_t aoff[2], boff[2];
    #pragma unroll
    for (int i = 0; i < 2; i++)
        aoff[i] = smemBase + (wm * 32 + i * 16 + (lane & 15)) * 80 + (lane >> 4) * 16;
    #pragma unroll
    for (int jp = 0; jp < 2; jp++)
        boff[jp] = smemBase + 10240 + (wn * 32 + jp * 16 + (lane & 15)) * 80 + (lane >> 4) * 16;

    auto issue = [&](int s, int kt) {
        uint32_t sb = s * STG_BYTES;
        int go = kt * GKT;
        asm volatile("cp.async.cg.shared.global [%0], [%1], 16;\n" :: "r"(dA0 + sb), "l"(gA0 + go));
        asm volatile("cp.async.cg.shared.global [%0], [%1], 16;\n" :: "r"(dA1 + sb), "l"(gA1 + go));
        asm volatile("cp.async.cg.shared.global [%0], [%1], 16;\n" :: "r"(dB0 + sb), "l"(gB0 + go));
        asm volatile("cp.async.commit_group;\n");
    };

    issue(0, 0);
    issue(1, 1);
    #pragma unroll
    for (int kt = 0; kt < NK; kt++) {
        const int s = kt & (NSTAGE - 1);
        if (kt + 2 < NK) {
            issue((kt + 2) & (NSTAGE - 1), kt + 2);
            asm volatile("cp.async.wait_group 2;\n");
        } else if (kt + 1 < NK) {
            asm volatile("cp.async.wait_group 1;\n");
        } else {
            asm volatile("cp.async.wait_group 0;\n");
        }
        __syncthreads();

        const uint32_t sb = s * STG_BYTES;
        #pragma unroll
        for (int kk = 0; kk < 2; kk++) {
            uint32_t af[2][4];
            #pragma unroll
            for (int i = 0; i < 2; i++) {
                asm volatile("ldmatrix.sync.aligned.m8n8.x4.shared.b16 {%0,%1,%2,%3}, [%4];"
                             : "=r"(af[i][0]), "=r"(af[i][1]), "=r"(af[i][2]), "=r"(af[i][3])
                             : "r"(aoff[i] + sb + kk * 32));
            }
            uint32_t bf[4][2];
            #pragma unroll
            for (int jp = 0; jp < 2; jp++) {
                uint32_t r0, r1, r2, r3;
                asm volatile("ldmatrix.sync.aligned.m8n8.x4.shared.b16 {%0,%1,%2,%3}, [%4];"
                             : "=r"(r0), "=r"(r1), "=r"(r2), "=r"(r3)
                             : "r"(boff[jp] + sb + kk * 32));
                bf[2*jp][0] = r0; bf[2*jp+1][0] = r1;
                bf[2*jp][1] = r2; bf[2*jp+1][1] = r3;
            }
            #pragma unroll
            for (int i = 0; i < 2; i++)
                #pragma unroll
                for (int j = 0; j < 4; j++) {
                    asm volatile("mma.sync.aligned.m16n8k16.row.col.f32.bf16.bf16.f32 "
                                 "{%0,%1,%2,%3}, {%4,%5,%6,%7}, {%8,%9}, {%0,%1,%2,%3};"
                                 : "+f"(acc[i][j][0]), "+f"(acc[i][j][1]),
                                   "+f"(acc[i][j][2]), "+f"(acc[i][j][3])
                                 : "r"(af[i][0]), "r"(af[i][1]), "r"(af[i][2]), "r"(af[i][3]),
                                   "r"(bf[j][0]), "r"(bf[j][1]));
                }
        }
    }

    const int rbase = m0 + wm * 32 + (lane >> 2);
    const int cbase = n0 + wn * 32 + 2 * (lane & 3);
    float gta[4][2];
    #pragma unroll
    for (int j = 0; j < 4; j++) { gta[j][0] = 0.f; gta[j][1] = 0.f; }

    #pragma unroll
    for (int i = 0; i < 2; i++) {
        #pragma unroll
        for (int half = 0; half < 2; half++) {
            int m = rbase + i * 16 + half * 8;
            const float* bp = (cloudLen > 0) ? (bias + (size_t)(m / cloudLen) * Ncols) : bias;
            #pragma unroll
            for (int j = 0; j < 4; j++) {
                int n = cbase + j * 8;
                float v0 = acc[i][j][half * 2 + 0] + bp[n];
                float v1 = acc[i][j][half * 2 + 1] + bp[n + 1];
                size_t o = (size_t)m * Ncols + n;
                bool stored = false;
                switch (epi) {
                    case 1: v0 = fmaxf(v0, 0.f); v1 = fmaxf(v1, 0.f); break;
                    case 2:
                        v0 = 0.5f * v0 * (1.f + erff(v0 * 0.70710678118f));
                        v1 = 0.5f * v1 * (1.f + erff(v1 * 0.70710678118f));
                        break;
                    case 3:
                        v0 = frcp_fast(1.f + fexpf_fast(-v0));
                        v1 = frcp_fast(1.f + fexpf_fast(-v1));
                        break;
                    case 4: {
                        size_t ro = (size_t)(ridx ? ridx[m] : m) * Ncols + n;
                        __nv_bfloat162 r2 = *(const __nv_bfloat162*)(resid + ro);
                        float2 r = __bfloat1622float2(r2);
                        v0 += r.x; v1 += r.y;
                    } break;
                    case 6: {
                        __nv_bfloat162 r2 = *(const __nv_bfloat162*)(resid + o);
                        float2 r = __bfloat1622float2(r2);
                        v0 += r.x; v1 += r.y;
                        gta[j][0] += v0; gta[j][1] += v1;
                        size_t od = (size_t)ridx[m] * Ncols + n;
                        __nv_bfloat162 h;
                        h.x = __float2bfloat16(v0); h.y = __float2bfloat16(v1);
                        *(__nv_bfloat162*)((__nv_bfloat16*)Cout + od) = h;
                        stored = true;
                    } break;
                    default: break;
                }
                if (!stored) {
                    if (outBf16) {
                        __nv_bfloat162 h;
                        h.x = __float2bfloat16(v0); h.y = __float2bfloat16(v1);
                        *(__nv_bfloat162*)((__nv_bfloat16*)Cout + o) = h;
                    } else {
                        *(float2*)((float*)Cout + o) = make_float2(v0, v1);
                    }
                }
            }
        }
    }
    if (epi == 6) {
        int c = m0 / gtLc;
        #pragma unroll
        for (int j = 0; j < 4; j++) {
            float s0 = gta[j][0], s1 = gta[j][1];
            #pragma unroll
            for (int off = 4; off <= 16; off <<= 1) {
                s0 += __shfl_xor_sync(0xffffffffu, s0, off);
                s1 += __shfl_xor_sync(0xffffffffu, s1, off);
            }
            if ((lane >> 2) == 0) {
                int n = cbase + j * 8;
                atomicAdd(gtp + c * 256 + n, s0);
                atomicAdd(gtp + c * 256 + n + 1, s1);
            }
        }
    }
}

// ---------------- dual GEMM final: out = feats + sigmoid(A1@W1+b1) * (A2@W2+b2) ----------------
#define DSTG 30720
#define DNSTAGE 3
__global__ void __launch_bounds__(256, 2) gemm_final(
    const __nv_bfloat16* __restrict__ A1, const __nv_bfloat16* __restrict__ W1,
    const float* __restrict__ b1,
    const __nv_bfloat16* __restrict__ A2, const __nv_bfloat16* __restrict__ W2,
    const float* __restrict__ b2,
    const float* __restrict__ feats, float* __restrict__ out, int Ncols)
{
    constexpr int NK = 8;
    extern __shared__ char smraw[];
    const int tid = threadIdx.x;
    const int lane = tid & 31;
    const int warp = tid >> 5;
    const int wm = warp >> 1, wn = warp & 1;
    const int m0 = blockIdx.y * 128, n0 = blockIdx.x * 64;

    float acc1[2][4][4], acc2[2][4][4];
    #pragma unroll
    for (int i = 0; i < 2; i++)
        #pragma unroll
        for (int j = 0; j < 4; j++)
            #pragma unroll
            for (int q = 0; q < 4; q++) { acc1[i][j][q] = 0.f; acc2[i][j][q] = 0.f; }

    const int arow0 = tid >> 2, ac0 = tid & 3;
    const int arow1 = (tid + 256) >> 2;
    const __nv_bfloat16* gA1_0 = A1 + (size_t)(m0 + arow0) * 256 + ac0 * 8;
    const __nv_bfloat16* gA1_1 = A1 + (size_t)(m0 + arow1) * 256 + ac0 * 8;
    const __nv_bfloat16* gA2_0 = A2 + (size_t)(m0 + arow0) * 256 + ac0 * 8;
    const __nv_bfloat16* gA2_1 = A2 + (size_t)(m0 + arow1) * 256 + ac0 * 8;
    const __nv_bfloat16* gB1_0 = W1 + (size_t)(n0 + arow0) * 256 + ac0 * 8;
    const __nv_bfloat16* gB2_0 = W2 + (size_t)(n0 + arow0) * 256 + ac0 * 8;
    const uint32_t smemBase = smem_u32(smraw);
    const uint32_t dA1_0 = smemBase + arow0 * 80 + ac0 * 16;
    const uint32_t dA1_1 = smemBase + arow1 * 80 + ac0 * 16;
    const uint32_t dB1_0 = smemBase + 10240 + arow0 * 80 + ac0 * 16;
    const uint32_t dA2_0 = smemBase + 15360 + arow0 * 80 + ac0 * 16;
    const uint32_t dA2_1 = smemBase + 15360 + arow1 * 80 + ac0 * 16;
    const uint32_t dB2_0 = smemBase + 25600 + arow0 * 80 + ac0 * 16;

    uint32_t aoff[2], boff[2];
    #pragma unroll
    for (int i = 0; i < 2; i++)
        aoff[i] = smemBase + (wm * 32 + i * 16 + (lane & 15)) * 80 + (lane >> 4) * 16;
    #pragma unroll
    for (int jp = 0; jp < 2; jp++)
        boff[jp] = smemBase + 10240 + (wn * 32 + jp * 16 + (lane & 15)) * 80 + (lane >> 4) * 16;

    auto issue = [&](int s, int kt) {
        uint32_t sb = s * DSTG;
        int go = kt * 32;
        asm volatile("cp.async.cg.shared.global [%0], [%1], 16;\n" :: "r"(dA1_0 + sb), "l"(gA1_0 + go));
        asm volatile("cp.async.cg.shared.global [%0], [%1], 16;\n" :: "r"(dA1_1 + sb), "l"(gA1_1 + go));
        asm volatile("cp.async.cg.shared.global [%0], [%1], 16;\n" :: "r"(dB1_0 + sb), "l"(gB1_0 + go));
        asm volatile("cp.async.cg.shared.global [%0], [%1], 16;\n" :: "r"(dA2_0 + sb), "l"(gA2_0 + go));
        asm volatile("cp.async.cg.shared.global [%0], [%1], 16;\n" :: "r"(dA2_1 + sb), "l"(gA2_1 + go));
        asm volatile("cp.async.cg.shared.global [%0], [%1], 16;\n" :: "r"(dB2_0 + sb), "l"(gB2_0 + go));
        asm volatile("cp.async.commit_group;\n");
    };

    issue(0, 0);
    issue(1, 1);
    #pragma unroll
    for (int kt = 0; kt < NK; kt++) {
        const int s = kt % DNSTAGE;
        if (kt + 1 < NK) {
            asm volatile("cp.async.wait_group 1;\n");
        } else {
            asm volatile("cp.async.wait_group 0;\n");
        }
        __syncthreads();
        if (kt + 2 < NK) issue((kt + 2) % DNSTAGE, kt + 2);

        const uint32_t sb = s * DSTG;
        #pragma unroll
        for (int kk = 0; kk < 2; kk++) {
            uint32_t af1[2][4], af2[2][4];
            #pragma unroll
            for (int i = 0; i < 2; i++) {
                asm volatile("ldmatrix.sync.aligned.m8n8.x4.shared.b16 {%0,%1,%2,%3}, [%4];"
                             : "=r"(af1[i][0]), "=r"(af1[i][1]), "=r"(af1[i][2]), "=r"(af1[i][3])
                             : "r"(aoff[i] + sb + kk * 32));
                asm volatile("ldmatrix.sync.aligned.m8n8.x4.shared.b16 {%0,%1,%2,%3}, [%4];"
                             : "=r"(af2[i][0]), "=r"(af2[i][1]), "=r"(af2[i][2]), "=r"(af2[i][3])
                             : "r"(aoff[i] + sb + 15360 + kk * 32));
            }
            uint32_t bf1[4][2], bf2[4][2];
            #pragma unroll
            for (int jp = 0; jp < 2; jp++) {
                uint32_t r0, r1, r2, r3;
                asm volatile("ldmatrix.sync.aligned.m8n8.x4.shared.b16 {%0,%1,%2,%3}, [%4];"
                             : "=r"(r0), "=r"(r1), "=r"(r2), "=r"(r3)
                             : "r"(boff[jp] + sb + kk * 32));
                bf1[2*jp][0] = r0; bf1[2*jp+1][0] = r1;
                bf1[2*jp][1] = r2; bf1[2*jp+1][1] = r3;
                asm volatile("ldmatrix.sync.aligned.m8n8.x4.shared.b16 {%0,%1,%2,%3}, [%4];"
                             : "=r"(r0), "=r"(r1), "=r"(r2), "=r"(r3)
                             : "r"(boff[jp] + sb + 15360 + kk * 32));
                bf2[2*jp][0] = r0; bf2[2*jp+1][0] = r1;
                bf2[2*jp][1] = r2; bf2[2*jp+1][1] = r3;
            }
            #pragma unroll
            for (int i = 0; i < 2; i++)
                #pragma unroll
                for (int j = 0; j < 4; j++) {
                    asm volatile("mma.sync.aligned.m16n8k16.row.col.f32.bf16.bf16.f32 "
                                 "{%0,%1,%2,%3}, {%4,%5,%6,%7}, {%8,%9}, {%0,%1,%2,%3};"
                                 : "+f"(acc1[i][j][0]), "+f"(acc1[i][j][1]),
                                   "+f"(acc1[i][j][2]), "+f"(acc1[i][j][3])
                                 : "r"(af1[i][0]), "r"(af1[i][1]), "r"(af1[i][2]), "r"(af1[i][3]),
                                   "r"(bf1[j][0]), "r"(bf1[j][1]));
                    asm volatile("mma.sync.aligned.m16n8k16.row.col.f32.bf16.bf16.f32 "
                                 "{%0,%1,%2,%3}, {%4,%5,%6,%7}, {%8,%9}, {%0,%1,%2,%3};"
                                 : "+f"(acc2[i][j][0]), "+f"(acc2[i][j][1]),
                                   "+f"(acc2[i][j][2]), "+f"(acc2[i][j][3])
                                 : "r"(af2[i][0]), "r"(af2[i][1]), "r"(af2[i][2]), "r"(af2[i][3]),
                                   "r"(bf2[j][0]), "r"(bf2[j][1]));
                }
        }
    }

    const int rbase = m0 + wm * 32 + (lane >> 2);
    const int cbase = n0 + wn * 32 + 2 * (lane & 3);
    #pragma unroll
    for (int i = 0; i < 2; i++) {
        #pragma unroll
        for (int half = 0; half < 2; half++) {
            int m = rbase + i * 16 + half * 8;
            #pragma unroll
            for (int j = 0; j < 4; j++) {
                int n = cbase + j * 8;
                float g0 = frcp_fast(1.f + fexpf_fast(-(acc1[i][j][half*2+0] + b1[n])));
                float g1 = frcp_fast(1.f + fexpf_fast(-(acc1[i][j][half*2+1] + b1[n+1])));
                float f0 = acc2[i][j][half*2+0] + b2[n];
                float f1 = acc2[i][j][half*2+1] + b2[n+1];
                size_t o = (size_t)m * Ncols + n;
                float2 r = *(const float2*)(feats + o);
                *(float2*)(out + o) = make_float2(r.x + g0 * f0, r.y + g1 * f1);
            }
        }
    }
}

// ---------------- flash attention (gathers rows via sidx) ----------------
#define FA_SMEM (20480 * 2 + 32 * 528)
__global__ void __launch_bounds__(256) fattn(const __nv_bfloat16* __restrict__ qkv,
                                             const int* __restrict__ sidx,
                                             __nv_bfloat16* __restrict__ o) {
    extern __shared__ char sm[];
    char* sq = sm;
    char* sk = sm + 20480;
    char* svt = sm + 40960;
    const int p = blockIdx.x, h = blockIdx.y;
    const int tid = threadIdx.x;
    const int lane = tid & 31;
    const int w = tid >> 5;
    const size_t base = (size_t)p * 256;
    const float SC = 0.17677669529663687f * 1.4426950408889634f;

    {
        const size_t src = (size_t)sidx[base + tid] * 768;
        const uint4* qr = (const uint4*)(qkv + src + h * 32);
        const uint4* kr = (const uint4*)(qkv + src + 256 + h * 32);
        const uint4* vr = (const uint4*)(qkv + src + 512 + h * 32);
        uint4* dq = (uint4*)(sq + tid * 80);
        uint4* dk = (uint4*)(sk + tid * 80);
        uint4 v0 = vr[0], v1 = vr[1], v2 = vr[2], v3 = vr[3];
        dq[0] = qr[0]; dq[1] = qr[1]; dq[2] = qr[2]; dq[3] = qr[3];
        dk[0] = kr[0]; dk[1] = kr[1]; dk[2] = kr[2]; dk[3] = kr[3];
        uint32_t vu[8] = {v0.x, v0.y, v0.z, v0.w, v1.x, v1.y, v1.z, v1.w};
        uint32_t vu2[8] = {v2.x, v2.y, v2.z, v2.w, v3.x, v3.y, v3.z, v3.w};
        #pragma unroll
        for (int e = 0; e < 8; e++) {
            ((__nv_bfloat16*)(svt + (2 * e + 0) * 528))[tid] = ((__nv_bfloat162*)&vu[e])->x;
            ((__nv_bfloat16*)(svt + (2 * e + 1) * 528))[tid] = ((__nv_bfloat162*)&vu[e])->y;
        }
        #pragma unroll
        for (int e = 0; e < 8; e++) {
            ((__nv_bfloat16*)(svt + (16 + 2 * e + 0) * 528))[tid] = ((__nv_bfloat162*)&vu2[e])->x;
            ((__nv_bfloat16*)(svt + (16 + 2 * e + 1) * 528))[tid] = ((__nv_bfloat162*)&vu2[e])->y;
        }
    }
    __syncthreads();

    const int m0w = w * 32;
    uint32_t qa[2][2][4];
    #pragma unroll
    for (int i = 0; i < 2; i++)
        #pragma unroll
        for (int kk = 0; kk < 2; kk++) {
            int r = m0w + i * 16 + (lane & 15);
            uint32_t addr = smem_u32(sq + r * 80 + kk * 32 + (lane >> 4) * 16);
            asm volatile("ldmatrix.sync.aligned.m8n8.x4.shared.b16 {%0,%1,%2,%3}, [%4];"
                         : "=r"(qa[i][kk][0]), "=r"(qa[i][kk][1]),
                           "=r"(qa[i][kk][2]), "=r"(qa[i][kk][3])
                         : "r"(addr));
        }

    float oacc[2][4][4];
    #pragma unroll
    for (int i = 0; i < 2; i++)
        #pragma unroll
        for (int d = 0; d < 4; d++)
            #pragma unroll
            for (int q = 0; q < 4; q++) oacc[i][d][q] = 0.f;
    float mrow[2][2] = {{-1e30f, -1e30f}, {-1e30f, -1e30f}};
    float lrow[2][2] = {{0.f, 0.f}, {0.f, 0.f}};

    for (int jc = 0; jc < 8; jc++) {
        uint32_t kb[2][4][2];
        #pragma unroll
        for (int jp = 0; jp < 2; jp++)
            #pragma unroll
            for (int kk = 0; kk < 2; kk++) {
                int r = jc * 32 + jp * 16 + (lane & 15);
                uint32_t addr = smem_u32(sk + r * 80 + kk * 32 + (lane >> 4) * 16);
                uint32_t r0, r1, r2, r3;
                asm volatile("ldmatrix.sync.aligned.m8n8.x4.shared.b16 {%0,%1,%2,%3}, [%4];"
                             : "=r"(r0), "=r"(r1), "=r"(r2), "=r"(r3) : "r"(addr));
                kb[kk][2*jp][0] = r0;   kb[kk][2*jp][1] = r2;
                kb[kk][2*jp+1][0] = r1; kb[kk][2*jp+1][1] = r3;
            }

        float sacc[2][4][4];
        #pragma unroll
        for (int i = 0; i < 2; i++)
            #pragma unroll
            for (int nt = 0; nt < 4; nt++)
                #pragma unroll
                for (int q = 0; q < 4; q++) sacc[i][nt][q] = 0.f;
        #pragma unroll
        for (int kk = 0; kk < 2; kk++)
            #pragma unroll
            for (int i = 0; i < 2; i++)
                #pragma unroll
                for (int nt = 0; nt < 4; nt++) {
                    asm volatile("mma.sync.aligned.m16n8k16.row.col.f32.bf16.bf16.f32 "
                                 "{%0,%1,%2,%3}, {%4,%5,%6,%7}, {%8,%9}, {%0,%1,%2,%3};"
                                 : "+f"(sacc[i][nt][0]), "+f"(sacc[i][nt][1]),
                                   "+f"(sacc[i][nt][2]), "+f"(sacc[i][nt][3])
                                 : "r"(qa[i][kk][0]), "r"(qa[i][kk][1]),
                                   "r"(qa[i][kk][2]), "r"(qa[i][kk][3]),
                                   "r"(kb[kk][nt][0]), "r"(kb[kk][nt][1]));
                }

        #pragma unroll
        for (int i = 0; i < 2; i++)
            #pragma unroll
            for (int nt = 0; nt < 4; nt++)
                #pragma unroll
                for (int q = 0; q < 4; q++) sacc[i][nt][q] *= SC;

        #pragma unroll
        for (int i = 0; i < 2; i++) {
            #pragma unroll
            for (int half = 0; half < 2; half++) {
                float mx = -1e30f;
                #pragma unroll
                for (int nt = 0; nt < 4; nt++) {
                    mx = fmaxf(mx, sacc[i][nt][half*2+0]);
                    mx = fmaxf(mx, sacc[i][nt][half*2+1]);
                }
                mx = fmaxf(mx, __shfl_xor_sync(0xffffffffu, mx, 1));
                mx = fmaxf(mx, __shfl_xor_sync(0xffffffffu, mx, 2));
                float newm = fmaxf(mrow[i][half], mx);
                float alpha = fexp2_fast(mrow[i][half] - newm);
                mrow[i][half] = newm;
                float rs = 0.f;
                #pragma unroll
                for (int nt = 0; nt < 4; nt++) {
                    float p0 = fexp2_fast(sacc[i][nt][half*2+0] - newm);
                    float p1 = fexp2_fast(sacc[i][nt][half*2+1] - newm);
                    sacc[i][nt][half*2+0] = p0;
                    sacc[i][nt][half*2+1] = p1;
                    rs += p0 + p1;
                }
                rs += __shfl_xor_sync(0xffffffffu, rs, 1);
                rs += __shfl_xor_sync(0xffffffffu, rs, 2);
                lrow[i][half] = lrow[i][half] * alpha + rs;
                #pragma unroll
                for (int dt = 0; dt < 4; dt++) {
                    oacc[i][dt][half*2+0] *= alpha;
                    oacc[i][dt][half*2+1] *= alpha;
                }
            }
        }

        uint32_t pa[2][2][4];
        #pragma unroll
        for (int i = 0; i < 2; i++)
            #pragma unroll
            for (int kk = 0; kk < 2; kk++) {
                int ntl = kk * 2, nth = kk * 2 + 1;
                __nv_bfloat162 b0 = __float22bfloat162_rn(make_float2(sacc[i][ntl][0], sacc[i][ntl][1]));
                __nv_bfloat162 b1 = __float22bfloat162_rn(make_float2(sacc[i][ntl][2], sacc[i][ntl][3]));
                __nv_bfloat162 b2 = __float22bfloat162_rn(make_float2(sacc[i][nth][0], sacc[i][nth][1]));
                __nv_bfloat162 b3 = __float22bfloat162_rn(make_float2(sacc[i][nth][2], sacc[i][nth][3]));
                pa[i][kk][0] = *(uint32_t*)&b0;
                pa[i][kk][1] = *(uint32_t*)&b1;
                pa[i][kk][2] = *(uint32_t*)&b2;
                pa[i][kk][3] = *(uint32_t*)&b3;
            }

        uint32_t vb[2][4][2];
        #pragma unroll
        for (int jp = 0; jp < 2; jp++)
            #pragma unroll
            for (int kk = 0; kk < 2; kk++) {
                int r = jp * 16 + (lane & 15);
                uint32_t addr = smem_u32(svt + r * 528 + jc * 64 + kk * 32 + (lane >> 4) * 16);
                uint32_t r0, r1, r2, r3;
                asm volatile("ldmatrix.sync.aligned.m8n8.x4.shared.b16 {%0,%1,%2,%3}, [%4];"
                             : "=r"(r0), "=r"(r1), "=r"(r2), "=r"(r3) : "r"(addr));
                vb[kk][2*jp][0] = r0;   vb[kk][2*jp][1] = r2;
                vb[kk][2*jp+1][0] = r1; vb[kk][2*jp+1][1] = r3;
            }

        #pragma unroll
        for (int kk = 0; kk < 2; kk++)
            #pragma unroll
            for (int i = 0; i < 2; i++)
                #pragma unroll
                for (int dt = 0; dt < 4; dt++) {
                    asm volatile("mma.sync.aligned.m16n8k16.row.col.f32.bf16.bf16.f32 "
                                 "{%0,%1,%2,%3}, {%4,%5,%6,%7}, {%8,%9}, {%0,%1,%2,%3};"
                                 : "+f"(oacc[i][dt][0]), "+f"(oacc[i][dt][1]),
                                   "+f"(oacc[i][dt][2]), "+f"(oacc[i][dt][3])
                                 : "r"(pa[i][kk][0]), "r"(pa[i][kk][1]),
                                   "r"(pa[i][kk][2]), "r"(pa[i][kk][3]),
                                   "r"(vb[kk][dt][0]), "r"(vb[kk][dt][1]));
                }
    }

    #pragma unroll
    for (int i = 0; i < 2; i++)
        #pragma unroll
        for (int half = 0; half < 2; half++) {
            float inv = 1.f / lrow[i][half];
            int row = m0w + i * 16 + half * 8 + (lane >> 2);
            #pragma unroll
            for (int dt = 0; dt < 4; dt++) {
                int col = h * 32 + dt * 8 + 2 * (lane & 3);
                __nv_bfloat162 hv;
                hv.x = __float2bfloat16(oacc[i][dt][half*2+0] * inv);
                hv.y = __float2bfloat16(oacc[i][dt][half*2+1] * inv);
                *(__nv_bfloat162*)(o + (base + row) * 256 + col) = hv;
            }
        }
}

// ---------------- fold gt into per-cloud biases ----------------
__global__ void cloudbias_kernel(const float* __restrict__ gtsum,
                                 const float* __restrict__ gg_w1, const float* __restrict__ gg_b1,
                                 const float* __restrict__ f_w1, const float* __restrict__ f_b1,
                                 float* __restrict__ ggb, float* __restrict__ fb, int Lc) {
    int c = blockIdx.x, j = threadIdx.x;
    float s1 = gg_b1[j], s2 = f_b1[j];
    float invL = 1.f / (float)Lc;
    for (int h = 0; h < 256; h++) {
        float gv = gtsum[c * 256 + h] * invL;
        s1 += gv * gg_w1[(size_t)(256 + h) * 256 + j];
        s2 += gv * f_w1[(size_t)(256 + h) * 256 + j];
    }
    ggb[c * 256 + j] = s1;
    fb[c * 256 + j] = s2;
}

// ---------------- launch ----------------
extern "C" void kernel_launch(void* const* d_in, const int* in_sizes, int n_in,
                              void* d_out, int out_size) {
    const float* feats = (const float*)d_in[0];
    const float* coord = (const float*)d_in[1];
    const float* pe_w1 = (const float*)d_in[3];
    const float* pe_b1 = (const float*)d_in[4];
    const float* pe_w2 = (const float*)d_in[5];
    const float* pe_b2 = (const float*)d_in[6];
    const float* pre_g = (const float*)d_in[7];
    const float* pre_b = (const float*)d_in[8];
    const float* n1_g  = (const float*)d_in[9];
    const float* n1_b  = (const float*)d_in[10];
    const float* wqkv  = (const float*)d_in[11];
    const float* bqkv  = (const float*)d_in[12];
    const float* wo    = (const float*)d_in[13];
    const float* bo    = (const float*)d_in[14];
    const float* n2_g  = (const float*)d_in[15];
    const float* n2_b  = (const float*)d_in[16];
    const float* m_w1  = (const float*)d_in[17];
    const float* m_b1  = (const float*)d_in[18];
    const float* m_w2  = (const float*)d_in[19];
    const float* m_b2  = (const float*)d_in[20];
    const float* gg_w1 = (const float*)d_in[21];
    const float* gg_b1 = (const float*)d_in[22];
    const float* gg_w2 = (const float*)d_in[23];
    const float* gg_b2 = (const float*)d_in[24];
    const float* f_w1  = (const float*)d_in[25];
    const float* f_b1  = (const float*)d_in[26];
    const float* f_w2  = (const float*)d_in[27];
    const float* f_b2  = (const float*)d_in[28];
    float* out = (float*)d_out;

    int N = in_sizes[0] / 256;
    int B = in_sizes[2];
    int Lc = N / B;
    int patches = N / 256;

    float *p_key, *p_gt, *p_ggb, *p_fb, *p_stats;
    __nv_bfloat16 *p_x, *p_xs, *p_ba, *p_bb, *p_fe, *p_wt;
    int* p_idx;
    cudaGetSymbolAddress((void**)&p_x, g_x);
    cudaGetSymbolAddress((void**)&p_xs, g_xs);
    cudaGetSymbolAddress((void**)&p_ba, g_ba);
    cudaGetSymbolAddress((void**)&p_bb, g_bb);
    cudaGetSymbolAddress((void**)&p_fe, g_fe);
    cudaGetSymbolAddress((void**)&p_wt, g_wt);
    cudaGetSymbolAddress((void**)&p_key, g_key);
    cudaGetSymbolAddress((void**)&p_idx, g_idx);
    cudaGetSymbolAddress((void**)&p_gt, g_gt);
    cudaGetSymbolAddress((void**)&p_ggb, g_ggb);
    cudaGetSymbolAddress((void**)&p_fb, g_fb);
    cudaGetSymbolAddress((void**)&p_stats, g_stats);

    __nv_bfloat16* wqkv_t = p_wt + 0;
    __nv_bfloat16* wo_t   = p_wt + 196608;
    __nv_bfloat16* mw1_t  = p_wt + 262144;
    __nv_bfloat16* mw2_t  = p_wt + 393216;
    __nv_bfloat16* ggw1_t = p_wt + 524288;
    __nv_bfloat16* ggw2_t = p_wt + 589824;
    __nv_bfloat16* fw1_t  = p_wt + 655360;
    __nv_bfloat16* fw2_t  = p_wt + 720896;
    __nv_bfloat16* pew2_t = p_wt + 786432;
    __nv_bfloat16* bb_lo = p_bb;
    __nv_bfloat16* bb_hi = p_bb + (size_t)N * 256;
    __nv_bfloat16* p_pe  = p_ba;
    __nv_bfloat16* p_hid = p_ba + (size_t)N * 512;

    static cudaStream_t s2 = nullptr;
    static cudaEvent_t ev1 = nullptr, ev2 = nullptr;
    if (!s2) {
        cudaStreamCreateWithFlags(&s2, cudaStreamNonBlocking);
        cudaEventCreateWithFlags(&ev1, cudaEventDisableTiming);
        cudaEventCreateWithFlags(&ev2, cudaEventDisableTiming);
    }

    cudaFuncSetAttribute(fattn, cudaFuncAttributeMaxDynamicSharedMemorySize, FA_SMEM);
    cudaFuncSetAttribute(gemm_bf16<2>, cudaFuncAttributeMaxDynamicSharedMemorySize, NSTAGE * STG_BYTES);
    cudaFuncSetAttribute(gemm_bf16<8>, cudaFuncAttributeMaxDynamicSharedMemorySize, NSTAGE * STG_BYTES);
    cudaFuncSetAttribute(gemm_bf16<16>, cudaFuncAttributeMaxDynamicSharedMemorySize, NSTAGE * STG_BYTES);
    cudaFuncSetAttribute(gemm_final, cudaFuncAttributeMaxDynamicSharedMemorySize, DNSTAGE * DSTG);

    PrepArgs pa;
    pa.coord = coord; pa.stats = p_stats; pa.Lc = Lc; pa.B = B;
    const float* ws[9] = {wqkv, wo, m_w1, m_w2, gg_w1, gg_w2, f_w1, f_w2, pe_w2};
    __nv_bfloat16* wd[9] = {wqkv_t, wo_t, mw1_t, mw2_t, ggw1_t, ggw2_t, fw1_t, fw2_t, pew2_t};
    int wK[9] = {256, 256, 256, 512, 256, 256, 256, 256, 64};
    int wN[9] = {768, 256, 512, 256, 256, 256, 256, 256, 256};
    int tiles = 0;
    for (int i = 0; i < 9; i++) {
        pa.wsrc[i] = ws[i]; pa.wdst[i] = wd[i];
        pa.wK[i] = wK[i]; pa.wN[i] = wN[i];
        pa.wt0[i] = tiles;
        tiles += (wK[i] / 32) * (wN[i] / 32);
    }
    pa.totalWTiles = tiles;
    pa.gt = p_gt;

    // 1: prep
    prep_kernel<<<B + tiles + 1, 1024>>>(pa);
    // 2: hid + key (warp per point)
    hid_key_kernel<<<N / 8, 256>>>(coord, pe_w1, pe_b1, p_stats, p_hid, p_key, p_idx, Lc);
    // fork: sort on s2; PE-GEMM + LN1 + qkv on main
    cudaEventRecord(ev1, 0);
    cudaStreamWaitEvent(s2, ev1, 0);
    sort_local<<<N / CHUNK, 1024, CHUNK * 8, s2>>>(p_key, p_idx, Lc);
    // main: pe = hid @ pe_w2^T + pe_b2 -> bf16
    gemm_bf16<2><<<dim3(256/GBN, N/GBM), 256, NSTAGE*STG_BYTES>>>(
        p_hid, pew2_t, pe_b2, nullptr, nullptr, p_pe, N, 256, 0, 0, 1,
        nullptr, nullptr, 0, nullptr, nullptr, nullptr, nullptr);
    // main: LN1 chain (warp per point) -> x bf16, hbf, febf
    ln1_kernel<<<N / 8, 256>>>(feats, p_pe, pre_g, pre_b, n1_g, n1_b, p_x, p_bb, p_fe);
    // main: qkv GEMM -> ba
    gemm_bf16<8><<<dim3(768/GBN, N/GBM), 256, NSTAGE*STG_BYTES>>>(
        p_bb, wqkv_t, bqkv, nullptr, nullptr, p_ba, N, 768, 0, 0, 1,
        nullptr, nullptr, 0, nullptr, nullptr, nullptr, nullptr);
    // (s2): finish the sort
    for (int k = CHUNK * 2; k <= Lc; k <<= 1) {
        for (int j = k >> 1; j >= CHUNK; j >>= 1)
            sort_global<<<dim3(Lc / 512, B), 256, 0, s2>>>(p_key, p_idx, k, j, Lc);
        merge_local<<<N / CHUNK, 1024, CHUNK * 8, s2>>>(p_key, p_idx, k, Lc);
    }
    cudaEventRecord(ev2, s2);
    cudaStreamWaitEvent(0, ev2, 0);
    // flash attention (gather via idx) -> bb
    fattn<<<dim3(patches, 8), 256, FA_SMEM>>>(p_ba, p_idx, p_bb);
    // wo GEMM + gathered bf16 residual -> xs bf16
    gemm_bf16<8><<<dim3(256/GBN, N/GBM), 256, NSTAGE*STG_BYTES>>>(
        p_bb, wo_t, bo, p_x, nullptr, p_xs, N, 256, 0, 4, 1,
        p_idx, nullptr, 0, nullptr, nullptr, nullptr, nullptr);
    // LN2 -> ba bf16 (warp per row, bf16 in)
    ln_bf<<<N / 8, 256>>>(p_xs, n2_g, n2_b, p_ba);
    // MLP1 + gelu -> bb
    gemm_bf16<8><<<dim3(512/GBN, N/GBM), 256, NSTAGE*STG_BYTES>>>(
        p_ba, mw1_t, m_b1, nullptr, nullptr, p_bb, N, 512, 0, 2, 1,
        nullptr, nullptr, 0, nullptr, nullptr, nullptr, nullptr);
    // MLP2 + bf16 resid; scatter xo -> ba; gt atomics
    gemm_bf16<16><<<dim3(256/GBN, N/GBM), 256, NSTAGE*STG_BYTES>>>(
        p_bb, mw2_t, m_b2, p_xs, nullptr, p_ba, N, 256, 0, 6, 1,
        p_idx, p_gt, Lc, nullptr, nullptr, nullptr, nullptr);
    // per-cloud biases
    cloudbias_kernel<<<B, 256>>>(p_gt, gg_w1, gg_b1, f_w1, f_b1, p_ggb, p_fb, Lc);
    // batched hidden GEMMs (z=0 gate-hidden, z=1 fuse-hidden)
    gemm_bf16<8><<<dim3(256/GBN, N/GBM, 2), 256, NSTAGE*STG_BYTES>>>(
        p_fe, ggw1_t, p_ggb, nullptr, nullptr, bb_lo, N, 256, Lc, 1, 1,
        nullptr, nullptr, 0, p_ba, fw1_t, p_fb, bb_hi);
    // fused final: out = feats + sigmoid(bb_lo@gg_w2+gg_b2) * (bb_hi@f_w2+f_b2)
    gemm_final<<<dim3(256/64, N/128), 256, DNSTAGE*DSTG>>>(
        bb_lo, ggw2_t, gg_b2, bb_hi, fw2_t, f_b2, feats, out, 256);
}